// round 5
// baseline (speedup 1.0000x reference)
#include <cuda_runtime.h>
#include <cuda_bf16.h>
#include <math.h>
#include <stdint.h>

// ---------------- problem constants ----------------
#define SQ   2048
#define BB   2
#define DIM  1024
#define NH   16
#define HD   64
#define NTOK 4096
#define NE   8
#define DFF  4096
#define CAP  2048
#define LN_EPS 1e-5f

// ---------------- scratch (device globals) ----------------
__device__ __nv_bfloat16 g_tgt_h[NTOK * DIM], g_tgt_l[NTOK * DIM];
__device__ __nv_bfloat16 g_mem_h[NTOK * DIM], g_mem_l[NTOK * DIM];
__device__ __nv_bfloat16 g_att_h[NTOK * DIM], g_att_l[NTOK * DIM];
__device__ __nv_bfloat16 g_x1_h [NTOK * DIM], g_x1_l [NTOK * DIM];
__device__ __nv_bfloat16 g_buf_h[NE * CAP * DIM], g_buf_l[NE * CAP * DIM];
__device__ __nv_bfloat16 g_hb_h[(size_t)NE * CAP * DFF], g_hb_l[(size_t)NE * CAP * DFF];
__device__ __nv_bfloat16 g_wqsa_h[3 * DIM * DIM], g_wqsa_l[3 * DIM * DIM];
__device__ __nv_bfloat16 g_wosa_h[DIM * DIM],     g_wosa_l[DIM * DIM];
__device__ __nv_bfloat16 g_wqca_h[3 * DIM * DIM], g_wqca_l[3 * DIM * DIM];
__device__ __nv_bfloat16 g_woca_h[DIM * DIM],     g_woca_l[DIM * DIM];
__device__ __nv_bfloat16 g_w1t_h[(size_t)NE * DIM * DFF], g_w1t_l[(size_t)NE * DIM * DFF];
__device__ __nv_bfloat16 g_w2t_h[(size_t)NE * DIM * DFF], g_w2t_l[(size_t)NE * DIM * DFF];
__device__ float g_qkv [NTOK * 3 * DIM];
__device__ float g_attn[NTOK * DIM];
__device__ float g_qca [NTOK * DIM];
__device__ float g_kvca[NTOK * 2 * DIM];
__device__ float g_x2  [NTOK * DIM];
__device__ float g_probs[NTOK * NE];
__device__ float g_gatev[NTOK * 2];
__device__ int   g_gidx[NTOK * 2];
__device__ int   g_sl  [NTOK * 2];
__device__ int   g_rows[NE];
__device__ float g_aux;
__device__ float g_y [NE * CAP * DIM];
__device__ float g_x3[NTOK * DIM];

__device__ __forceinline__ float gelu_exact(float x) {
    return 0.5f * x * (1.0f + erff(x * 0.70710678118654752440f));
}
__device__ __forceinline__ void split2(float v, __nv_bfloat16& h, __nv_bfloat16& l) {
    h = __float2bfloat16(v);
    l = __float2bfloat16(v - __bfloat162float(h));
}
__device__ __forceinline__ uint32_t smem_u32(const void* p) {
    uint32_t a;
    asm("{ .reg .u64 t; cvta.to.shared.u64 t, %1; cvt.u32.u64 %0, t; }" : "=r"(a) : "l"(p));
    return a;
}
#define CP_ASYNC16(s, g) \
    asm volatile("cp.async.cg.shared.global [%0], [%1], 16;" :: "r"(s), "l"(g))
#define CP_COMMIT() asm volatile("cp.async.commit_group;" ::: "memory")

__device__ __forceinline__ void mma16816(float* d, const uint32_t* a, const uint32_t* b) {
    asm volatile(
        "mma.sync.aligned.m16n8k16.row.col.f32.bf16.bf16.f32 "
        "{%0,%1,%2,%3}, {%4,%5,%6,%7}, {%8,%9}, {%0,%1,%2,%3};"
        : "+f"(d[0]), "+f"(d[1]), "+f"(d[2]), "+f"(d[3])
        : "r"(a[0]), "r"(a[1]), "r"(a[2]), "r"(a[3]), "r"(b[0]), "r"(b[1]));
}

// ---------------- bf16 mma NT GEMM with 3-term hi/lo split ----------------
// C[r,c] = sum_k A[r,k]*B[c,k] (+bias[c], opt GELU). A,B K-major bf16 hi/lo.
// 128x128 block tile, 8 warps (2x4), warp tile 64x32, K-chunk 32, cp.async x2 stages.
#define TPAD       40                    // smem row stride in bf16 (80 bytes)
#define TILE_B     (128 * TPAD * 2)      // 10240 bytes per tile
#define STAGE_B    (4 * TILE_B)          // Ah, Al, Bh, Bl
#define GEMM_SMEM  (2 * STAGE_B)         // 81920 bytes

template<int DOGELU, int SPLITOUT>
__global__ void __launch_bounds__(256) mmagemm_kernel(
    const __nv_bfloat16* __restrict__ Ah, const __nv_bfloat16* __restrict__ Al,
    const __nv_bfloat16* __restrict__ Bh, const __nv_bfloat16* __restrict__ Bl,
    const float* __restrict__ bias, float* __restrict__ C,
    __nv_bfloat16* __restrict__ Ch, __nv_bfloat16* __restrict__ Cl,
    int K, int ldc,
    long long sA, long long sB, long long sBias, long long sC,
    const int* __restrict__ rows_used)
{
    extern __shared__ char smem[];
    const int z = blockIdx.z;
    if (rows_used && (int)(blockIdx.y * 128) >= rows_used[z]) return;

    const int tid = threadIdx.x, wid = tid >> 5, lane = tid & 31;
    const int wm = wid & 1, wn = wid >> 1;                 // 2 x 4 warp grid
    const long long rowBase = (long long)blockIdx.y * 128;
    const int colBase = blockIdx.x * 128;
    Ah += z * sA; Al += z * sA; Bh += z * sB; Bl += z * sB; bias += z * sBias;

    const __nv_bfloat16* src[4];
    src[0] = Ah + rowBase * K;
    src[1] = Al + rowBase * K;
    src[2] = Bh + (long long)colBase * K;
    src[3] = Bl + (long long)colBase * K;

    const uint32_t sbase = smem_u32(smem);
    const int NC = K >> 5;                                  // chunks of 32

    // async load one stage: 4 tiles of 128 rows x 32 bf16 (64 B/row = 4 x 16B)
    auto prefetch = [&](int st, int kc) {
        const int koff = kc * 32;
        const uint32_t stb = sbase + st * STAGE_B;
        #pragma unroll
        for (int bi = 0; bi < 4; bi++) {
            const __nv_bfloat16* s = src[bi] + koff;
            const uint32_t tb = stb + bi * TILE_B;
            #pragma unroll
            for (int it = 0; it < 2; it++) {
                int idx = it * 256 + tid;
                int row = idx >> 2, c = idx & 3;
                CP_ASYNC16(tb + row * (TPAD * 2) + c * 16,
                           (const void*)(s + (long long)row * K + c * 8));
            }
        }
        CP_COMMIT();
    };

    float acc[4][4][4];
    #pragma unroll
    for (int i = 0; i < 4; i++)
        #pragma unroll
        for (int j = 0; j < 4; j++)
            #pragma unroll
            for (int r = 0; r < 4; r++) acc[i][j][r] = 0.f;

    const int lr = lane >> 2, lc2 = (lane & 3) * 2;

    prefetch(0, 0);

    for (int ic = 0; ic < NC; ic++) {
        const int p = ic & 1;
        if (ic + 1 < NC) {
            prefetch(p ^ 1, ic + 1);
            asm volatile("cp.async.wait_group 1;" ::: "memory");
        } else {
            asm volatile("cp.async.wait_group 0;" ::: "memory");
        }
        __syncthreads();

        const char* stp = smem + p * STAGE_B;
        const char* aH = stp;
        const char* aL = stp + TILE_B;
        const char* bH = stp + 2 * TILE_B;
        const char* bL = stp + 3 * TILE_B;

        #pragma unroll
        for (int ks = 0; ks < 2; ks++) {
            const int kof = ks * 16 + lc2;                 // bf16 offset in row
            uint32_t ah[4][4], al[4][4], bh[4][2], bl[4][2];
            #pragma unroll
            for (int i = 0; i < 4; i++) {
                int r0 = wm * 64 + i * 16 + lr;
                const char* p0 = aH + (r0 * TPAD + kof) * 2;
                const char* p1 = aH + ((r0 + 8) * TPAD + kof) * 2;
                ah[i][0] = *(const uint32_t*)p0;
                ah[i][1] = *(const uint32_t*)p1;
                ah[i][2] = *(const uint32_t*)(p0 + 16);
                ah[i][3] = *(const uint32_t*)(p1 + 16);
                const char* q0 = aL + (r0 * TPAD + kof) * 2;
                const char* q1 = aL + ((r0 + 8) * TPAD + kof) * 2;
                al[i][0] = *(const uint32_t*)q0;
                al[i][1] = *(const uint32_t*)q1;
                al[i][2] = *(const uint32_t*)(q0 + 16);
                al[i][3] = *(const uint32_t*)(q1 + 16);
            }
            #pragma unroll
            for (int j = 0; j < 4; j++) {
                int br = wn * 32 + j * 8 + lr;
                const char* p0 = bH + (br * TPAD + kof) * 2;
                bh[j][0] = *(const uint32_t*)p0;
                bh[j][1] = *(const uint32_t*)(p0 + 16);
                const char* q0 = bL + (br * TPAD + kof) * 2;
                bl[j][0] = *(const uint32_t*)q0;
                bl[j][1] = *(const uint32_t*)(q0 + 16);
            }
            #pragma unroll
            for (int i = 0; i < 4; i++)
                #pragma unroll
                for (int j = 0; j < 4; j++) {
                    mma16816(acc[i][j], ah[i], bh[j]);
                    mma16816(acc[i][j], ah[i], bl[j]);
                    mma16816(acc[i][j], al[i], bh[j]);
                }
        }
        __syncthreads();
    }

    // epilogue
    #pragma unroll
    for (int i = 0; i < 4; i++) {
        const int r0 = (int)rowBase + wm * 64 + i * 16 + lr;
        #pragma unroll
        for (int j = 0; j < 4; j++) {
            const int col = colBase + wn * 32 + j * 8 + lc2;
            float b0 = bias[col], b1 = bias[col + 1];
            float v0 = acc[i][j][0] + b0, v1 = acc[i][j][1] + b1;
            float v2 = acc[i][j][2] + b0, v3 = acc[i][j][3] + b1;
            if (DOGELU) {
                v0 = gelu_exact(v0); v1 = gelu_exact(v1);
                v2 = gelu_exact(v2); v3 = gelu_exact(v3);
            }
            if (SPLITOUT == 0) {
                float* c0 = C + ((long long)r0 * ldc + col) + z * sC;
                float* c1 = C + ((long long)(r0 + 8) * ldc + col) + z * sC;
                c0[0] = v0; c0[1] = v1;
                c1[0] = v2; c1[1] = v3;
            } else {
                long long o0 = (long long)r0 * ldc + col + z * sC;
                long long o1 = (long long)(r0 + 8) * ldc + col + z * sC;
                __nv_bfloat16 h0, l0, h1, l1, h2, l2, h3, l3;
                split2(v0, h0, l0); split2(v1, h1, l1);
                split2(v2, h2, l2); split2(v3, h3, l3);
                *(__nv_bfloat162*)(Ch + o0) = __halves2bfloat162(h0, h1);
                *(__nv_bfloat162*)(Cl + o0) = __halves2bfloat162(l0, l1);
                *(__nv_bfloat162*)(Ch + o1) = __halves2bfloat162(h2, h3);
                *(__nv_bfloat162*)(Cl + o1) = __halves2bfloat162(l2, l3);
            }
        }
    }
}

// ---------------- fp32 -> bf16 hi/lo split ----------------
__global__ void __launch_bounds__(256) split_kernel(
    const float4* __restrict__ x, __nv_bfloat16* __restrict__ h,
    __nv_bfloat16* __restrict__ l, int n4)
{
    int i = blockIdx.x * 256 + threadIdx.x;
    if (i >= n4) return;
    float4 v = x[i];
    __nv_bfloat16 h0, l0, h1, l1, h2, l2, h3, l3;
    split2(v.x, h0, l0); split2(v.y, h1, l1);
    split2(v.z, h2, l2); split2(v.w, h3, l3);
    ((__nv_bfloat162*)h)[2 * i]     = __halves2bfloat162(h0, h1);
    ((__nv_bfloat162*)h)[2 * i + 1] = __halves2bfloat162(h2, h3);
    ((__nv_bfloat162*)l)[2 * i]     = __halves2bfloat162(l0, l1);
    ((__nv_bfloat162*)l)[2 * i + 1] = __halves2bfloat162(l2, l3);
}

// ---------------- transpose + split: src[z][R][Cc] -> dst[z][Cc][R] ----------------
__global__ void __launch_bounds__(256) tsplit_kernel(
    const float* __restrict__ src, __nv_bfloat16* __restrict__ dh,
    __nv_bfloat16* __restrict__ dl, int R, int Cc)
{
    __shared__ float t[32][33];
    const long long zoff = (long long)blockIdx.z * R * Cc;
    src += zoff; dh += zoff; dl += zoff;
    const int r0 = blockIdx.y * 32, c0 = blockIdx.x * 32;
    const int tx = threadIdx.x & 31, ty = threadIdx.x >> 5;
    #pragma unroll
    for (int i = 0; i < 32; i += 8)
        t[ty + i][tx] = src[(long long)(r0 + ty + i) * Cc + c0 + tx];
    __syncthreads();
    #pragma unroll
    for (int i = 0; i < 32; i += 8) {
        float v = t[tx][ty + i];
        long long o = (long long)(c0 + ty + i) * R + r0 + tx;
        __nv_bfloat16 h, l;
        split2(v, h, l);
        dh[o] = h; dl[o] = l;
    }
}

// ---------------- flash attention (fp32, Br=Bc=64, hd=64) ----------------
#define ATTN_SMEM (4 * 64 * 65 * 4)
__global__ void __launch_bounds__(256) attn_kernel(
    const float* __restrict__ Qb, int ldq,
    const float* __restrict__ Kb, int ldk,
    const float* __restrict__ Vb, int ldv,
    float* __restrict__ Ob, int ldo, int Skv)
{
    extern __shared__ float sm[];
    float* Qs = sm;
    float* Ks = sm + 64 * 65;
    float* Vs = sm + 2 * 64 * 65;
    float* Ss = sm + 3 * 64 * 65;

    const int b = blockIdx.z, h = blockIdx.y, qt = blockIdx.x;
    const int tid = threadIdx.x, tx = tid & 15, ty = tid >> 4;
    const float* Q  = Qb + h * HD;
    const float* Kp = Kb + h * HD;
    const float* Vp = Vb + h * HD;

    for (int u = tid; u < 64 * 16; u += 256) {
        int r = u >> 4, c4 = (u & 15) << 2;
        long long tok = (long long)(qt * 64 + r) * BB + b;
        float4 v = *(const float4*)(Q + tok * ldq + c4);
        float* d = Qs + r * 65 + c4;
        d[0] = v.x * 0.125f; d[1] = v.y * 0.125f;
        d[2] = v.z * 0.125f; d[3] = v.w * 0.125f;
    }

    float o[4][4], mrow[4], lrow[4];
    #pragma unroll
    for (int i = 0; i < 4; i++) {
        mrow[i] = -1e30f; lrow[i] = 0.f;
        #pragma unroll
        for (int j = 0; j < 4; j++) o[i][j] = 0.f;
    }

    const int nkt = Skv / 64;
    for (int kt = 0; kt < nkt; kt++) {
        __syncthreads();
        for (int u = tid; u < 64 * 16; u += 256) {
            int r = u >> 4, c4 = (u & 15) << 2;
            long long tok = (long long)(kt * 64 + r) * BB + b;
            float4 kv = *(const float4*)(Kp + tok * ldk + c4);
            float* kd = Ks + r * 65 + c4;
            kd[0] = kv.x; kd[1] = kv.y; kd[2] = kv.z; kd[3] = kv.w;
            float4 vv = *(const float4*)(Vp + tok * ldv + c4);
            float* vd = Vs + r * 65 + c4;
            vd[0] = vv.x; vd[1] = vv.y; vd[2] = vv.z; vd[3] = vv.w;
        }
        __syncthreads();

        float s[4][4];
        #pragma unroll
        for (int i = 0; i < 4; i++)
            #pragma unroll
            for (int j = 0; j < 4; j++) s[i][j] = 0.f;

        #pragma unroll 4
        for (int k = 0; k < 64; k++) {
            float a[4], bb2[4];
            #pragma unroll
            for (int i = 0; i < 4; i++) a[i] = Qs[(ty * 4 + i) * 65 + k];
            #pragma unroll
            for (int j = 0; j < 4; j++) bb2[j] = Ks[(tx * 4 + j) * 65 + k];
            #pragma unroll
            for (int i = 0; i < 4; i++)
                #pragma unroll
                for (int j = 0; j < 4; j++)
                    s[i][j] = fmaf(a[i], bb2[j], s[i][j]);
        }

        #pragma unroll
        for (int i = 0; i < 4; i++) {
            float rmax = fmaxf(fmaxf(s[i][0], s[i][1]), fmaxf(s[i][2], s[i][3]));
            #pragma unroll
            for (int off = 8; off >= 1; off >>= 1)
                rmax = fmaxf(rmax, __shfl_xor_sync(0xffffffffu, rmax, off));
            float mn = fmaxf(mrow[i], rmax);
            float sc = __expf(mrow[i] - mn);
            float p0 = __expf(s[i][0] - mn);
            float p1 = __expf(s[i][1] - mn);
            float p2 = __expf(s[i][2] - mn);
            float p3 = __expf(s[i][3] - mn);
            float* sp = Ss + (ty * 4 + i) * 65 + tx * 4;
            sp[0] = p0; sp[1] = p1; sp[2] = p2; sp[3] = p3;
            float ps = p0 + p1 + p2 + p3;
            #pragma unroll
            for (int off = 8; off >= 1; off >>= 1)
                ps += __shfl_xor_sync(0xffffffffu, ps, off);
            lrow[i] = lrow[i] * sc + ps;
            mrow[i] = mn;
            #pragma unroll
            for (int j = 0; j < 4; j++) o[i][j] *= sc;
        }
        __syncthreads();

        #pragma unroll 4
        for (int k = 0; k < 64; k++) {
            float ss[4], vv[4];
            #pragma unroll
            for (int i = 0; i < 4; i++) ss[i] = Ss[(ty * 4 + i) * 65 + k];
            #pragma unroll
            for (int j = 0; j < 4; j++) vv[j] = Vs[k * 65 + tx * 4 + j];
            #pragma unroll
            for (int i = 0; i < 4; i++)
                #pragma unroll
                for (int j = 0; j < 4; j++)
                    o[i][j] = fmaf(ss[i], vv[j], o[i][j]);
        }
    }

    #pragma unroll
    for (int i = 0; i < 4; i++) {
        float inv = 1.0f / lrow[i];
        long long tok = (long long)(qt * 64 + ty * 4 + i) * BB + b;
        float* op = Ob + tok * ldo + h * HD + tx * 4;
        op[0] = o[i][0] * inv; op[1] = o[i][1] * inv;
        op[2] = o[i][2] * inv; op[3] = o[i][3] * inv;
    }
}

// ---------------- gating ----------------
__global__ void __launch_bounds__(128) gate_kernel(
    const float* __restrict__ x, const float* __restrict__ wg,
    float* __restrict__ probs, float* __restrict__ gatev, int* __restrict__ gidx)
{
    const int t = blockIdx.x, tid = threadIdx.x;
    __shared__ float red[128][8];
    float acc[8];
    #pragma unroll
    for (int e = 0; e < 8; e++) acc[e] = 0.f;
    for (int d = tid; d < DIM; d += 128) {
        float xv = x[(long long)t * DIM + d];
        const float4* w = (const float4*)(wg + d * 8);
        float4 w0 = w[0], w1 = w[1];
        acc[0] += xv * w0.x; acc[1] += xv * w0.y; acc[2] += xv * w0.z; acc[3] += xv * w0.w;
        acc[4] += xv * w1.x; acc[5] += xv * w1.y; acc[6] += xv * w1.z; acc[7] += xv * w1.w;
    }
    #pragma unroll
    for (int e = 0; e < 8; e++) red[tid][e] = acc[e];
    __syncthreads();
    for (int s = 64; s > 0; s >>= 1) {
        if (tid < s)
            #pragma unroll
            for (int e = 0; e < 8; e++) red[tid][e] += red[tid + s][e];
        __syncthreads();
    }
    if (tid == 0) {
        float l[8], mx = -1e30f;
        #pragma unroll
        for (int e = 0; e < 8; e++) { l[e] = red[0][e]; mx = fmaxf(mx, l[e]); }
        float sum = 0.f;
        #pragma unroll
        for (int e = 0; e < 8; e++) { l[e] = __expf(l[e] - mx); sum += l[e]; }
        float inv = 1.0f / sum;
        #pragma unroll
        for (int e = 0; e < 8; e++) { l[e] *= inv; probs[t * 8 + e] = l[e]; }
        int i1 = 0; float v1 = l[0];
        #pragma unroll
        for (int e = 1; e < 8; e++) if (l[e] > v1) { v1 = l[e]; i1 = e; }
        int i2 = -1; float v2 = -1.f;
        #pragma unroll
        for (int e = 0; e < 8; e++) if (e != i1 && l[e] > v2) { v2 = l[e]; i2 = e; }
        gatev[2 * t] = v1; gatev[2 * t + 1] = v2;
        gidx[2 * t] = i1;  gidx[2 * t + 1] = i2;
    }
}

// ---------------- routing ----------------
__global__ void __launch_bounds__(256) route_kernel(
    const int* __restrict__ gidx, const float* __restrict__ probs,
    int* __restrict__ sl, int* __restrict__ rows, float* __restrict__ auxp)
{
    __shared__ signed char s1[NTOK];
    __shared__ signed char s2[NTOK];
    __shared__ int cnt1[8];
    __shared__ float pr[256 * 8];
    const int tid = threadIdx.x;

    for (int i = tid; i < NTOK; i += 256) {
        int2 v = ((const int2*)gidx)[i];
        s1[i] = (signed char)v.x; s2[i] = (signed char)v.y;
    }
    float lp[8];
    #pragma unroll
    for (int e = 0; e < 8; e++) lp[e] = 0.f;
    for (int i = tid; i < NTOK; i += 256) {
        const float4* p = (const float4*)(probs + i * 8);
        float4 p0 = p[0], p1 = p[1];
        lp[0] += p0.x; lp[1] += p0.y; lp[2] += p0.z; lp[3] += p0.w;
        lp[4] += p1.x; lp[5] += p1.y; lp[6] += p1.z; lp[7] += p1.w;
    }
    #pragma unroll
    for (int e = 0; e < 8; e++) pr[tid * 8 + e] = lp[e];
    __syncthreads();
    for (int s = 128; s > 0; s >>= 1) {
        if (tid < s)
            #pragma unroll
            for (int e = 0; e < 8; e++) pr[tid * 8 + e] += pr[(tid + s) * 8 + e];
        __syncthreads();
    }

    if (tid < 8) {
        int e = tid, c = 0;
        #pragma unroll 1
        for (int i = 0; i < NTOK; i++)
            if (s1[i] == e) { sl[2 * i] = (c < CAP) ? c : -1; c++; }
        cnt1[e] = c;
    }
    __syncthreads();
    if (tid < 8) {
        int e = tid, base = cnt1[e], c = 0;
        #pragma unroll 1
        for (int i = 0; i < NTOK; i++)
            if (s2[i] == e) { int loc = base + c; sl[2 * i + 1] = (loc < CAP) ? loc : -1; c++; }
        int ru = cnt1[e] + c; if (ru > CAP) ru = CAP;
        rows[e] = ru;
    }
    __syncthreads();
    if (tid == 0) {
        float a = 0.f;
        for (int e = 0; e < 8; e++)
            a += ((float)cnt1[e] / (float)NTOK) * (pr[e] / (float)NTOK);
        *auxp = 0.01f * 8.0f * a;
    }
}

// ---------------- scatter (writes bf16 hi/lo) ----------------
__global__ void __launch_bounds__(256) scatter_kernel(
    const float* __restrict__ x, const int* __restrict__ gidx,
    const int* __restrict__ sl, __nv_bfloat16* __restrict__ bh,
    __nv_bfloat16* __restrict__ bl)
{
    const int t = blockIdx.x, ch = blockIdx.y;
    const int s = sl[2 * t + ch];
    if (s < 0) return;
    const int e = gidx[2 * t + ch];
    float4 v = ((const float4*)(x + (long long)t * DIM))[threadIdx.x];
    size_t base = ((size_t)e * CAP + s) * DIM + threadIdx.x * 4;
    __nv_bfloat16 h0, l0, h1, l1, h2, l2, h3, l3;
    split2(v.x, h0, l0); split2(v.y, h1, l1);
    split2(v.z, h2, l2); split2(v.w, h3, l3);
    *(__nv_bfloat162*)(bh + base)     = __halves2bfloat162(h0, h1);
    *(__nv_bfloat162*)(bh + base + 2) = __halves2bfloat162(h2, h3);
    *(__nv_bfloat162*)(bl + base)     = __halves2bfloat162(l0, l1);
    *(__nv_bfloat162*)(bl + base + 2) = __halves2bfloat162(l2, l3);
}

// ---------------- gather ----------------
__global__ void __launch_bounds__(256) gather_kernel(
    const float* __restrict__ y, const int* __restrict__ gidx,
    const int* __restrict__ sl, const float* __restrict__ gatev,
    float* __restrict__ out)
{
    const int t = blockIdx.x;
    const float gv1 = gatev[2 * t], gv2 = gatev[2 * t + 1];
    const int s1 = sl[2 * t], s2 = sl[2 * t + 1];
    const int e1 = gidx[2 * t], e2 = gidx[2 * t + 1];
    float4 r = make_float4(0.f, 0.f, 0.f, 0.f);
    if (s1 >= 0) {
        float4 a = ((const float4*)(y + ((size_t)e1 * CAP + s1) * DIM))[threadIdx.x];
        r.x += gv1 * a.x; r.y += gv1 * a.y; r.z += gv1 * a.z; r.w += gv1 * a.w;
    }
    if (s2 >= 0) {
        float4 a = ((const float4*)(y + ((size_t)e2 * CAP + s2) * DIM))[threadIdx.x];
        r.x += gv2 * a.x; r.y += gv2 * a.y; r.z += gv2 * a.z; r.w += gv2 * a.w;
    }
    ((float4*)(out + (long long)t * DIM))[threadIdx.x] = r;
}

// ---------------- triple layernorm + aux ----------------
__device__ __forceinline__ float block_sum(float v, float* red) {
    int tid = threadIdx.x;
    red[tid] = v; __syncthreads();
    for (int s = 128; s > 0; s >>= 1) {
        if (tid < s) red[tid] += red[tid + s];
        __syncthreads();
    }
    float r = red[0]; __syncthreads();
    return r;
}

__global__ void __launch_bounds__(256) ln3_kernel(
    const float* __restrict__ x,
    const float* __restrict__ g1, const float* __restrict__ b1,
    const float* __restrict__ g2, const float* __restrict__ b2,
    const float* __restrict__ g3, const float* __restrict__ b3,
    float* __restrict__ out, const float* __restrict__ auxp, long long out_size)
{
    __shared__ float red[256];
    const int t = blockIdx.x, tid = threadIdx.x;
    float4 v = ((const float4*)(x + (long long)t * DIM))[tid];

    const float* gs[3] = {g1, g2, g3};
    const float* bs[3] = {b1, b2, b3};
    #pragma unroll
    for (int r3 = 0; r3 < 3; r3++) {
        float s = v.x + v.y + v.z + v.w;
        float mean = block_sum(s, red) * (1.0f / DIM);
        float dx = v.x - mean, dy = v.y - mean, dz = v.z - mean, dw = v.w - mean;
        float s2 = dx * dx + dy * dy + dz * dz + dw * dw;
        float var = block_sum(s2, red) * (1.0f / DIM);
        float rstd = rsqrtf(var + LN_EPS);
        float4 gg = ((const float4*)gs[r3])[tid];
        float4 bb = ((const float4*)bs[r3])[tid];
        v.x = dx * rstd * gg.x + bb.x;
        v.y = dy * rstd * gg.y + bb.y;
        v.z = dz * rstd * gg.z + bb.z;
        v.w = dw * rstd * gg.w + bb.w;
    }
    ((float4*)(out + (long long)t * DIM))[tid] = v;
    if (t == 0 && tid == 0 && out_size > (long long)NTOK * DIM)
        out[(long long)NTOK * DIM] = *auxp;
}

// ---------------- launch ----------------
extern "C" void kernel_launch(void* const* d_in, const int* in_sizes, int n_in,
                              void* d_out, int out_size) {
    const float* tgt      = (const float*)d_in[0];
    const float* mem      = (const float*)d_in[1];
    const float* w_qkv_sa = (const float*)d_in[2];
    const float* b_qkv_sa = (const float*)d_in[3];
    const float* w_o_sa   = (const float*)d_in[4];
    const float* b_o_sa   = (const float*)d_in[5];
    const float* w_qkv_ca = (const float*)d_in[6];
    const float* b_qkv_ca = (const float*)d_in[7];
    const float* w_o_ca   = (const float*)d_in[8];
    const float* b_o_ca   = (const float*)d_in[9];
    const float* ln1_g = (const float*)d_in[10];
    const float* ln1_b = (const float*)d_in[11];
    const float* ln2_g = (const float*)d_in[12];
    const float* ln2_b = (const float*)d_in[13];
    const float* ln3_g = (const float*)d_in[14];
    const float* ln3_b = (const float*)d_in[15];
    const float* w_gate = (const float*)d_in[16];
    const float* w1  = (const float*)d_in[17];
    const float* b1e = (const float*)d_in[18];
    const float* w2  = (const float*)d_in[19];
    const float* b2e = (const float*)d_in[20];
    float* out = (float*)d_out;

    float *qkv, *attn, *qca, *kvca, *x2, *probs, *gatev, *x3, *ybuf, *auxp;
    int *gidx, *sl, *rows;
    __nv_bfloat16 *tgt_h, *tgt_l, *mem_h, *mem_l, *att_h, *att_l, *x1_h, *x1_l;
    __nv_bfloat16 *buf_h, *buf_l, *hb_h, *hb_l;
    __nv_bfloat16 *wqsa_h, *wqsa_l, *wosa_h, *wosa_l, *wqca_h, *wqca_l, *woca_h, *woca_l;
    __nv_bfloat16 *w1t_h, *w1t_l, *w2t_h, *w2t_l;

    cudaGetSymbolAddress((void**)&qkv,  g_qkv);
    cudaGetSymbolAddress((void**)&attn, g_attn);
    cudaGetSymbolAddress((void**)&qca,  g_qca);
    cudaGetSymbolAddress((void**)&kvca, g_kvca);
    cudaGetSymbolAddress((void**)&x2,   g_x2);
    cudaGetSymbolAddress((void**)&probs,g_probs);
    cudaGetSymbolAddress((void**)&gatev,g_gatev);
    cudaGetSymbolAddress((void**)&gidx, g_gidx);
    cudaGetSymbolAddress((void**)&sl,   g_sl);
    cudaGetSymbolAddress((void**)&rows, g_rows);
    cudaGetSymbolAddress((void**)&auxp, g_aux);
    cudaGetSymbolAddress((void**)&ybuf, g_y);
    cudaGetSymbolAddress((void**)&x3,   g_x3);
    cudaGetSymbolAddress((void**)&tgt_h, g_tgt_h); cudaGetSymbolAddress((void**)&tgt_l, g_tgt_l);
    cudaGetSymbolAddress((void**)&mem_h, g_mem_h); cudaGetSymbolAddress((void**)&mem_l, g_mem_l);
    cudaGetSymbolAddress((void**)&att_h, g_att_h); cudaGetSymbolAddress((void**)&att_l, g_att_l);
    cudaGetSymbolAddress((void**)&x1_h,  g_x1_h);  cudaGetSymbolAddress((void**)&x1_l,  g_x1_l);
    cudaGetSymbolAddress((void**)&buf_h, g_buf_h); cudaGetSymbolAddress((void**)&buf_l, g_buf_l);
    cudaGetSymbolAddress((void**)&hb_h,  g_hb_h);  cudaGetSymbolAddress((void**)&hb_l,  g_hb_l);
    cudaGetSymbolAddress((void**)&wqsa_h, g_wqsa_h); cudaGetSymbolAddress((void**)&wqsa_l, g_wqsa_l);
    cudaGetSymbolAddress((void**)&wosa_h, g_wosa_h); cudaGetSymbolAddress((void**)&wosa_l, g_wosa_l);
    cudaGetSymbolAddress((void**)&wqca_h, g_wqca_h); cudaGetSymbolAddress((void**)&wqca_l, g_wqca_l);
    cudaGetSymbolAddress((void**)&woca_h, g_woca_h); cudaGetSymbolAddress((void**)&woca_l, g_woca_l);
    cudaGetSymbolAddress((void**)&w1t_h, g_w1t_h); cudaGetSymbolAddress((void**)&w1t_l, g_w1t_l);
    cudaGetSymbolAddress((void**)&w2t_h, g_w2t_h); cudaGetSymbolAddress((void**)&w2t_l, g_w2t_l);

    cudaFuncSetAttribute(attn_kernel, cudaFuncAttributeMaxDynamicSharedMemorySize, ATTN_SMEM);
    cudaFuncSetAttribute(mmagemm_kernel<0,0>, cudaFuncAttributeMaxDynamicSharedMemorySize, GEMM_SMEM);
    cudaFuncSetAttribute(mmagemm_kernel<0,1>, cudaFuncAttributeMaxDynamicSharedMemorySize, GEMM_SMEM);
    cudaFuncSetAttribute(mmagemm_kernel<1,1>, cudaFuncAttributeMaxDynamicSharedMemorySize, GEMM_SMEM);

    // ---- weight & input conversions ----
    split_kernel<<<(3*DIM*DIM/4 + 255)/256, 256>>>((const float4*)w_qkv_sa, wqsa_h, wqsa_l, 3*DIM*DIM/4);
    split_kernel<<<(DIM*DIM/4 + 255)/256, 256>>>((const float4*)w_o_sa, wosa_h, wosa_l, DIM*DIM/4);
    split_kernel<<<(3*DIM*DIM/4 + 255)/256, 256>>>((const float4*)w_qkv_ca, wqca_h, wqca_l, 3*DIM*DIM/4);
    split_kernel<<<(DIM*DIM/4 + 255)/256, 256>>>((const float4*)w_o_ca, woca_h, woca_l, DIM*DIM/4);
    tsplit_kernel<<<dim3(DFF/32, DIM/32, NE), 256>>>(w1, w1t_h, w1t_l, DIM, DFF);
    tsplit_kernel<<<dim3(DIM/32, DFF/32, NE), 256>>>(w2, w2t_h, w2t_l, DFF, DIM);
    split_kernel<<<(NTOK*DIM/4 + 255)/256, 256>>>((const float4*)tgt, tgt_h, tgt_l, NTOK*DIM/4);
    split_kernel<<<(NTOK*DIM/4 + 255)/256, 256>>>((const float4*)mem, mem_h, mem_l, NTOK*DIM/4);

    // 1) SA qkv projection (NT)
    mmagemm_kernel<0,0><<<dim3(3072/128, NTOK/128, 1), 256, GEMM_SMEM>>>(
        tgt_h, tgt_l, wqsa_h, wqsa_l, b_qkv_sa, qkv, nullptr, nullptr,
        DIM, 3*DIM, 0, 0, 0, 0, nullptr);

    // 2) self-attention
    attn_kernel<<<dim3(SQ/64, NH, BB), 256, ATTN_SMEM>>>(
        qkv, 3*DIM, qkv + DIM, 3*DIM, qkv + 2*DIM, 3*DIM, attn, DIM, SQ);
    split_kernel<<<(NTOK*DIM/4 + 255)/256, 256>>>((const float4*)attn, att_h, att_l, NTOK*DIM/4);

    // 3) SA output projection -> x1 split
    mmagemm_kernel<0,1><<<dim3(DIM/128, NTOK/128, 1), 256, GEMM_SMEM>>>(
        att_h, att_l, wosa_h, wosa_l, b_o_sa, nullptr, x1_h, x1_l,
        DIM, DIM, 0, 0, 0, 0, nullptr);

    // 4) CA q projection -> fp32 qca
    mmagemm_kernel<0,0><<<dim3(DIM/128, NTOK/128, 1), 256, GEMM_SMEM>>>(
        x1_h, x1_l, wqca_h, wqca_l, b_qkv_ca, qca, nullptr, nullptr,
        DIM, DIM, 0, 0, 0, 0, nullptr);

    // 5) CA k,v projection from memory -> fp32 kvca
    mmagemm_kernel<0,0><<<dim3(2*DIM/128, NTOK/128, 1), 256, GEMM_SMEM>>>(
        mem_h, mem_l, wqca_h + (size_t)DIM*DIM, wqca_l + (size_t)DIM*DIM,
        b_qkv_ca + DIM, kvca, nullptr, nullptr,
        DIM, 2*DIM, 0, 0, 0, 0, nullptr);

    // 6) cross-attention
    attn_kernel<<<dim3(SQ/64, NH, BB), 256, ATTN_SMEM>>>(
        qca, DIM, kvca, 2*DIM, kvca + DIM, 2*DIM, attn, DIM, SQ);
    split_kernel<<<(NTOK*DIM/4 + 255)/256, 256>>>((const float4*)attn, att_h, att_l, NTOK*DIM/4);

    // 7) CA output projection -> fp32 x2
    mmagemm_kernel<0,0><<<dim3(DIM/128, NTOK/128, 1), 256, GEMM_SMEM>>>(
        att_h, att_l, woca_h, woca_l, b_o_ca, x2, nullptr, nullptr,
        DIM, DIM, 0, 0, 0, 0, nullptr);

    // 8-9) gating + routing
    gate_kernel<<<NTOK, 128>>>(x2, w_gate, probs, gatev, gidx);
    route_kernel<<<1, 256>>>(gidx, probs, sl, rows, auxp);

    // 10) scatter -> bf16 hi/lo expert buffer
    scatter_kernel<<<dim3(NTOK, 2), 256>>>(x2, gidx, sl, buf_h, buf_l);

    // 11) expert FFN layer 1 (+GELU, split-out), row-skip
    mmagemm_kernel<1,1><<<dim3(DFF/128, CAP/128, NE), 256, GEMM_SMEM>>>(
        buf_h, buf_l, w1t_h, w1t_l, b1e, nullptr, hb_h, hb_l,
        DIM, DFF, (long long)CAP*DIM, (long long)DFF*DIM, DFF, (long long)CAP*DFF, rows);

    // 12) expert FFN layer 2 -> fp32 ybuf, row-skip
    mmagemm_kernel<0,0><<<dim3(DIM/128, CAP/128, NE), 256, GEMM_SMEM>>>(
        hb_h, hb_l, w2t_h, w2t_l, b2e, ybuf, nullptr, nullptr,
        DFF, DIM, (long long)CAP*DFF, (long long)DIM*DFF, DIM, (long long)CAP*DIM, rows);

    // 13) gather
    gather_kernel<<<NTOK, 256>>>(ybuf, gidx, sl, gatev, x3);

    // 14) triple layernorm + aux
    ln3_kernel<<<NTOK, 256>>>(x3, ln1_g, ln1_b, ln2_g, ln2_b, ln3_g, ln3_b,
                              out, auxp, (long long)out_size);
}

// round 7
// speedup vs baseline: 1.6167x; 1.6167x over previous
#include <cuda_runtime.h>
#include <cuda_bf16.h>
#include <math.h>
#include <stdint.h>

// ---------------- problem constants ----------------
#define SQ   2048
#define BB   2
#define DIM  1024
#define NH   16
#define HD   64
#define NTOK 4096
#define NE   8
#define DFF  4096
#define CAP  2048
#define LN_EPS 1e-5f

// ---------------- scratch (device globals) ----------------
__device__ __nv_bfloat16 g_tgt_h[NTOK * DIM], g_tgt_l[NTOK * DIM];
__device__ __nv_bfloat16 g_mem_h[NTOK * DIM], g_mem_l[NTOK * DIM];
__device__ __nv_bfloat16 g_att_h[NTOK * DIM], g_att_l[NTOK * DIM];
__device__ __nv_bfloat16 g_x1_h [NTOK * DIM], g_x1_l [NTOK * DIM];
__device__ __nv_bfloat16 g_buf_h[NE * CAP * DIM], g_buf_l[NE * CAP * DIM];
__device__ __nv_bfloat16 g_hb_h[(size_t)NE * CAP * DFF], g_hb_l[(size_t)NE * CAP * DFF];
__device__ __nv_bfloat16 g_wqsa_h[3 * DIM * DIM], g_wqsa_l[3 * DIM * DIM];
__device__ __nv_bfloat16 g_wosa_h[DIM * DIM],     g_wosa_l[DIM * DIM];
__device__ __nv_bfloat16 g_wqca_h[3 * DIM * DIM], g_wqca_l[3 * DIM * DIM];
__device__ __nv_bfloat16 g_woca_h[DIM * DIM],     g_woca_l[DIM * DIM];
__device__ __nv_bfloat16 g_w1t_h[(size_t)NE * DIM * DFF], g_w1t_l[(size_t)NE * DIM * DFF];
__device__ __nv_bfloat16 g_w2t_h[(size_t)NE * DIM * DFF], g_w2t_l[(size_t)NE * DIM * DFF];
__device__ float g_qkv [NTOK * 3 * DIM];
__device__ float g_attn[NTOK * DIM];
__device__ float g_qca [NTOK * DIM];
__device__ float g_kvca[NTOK * 2 * DIM];
__device__ float g_x2  [NTOK * DIM];
__device__ float g_probs[NTOK * NE];
__device__ float g_gatev[NTOK * 2];
__device__ int   g_gidx[NTOK * 2];
__device__ int   g_sl  [NTOK * 2];
__device__ int   g_rows[NE];
__device__ float g_aux;
__device__ float g_y [NE * CAP * DIM];
__device__ float g_x3[NTOK * DIM];

__device__ __forceinline__ float gelu_exact(float x) {
    return 0.5f * x * (1.0f + erff(x * 0.70710678118654752440f));
}
__device__ __forceinline__ void split2(float v, __nv_bfloat16& h, __nv_bfloat16& l) {
    h = __float2bfloat16(v);
    l = __float2bfloat16(v - __bfloat162float(h));
}
__device__ __forceinline__ uint32_t smem_u32(const void* p) {
    uint32_t a;
    asm("{ .reg .u64 t; cvta.to.shared.u64 t, %1; cvt.u32.u64 %0, t; }" : "=r"(a) : "l"(p));
    return a;
}
#define CP_ASYNC16(s, g) \
    asm volatile("cp.async.cg.shared.global [%0], [%1], 16;" :: "r"(s), "l"(g))
#define CP_COMMIT() asm volatile("cp.async.commit_group;" ::: "memory")

__device__ __forceinline__ void mma16816(float* d, const uint32_t* a, const uint32_t* b) {
    asm volatile(
        "mma.sync.aligned.m16n8k16.row.col.f32.bf16.bf16.f32 "
        "{%0,%1,%2,%3}, {%4,%5,%6,%7}, {%8,%9}, {%0,%1,%2,%3};"
        : "+f"(d[0]), "+f"(d[1]), "+f"(d[2]), "+f"(d[3])
        : "r"(a[0]), "r"(a[1]), "r"(a[2]), "r"(a[3]), "r"(b[0]), "r"(b[1]));
}
#define LDSM_X4(r0, r1, r2, r3, addr) \
    asm volatile("ldmatrix.sync.aligned.m8n8.x4.shared.b16 {%0,%1,%2,%3}, [%4];" \
        : "=r"(r0), "=r"(r1), "=r"(r2), "=r"(r3) : "r"(addr))

// ---------------- bf16 mma NT GEMM, 3-term hi/lo split, ldmatrix path ----------------
// C[r,c] = sum_k A[r,k]*B[c,k] (+bias[c], opt GELU). A,B K-major bf16 hi/lo.
// 128x128 block, 8 warps (2x4), warp tile 64x32, K-chunk 32, cp.async double buffer.
#define TPAD       40                    // smem row stride in bf16 (80 bytes)
#define TILE_B     (128 * TPAD * 2)      // 10240 bytes
#define STAGE_B    (4 * TILE_B)          // Ah, Al, Bh, Bl
#define GEMM_SMEM  (2 * STAGE_B)         // 81920 bytes

template<int DOGELU, int SPLITOUT>
__global__ void __launch_bounds__(256, 2) mmagemm_kernel(
    const __nv_bfloat16* __restrict__ Ah, const __nv_bfloat16* __restrict__ Al,
    const __nv_bfloat16* __restrict__ Bh, const __nv_bfloat16* __restrict__ Bl,
    const float* __restrict__ bias, float* __restrict__ C,
    __nv_bfloat16* __restrict__ Ch, __nv_bfloat16* __restrict__ Cl,
    int K, int ldc,
    long long sA, long long sB, long long sBias, long long sC,
    const int* __restrict__ rows_used)
{
    extern __shared__ char smem[];
    const int z = blockIdx.z;
    if (rows_used && (int)(blockIdx.y * 128) >= rows_used[z]) return;

    const int tid = threadIdx.x, wid = tid >> 5, lane = tid & 31;
    const int wm = wid & 1, wn = wid >> 1;                 // 2 x 4 warp grid
    const long long rowBase = (long long)blockIdx.y * 128;
    const int colBase = blockIdx.x * 128;
    Ah += z * sA; Al += z * sA; Bh += z * sB; Bl += z * sB; bias += z * sBias;

    const __nv_bfloat16* src[4];
    src[0] = Ah + rowBase * K;
    src[1] = Al + rowBase * K;
    src[2] = Bh + (long long)colBase * K;
    src[3] = Bl + (long long)colBase * K;

    const uint32_t sbase = smem_u32(smem);
    const int NC = K >> 5;                                  // K chunks of 32

    auto prefetch = [&](int st, int kc) {
        const int koff = kc * 32;
        const uint32_t stb = sbase + st * STAGE_B;
        #pragma unroll
        for (int bi = 0; bi < 4; bi++) {
            const __nv_bfloat16* s = src[bi] + koff;
            const uint32_t tb = stb + bi * TILE_B;
            #pragma unroll
            for (int it = 0; it < 2; it++) {
                int idx = it * 256 + tid;
                int row = idx >> 2, c = idx & 3;
                CP_ASYNC16(tb + row * (TPAD * 2) + c * 16,
                           (const void*)(s + (long long)row * K + c * 8));
            }
        }
        CP_COMMIT();
    };

    float acc[4][4][4];
    #pragma unroll
    for (int i = 0; i < 4; i++)
        #pragma unroll
        for (int j = 0; j < 4; j++)
            #pragma unroll
            for (int r = 0; r < 4; r++) acc[i][j][r] = 0.f;

    // ldmatrix per-lane offset: row = (lane&7) + ((lane>>3)&1)*8, col16 = lane>>4
    const uint32_t lmoff =
        (uint32_t)(((lane & 7) + ((lane >> 3) & 1) * 8) * (TPAD * 2) + (lane >> 4) * 16);

    prefetch(0, 0);

    for (int ic = 0; ic < NC; ic++) {
        const int p = ic & 1;
        if (ic + 1 < NC) {
            prefetch(p ^ 1, ic + 1);
            asm volatile("cp.async.wait_group 1;" ::: "memory");
        } else {
            asm volatile("cp.async.wait_group 0;" ::: "memory");
        }
        __syncthreads();

        const uint32_t stp = sbase + p * STAGE_B;
        const uint32_t aHb = stp +              wm * 64 * (TPAD * 2) + lmoff;
        const uint32_t aLb = stp + TILE_B +     wm * 64 * (TPAD * 2) + lmoff;
        const uint32_t bHb = stp + 2 * TILE_B + wn * 32 * (TPAD * 2) + lmoff;
        const uint32_t bLb = stp + 3 * TILE_B + wn * 32 * (TPAD * 2) + lmoff;

        uint32_t afr[4][4];   // a[i] fragments
        uint32_t bfr[4][2];   // b[j] fragments

        #pragma unroll
        for (int ks = 0; ks < 2; ks++) {
            const uint32_t kb = ks * 32;     // 16 bf16 = 32 bytes per ks

            // ---- term 1: Ah x Bh ----
            #pragma unroll
            for (int i = 0; i < 4; i++)
                LDSM_X4(afr[i][0], afr[i][1], afr[i][2], afr[i][3],
                        aHb + i * 16 * (TPAD * 2) + kb);
            // b x4 load: mat0=(n0-7,k0)->b[j0][0], mat1=(n8-15,k0)->b[j1][0],
            //            mat2=(n0-7,k8)->b[j0][1], mat3=(n8-15,k8)->b[j1][1]
            #pragma unroll
            for (int pr = 0; pr < 2; pr++)
                LDSM_X4(bfr[pr * 2][0], bfr[pr * 2 + 1][0],
                        bfr[pr * 2][1], bfr[pr * 2 + 1][1],
                        bHb + pr * 16 * (TPAD * 2) + kb);
            #pragma unroll
            for (int i = 0; i < 4; i++)
                #pragma unroll
                for (int j = 0; j < 4; j++)
                    mma16816(acc[i][j], afr[i], bfr[j]);

            // ---- term 2: Al x Bh ----
            #pragma unroll
            for (int i = 0; i < 4; i++)
                LDSM_X4(afr[i][0], afr[i][1], afr[i][2], afr[i][3],
                        aLb + i * 16 * (TPAD * 2) + kb);
            #pragma unroll
            for (int i = 0; i < 4; i++)
                #pragma unroll
                for (int j = 0; j < 4; j++)
                    mma16816(acc[i][j], afr[i], bfr[j]);

            // ---- term 3: Ah x Bl ----
            #pragma unroll
            for (int i = 0; i < 4; i++)
                LDSM_X4(afr[i][0], afr[i][1], afr[i][2], afr[i][3],
                        aHb + i * 16 * (TPAD * 2) + kb);
            #pragma unroll
            for (int pr = 0; pr < 2; pr++)
                LDSM_X4(bfr[pr * 2][0], bfr[pr * 2 + 1][0],
                        bfr[pr * 2][1], bfr[pr * 2 + 1][1],
                        bLb + pr * 16 * (TPAD * 2) + kb);
            #pragma unroll
            for (int i = 0; i < 4; i++)
                #pragma unroll
                for (int j = 0; j < 4; j++)
                    mma16816(acc[i][j], afr[i], bfr[j]);
        }
        __syncthreads();
    }

    // epilogue: thread owns (r0 = lr, c = lc2, +8 row) per mma tile
    const int lr = lane >> 2, lc2 = (lane & 3) * 2;
    #pragma unroll
    for (int i = 0; i < 4; i++) {
        const int r0 = (int)rowBase + wm * 64 + i * 16 + lr;
        #pragma unroll
        for (int j = 0; j < 4; j++) {
            const int col = colBase + wn * 32 + j * 8 + lc2;
            float b0 = bias[col], b1 = bias[col + 1];
            float v0 = acc[i][j][0] + b0, v1 = acc[i][j][1] + b1;
            float v2 = acc[i][j][2] + b0, v3 = acc[i][j][3] + b1;
            if (DOGELU) {
                v0 = gelu_exact(v0); v1 = gelu_exact(v1);
                v2 = gelu_exact(v2); v3 = gelu_exact(v3);
            }
            if (SPLITOUT == 0) {
                float* c0 = C + ((long long)r0 * ldc + col) + z * sC;
                float* c1 = C + ((long long)(r0 + 8) * ldc + col) + z * sC;
                c0[0] = v0; c0[1] = v1;
                c1[0] = v2; c1[1] = v3;
            } else {
                long long o0 = (long long)r0 * ldc + col + z * sC;
                long long o1 = (long long)(r0 + 8) * ldc + col + z * sC;
                __nv_bfloat16 h0, l0, h1, l1, h2, l2, h3, l3;
                split2(v0, h0, l0); split2(v1, h1, l1);
                split2(v2, h2, l2); split2(v3, h3, l3);
                *(__nv_bfloat162*)(Ch + o0) = __halves2bfloat162(h0, h1);
                *(__nv_bfloat162*)(Cl + o0) = __halves2bfloat162(l0, l1);
                *(__nv_bfloat162*)(Ch + o1) = __halves2bfloat162(h2, h3);
                *(__nv_bfloat162*)(Cl + o1) = __halves2bfloat162(l2, l3);
            }
        }
    }
}

// ---------------- fp32 -> bf16 hi/lo split ----------------
__global__ void __launch_bounds__(256) split_kernel(
    const float4* __restrict__ x, __nv_bfloat16* __restrict__ h,
    __nv_bfloat16* __restrict__ l, int n4)
{
    int i = blockIdx.x * 256 + threadIdx.x;
    if (i >= n4) return;
    float4 v = x[i];
    __nv_bfloat16 h0, l0, h1, l1, h2, l2, h3, l3;
    split2(v.x, h0, l0); split2(v.y, h1, l1);
    split2(v.z, h2, l2); split2(v.w, h3, l3);
    ((__nv_bfloat162*)h)[2 * i]     = __halves2bfloat162(h0, h1);
    ((__nv_bfloat162*)h)[2 * i + 1] = __halves2bfloat162(h2, h3);
    ((__nv_bfloat162*)l)[2 * i]     = __halves2bfloat162(l0, l1);
    ((__nv_bfloat162*)l)[2 * i + 1] = __halves2bfloat162(l2, l3);
}

// ---------------- transpose + split: src[z][R][Cc] -> dst[z][Cc][R] ----------------
__global__ void __launch_bounds__(256) tsplit_kernel(
    const float* __restrict__ src, __nv_bfloat16* __restrict__ dh,
    __nv_bfloat16* __restrict__ dl, int R, int Cc)
{
    __shared__ float t[32][33];
    const long long zoff = (long long)blockIdx.z * R * Cc;
    src += zoff; dh += zoff; dl += zoff;
    const int r0 = blockIdx.y * 32, c0 = blockIdx.x * 32;
    const int tx = threadIdx.x & 31, ty = threadIdx.x >> 5;
    #pragma unroll
    for (int i = 0; i < 32; i += 8)
        t[ty + i][tx] = src[(long long)(r0 + ty + i) * Cc + c0 + tx];
    __syncthreads();
    #pragma unroll
    for (int i = 0; i < 32; i += 8) {
        float v = t[tx][ty + i];
        long long o = (long long)(c0 + ty + i) * R + r0 + tx;
        __nv_bfloat16 h, l;
        split2(v, h, l);
        dh[o] = h; dl[o] = l;
    }
}

// ---------------- flash attention (fp32, Br=Bc=64, hd=64) ----------------
#define ATTN_SMEM (4 * 64 * 65 * 4)
__global__ void __launch_bounds__(256) attn_kernel(
    const float* __restrict__ Qb, int ldq,
    const float* __restrict__ Kb, int ldk,
    const float* __restrict__ Vb, int ldv,
    float* __restrict__ Ob, int ldo, int Skv)
{
    extern __shared__ float sm[];
    float* Qs = sm;
    float* Ks = sm + 64 * 65;
    float* Vs = sm + 2 * 64 * 65;
    float* Ss = sm + 3 * 64 * 65;

    const int b = blockIdx.z, h = blockIdx.y, qt = blockIdx.x;
    const int tid = threadIdx.x, tx = tid & 15, ty = tid >> 4;
    const float* Q  = Qb + h * HD;
    const float* Kp = Kb + h * HD;
    const float* Vp = Vb + h * HD;

    for (int u = tid; u < 64 * 16; u += 256) {
        int r = u >> 4, c4 = (u & 15) << 2;
        long long tok = (long long)(qt * 64 + r) * BB + b;
        float4 v = *(const float4*)(Q + tok * ldq + c4);
        float* d = Qs + r * 65 + c4;
        d[0] = v.x * 0.125f; d[1] = v.y * 0.125f;
        d[2] = v.z * 0.125f; d[3] = v.w * 0.125f;
    }

    float o[4][4], mrow[4], lrow[4];
    #pragma unroll
    for (int i = 0; i < 4; i++) {
        mrow[i] = -1e30f; lrow[i] = 0.f;
        #pragma unroll
        for (int j = 0; j < 4; j++) o[i][j] = 0.f;
    }

    const int nkt = Skv / 64;
    for (int kt = 0; kt < nkt; kt++) {
        __syncthreads();
        for (int u = tid; u < 64 * 16; u += 256) {
            int r = u >> 4, c4 = (u & 15) << 2;
            long long tok = (long long)(kt * 64 + r) * BB + b;
            float4 kv = *(const float4*)(Kp + tok * ldk + c4);
            float* kd = Ks + r * 65 + c4;
            kd[0] = kv.x; kd[1] = kv.y; kd[2] = kv.z; kd[3] = kv.w;
            float4 vv = *(const float4*)(Vp + tok * ldv + c4);
            float* vd = Vs + r * 65 + c4;
            vd[0] = vv.x; vd[1] = vv.y; vd[2] = vv.z; vd[3] = vv.w;
        }
        __syncthreads();

        float s[4][4];
        #pragma unroll
        for (int i = 0; i < 4; i++)
            #pragma unroll
            for (int j = 0; j < 4; j++) s[i][j] = 0.f;

        #pragma unroll 4
        for (int k = 0; k < 64; k++) {
            float a[4], bb2[4];
            #pragma unroll
            for (int i = 0; i < 4; i++) a[i] = Qs[(ty * 4 + i) * 65 + k];
            #pragma unroll
            for (int j = 0; j < 4; j++) bb2[j] = Ks[(tx * 4 + j) * 65 + k];
            #pragma unroll
            for (int i = 0; i < 4; i++)
                #pragma unroll
                for (int j = 0; j < 4; j++)
                    s[i][j] = fmaf(a[i], bb2[j], s[i][j]);
        }

        #pragma unroll
        for (int i = 0; i < 4; i++) {
            float rmax = fmaxf(fmaxf(s[i][0], s[i][1]), fmaxf(s[i][2], s[i][3]));
            #pragma unroll
            for (int off = 8; off >= 1; off >>= 1)
                rmax = fmaxf(rmax, __shfl_xor_sync(0xffffffffu, rmax, off));
            float mn = fmaxf(mrow[i], rmax);
            float sc = __expf(mrow[i] - mn);
            float p0 = __expf(s[i][0] - mn);
            float p1 = __expf(s[i][1] - mn);
            float p2 = __expf(s[i][2] - mn);
            float p3 = __expf(s[i][3] - mn);
            float* sp = Ss + (ty * 4 + i) * 65 + tx * 4;
            sp[0] = p0; sp[1] = p1; sp[2] = p2; sp[3] = p3;
            float ps = p0 + p1 + p2 + p3;
            #pragma unroll
            for (int off = 8; off >= 1; off >>= 1)
                ps += __shfl_xor_sync(0xffffffffu, ps, off);
            lrow[i] = lrow[i] * sc + ps;
            mrow[i] = mn;
            #pragma unroll
            for (int j = 0; j < 4; j++) o[i][j] *= sc;
        }
        __syncthreads();

        #pragma unroll 4
        for (int k = 0; k < 64; k++) {
            float ss[4], vv[4];
            #pragma unroll
            for (int i = 0; i < 4; i++) ss[i] = Ss[(ty * 4 + i) * 65 + k];
            #pragma unroll
            for (int j = 0; j < 4; j++) vv[j] = Vs[k * 65 + tx * 4 + j];
            #pragma unroll
            for (int i = 0; i < 4; i++)
                #pragma unroll
                for (int j = 0; j < 4; j++)
                    o[i][j] = fmaf(ss[i], vv[j], o[i][j]);
        }
    }

    #pragma unroll
    for (int i = 0; i < 4; i++) {
        float inv = 1.0f / lrow[i];
        long long tok = (long long)(qt * 64 + ty * 4 + i) * BB + b;
        float* op = Ob + tok * ldo + h * HD + tx * 4;
        op[0] = o[i][0] * inv; op[1] = o[i][1] * inv;
        op[2] = o[i][2] * inv; op[3] = o[i][3] * inv;
    }
}

// ---------------- gating ----------------
__global__ void __launch_bounds__(128) gate_kernel(
    const float* __restrict__ x, const float* __restrict__ wg,
    float* __restrict__ probs, float* __restrict__ gatev, int* __restrict__ gidx)
{
    const int t = blockIdx.x, tid = threadIdx.x;
    __shared__ float red[128][8];
    float acc[8];
    #pragma unroll
    for (int e = 0; e < 8; e++) acc[e] = 0.f;
    for (int d = tid; d < DIM; d += 128) {
        float xv = x[(long long)t * DIM + d];
        const float4* w = (const float4*)(wg + d * 8);
        float4 w0 = w[0], w1 = w[1];
        acc[0] += xv * w0.x; acc[1] += xv * w0.y; acc[2] += xv * w0.z; acc[3] += xv * w0.w;
        acc[4] += xv * w1.x; acc[5] += xv * w1.y; acc[6] += xv * w1.z; acc[7] += xv * w1.w;
    }
    #pragma unroll
    for (int e = 0; e < 8; e++) red[tid][e] = acc[e];
    __syncthreads();
    for (int s = 64; s > 0; s >>= 1) {
        if (tid < s)
            #pragma unroll
            for (int e = 0; e < 8; e++) red[tid][e] += red[tid + s][e];
        __syncthreads();
    }
    if (tid == 0) {
        float l[8], mx = -1e30f;
        #pragma unroll
        for (int e = 0; e < 8; e++) { l[e] = red[0][e]; mx = fmaxf(mx, l[e]); }
        float sum = 0.f;
        #pragma unroll
        for (int e = 0; e < 8; e++) { l[e] = __expf(l[e] - mx); sum += l[e]; }
        float inv = 1.0f / sum;
        #pragma unroll
        for (int e = 0; e < 8; e++) { l[e] *= inv; probs[t * 8 + e] = l[e]; }
        int i1 = 0; float v1 = l[0];
        #pragma unroll
        for (int e = 1; e < 8; e++) if (l[e] > v1) { v1 = l[e]; i1 = e; }
        int i2 = -1; float v2 = -1.f;
        #pragma unroll
        for (int e = 0; e < 8; e++) if (e != i1 && l[e] > v2) { v2 = l[e]; i2 = e; }
        gatev[2 * t] = v1; gatev[2 * t + 1] = v2;
        gidx[2 * t] = i1;  gidx[2 * t + 1] = i2;
    }
}

// ---------------- routing ----------------
__global__ void __launch_bounds__(256) route_kernel(
    const int* __restrict__ gidx, const float* __restrict__ probs,
    int* __restrict__ sl, int* __restrict__ rows, float* __restrict__ auxp)
{
    __shared__ signed char s1[NTOK];
    __shared__ signed char s2[NTOK];
    __shared__ int cnt1[8];
    __shared__ float pr[256 * 8];
    const int tid = threadIdx.x;

    for (int i = tid; i < NTOK; i += 256) {
        int2 v = ((const int2*)gidx)[i];
        s1[i] = (signed char)v.x; s2[i] = (signed char)v.y;
    }
    float lp[8];
    #pragma unroll
    for (int e = 0; e < 8; e++) lp[e] = 0.f;
    for (int i = tid; i < NTOK; i += 256) {
        const float4* p = (const float4*)(probs + i * 8);
        float4 p0 = p[0], p1 = p[1];
        lp[0] += p0.x; lp[1] += p0.y; lp[2] += p0.z; lp[3] += p0.w;
        lp[4] += p1.x; lp[5] += p1.y; lp[6] += p1.z; lp[7] += p1.w;
    }
    #pragma unroll
    for (int e = 0; e < 8; e++) pr[tid * 8 + e] = lp[e];
    __syncthreads();
    for (int s = 128; s > 0; s >>= 1) {
        if (tid < s)
            #pragma unroll
            for (int e = 0; e < 8; e++) pr[tid * 8 + e] += pr[(tid + s) * 8 + e];
        __syncthreads();
    }

    if (tid < 8) {
        int e = tid, c = 0;
        #pragma unroll 1
        for (int i = 0; i < NTOK; i++)
            if (s1[i] == e) { sl[2 * i] = (c < CAP) ? c : -1; c++; }
        cnt1[e] = c;
    }
    __syncthreads();
    if (tid < 8) {
        int e = tid, base = cnt1[e], c = 0;
        #pragma unroll 1
        for (int i = 0; i < NTOK; i++)
            if (s2[i] == e) { int loc = base + c; sl[2 * i + 1] = (loc < CAP) ? loc : -1; c++; }
        int ru = cnt1[e] + c; if (ru > CAP) ru = CAP;
        rows[e] = ru;
    }
    __syncthreads();
    if (tid == 0) {
        float a = 0.f;
        for (int e = 0; e < 8; e++)
            a += ((float)cnt1[e] / (float)NTOK) * (pr[e] / (float)NTOK);
        *auxp = 0.01f * 8.0f * a;
    }
}

// ---------------- scatter (writes bf16 hi/lo) ----------------
__global__ void __launch_bounds__(256) scatter_kernel(
    const float* __restrict__ x, const int* __restrict__ gidx,
    const int* __restrict__ sl, __nv_bfloat16* __restrict__ bh,
    __nv_bfloat16* __restrict__ bl)
{
    const int t = blockIdx.x, ch = blockIdx.y;
    const int s = sl[2 * t + ch];
    if (s < 0) return;
    const int e = gidx[2 * t + ch];
    float4 v = ((const float4*)(x + (long long)t * DIM))[threadIdx.x];
    size_t base = ((size_t)e * CAP + s) * DIM + threadIdx.x * 4;
    __nv_bfloat16 h0, l0, h1, l1, h2, l2, h3, l3;
    split2(v.x, h0, l0); split2(v.y, h1, l1);
    split2(v.z, h2, l2); split2(v.w, h3, l3);
    *(__nv_bfloat162*)(bh + base)     = __halves2bfloat162(h0, h1);
    *(__nv_bfloat162*)(bh + base + 2) = __halves2bfloat162(h2, h3);
    *(__nv_bfloat162*)(bl + base)     = __halves2bfloat162(l0, l1);
    *(__nv_bfloat162*)(bl + base + 2) = __halves2bfloat162(l2, l3);
}

// ---------------- gather ----------------
__global__ void __launch_bounds__(256) gather_kernel(
    const float* __restrict__ y, const int* __restrict__ gidx,
    const int* __restrict__ sl, const float* __restrict__ gatev,
    float* __restrict__ out)
{
    const int t = blockIdx.x;
    const float gv1 = gatev[2 * t], gv2 = gatev[2 * t + 1];
    const int s1 = sl[2 * t], s2 = sl[2 * t + 1];
    const int e1 = gidx[2 * t], e2 = gidx[2 * t + 1];
    float4 r = make_float4(0.f, 0.f, 0.f, 0.f);
    if (s1 >= 0) {
        float4 a = ((const float4*)(y + ((size_t)e1 * CAP + s1) * DIM))[threadIdx.x];
        r.x += gv1 * a.x; r.y += gv1 * a.y; r.z += gv1 * a.z; r.w += gv1 * a.w;
    }
    if (s2 >= 0) {
        float4 a = ((const float4*)(y + ((size_t)e2 * CAP + s2) * DIM))[threadIdx.x];
        r.x += gv2 * a.x; r.y += gv2 * a.y; r.z += gv2 * a.z; r.w += gv2 * a.w;
    }
    ((float4*)(out + (long long)t * DIM))[threadIdx.x] = r;
}

// ---------------- triple layernorm + aux ----------------
__device__ __forceinline__ float block_sum(float v, float* red) {
    int tid = threadIdx.x;
    red[tid] = v; __syncthreads();
    for (int s = 128; s > 0; s >>= 1) {
        if (tid < s) red[tid] += red[tid + s];
        __syncthreads();
    }
    float r = red[0]; __syncthreads();
    return r;
}

__global__ void __launch_bounds__(256) ln3_kernel(
    const float* __restrict__ x,
    const float* __restrict__ g1, const float* __restrict__ b1,
    const float* __restrict__ g2, const float* __restrict__ b2,
    const float* __restrict__ g3, const float* __restrict__ b3,
    float* __restrict__ out, const float* __restrict__ auxp, long long out_size)
{
    __shared__ float red[256];
    const int t = blockIdx.x, tid = threadIdx.x;
    float4 v = ((const float4*)(x + (long long)t * DIM))[tid];

    const float* gs[3] = {g1, g2, g3};
    const float* bs[3] = {b1, b2, b3};
    #pragma unroll
    for (int r3 = 0; r3 < 3; r3++) {
        float s = v.x + v.y + v.z + v.w;
        float mean = block_sum(s, red) * (1.0f / DIM);
        float dx = v.x - mean, dy = v.y - mean, dz = v.z - mean, dw = v.w - mean;
        float s2 = dx * dx + dy * dy + dz * dz + dw * dw;
        float var = block_sum(s2, red) * (1.0f / DIM);
        float rstd = rsqrtf(var + LN_EPS);
        float4 gg = ((const float4*)gs[r3])[tid];
        float4 bb = ((const float4*)bs[r3])[tid];
        v.x = dx * rstd * gg.x + bb.x;
        v.y = dy * rstd * gg.y + bb.y;
        v.z = dz * rstd * gg.z + bb.z;
        v.w = dw * rstd * gg.w + bb.w;
    }
    ((float4*)(out + (long long)t * DIM))[tid] = v;
    if (t == 0 && tid == 0 && out_size > (long long)NTOK * DIM)
        out[(long long)NTOK * DIM] = *auxp;
}

// ---------------- launch ----------------
extern "C" void kernel_launch(void* const* d_in, const int* in_sizes, int n_in,
                              void* d_out, int out_size) {
    const float* tgt      = (const float*)d_in[0];
    const float* mem      = (const float*)d_in[1];
    const float* w_qkv_sa = (const float*)d_in[2];
    const float* b_qkv_sa = (const float*)d_in[3];
    const float* w_o_sa   = (const float*)d_in[4];
    const float* b_o_sa   = (const float*)d_in[5];
    const float* w_qkv_ca = (const float*)d_in[6];
    const float* b_qkv_ca = (const float*)d_in[7];
    const float* w_o_ca   = (const float*)d_in[8];
    const float* b_o_ca   = (const float*)d_in[9];
    const float* ln1_g = (const float*)d_in[10];
    const float* ln1_b = (const float*)d_in[11];
    const float* ln2_g = (const float*)d_in[12];
    const float* ln2_b = (const float*)d_in[13];
    const float* ln3_g = (const float*)d_in[14];
    const float* ln3_b = (const float*)d_in[15];
    const float* w_gate = (const float*)d_in[16];
    const float* w1  = (const float*)d_in[17];
    const float* b1e = (const float*)d_in[18];
    const float* w2  = (const float*)d_in[19];
    const float* b2e = (const float*)d_in[20];
    float* out = (float*)d_out;

    float *qkv, *attn, *qca, *kvca, *x2, *probs, *gatev, *x3, *ybuf, *auxp;
    int *gidx, *sl, *rows;
    __nv_bfloat16 *tgt_h, *tgt_l, *mem_h, *mem_l, *att_h, *att_l, *x1_h, *x1_l;
    __nv_bfloat16 *buf_h, *buf_l, *hb_h, *hb_l;
    __nv_bfloat16 *wqsa_h, *wqsa_l, *wosa_h, *wosa_l, *wqca_h, *wqca_l, *woca_h, *woca_l;
    __nv_bfloat16 *w1t_h, *w1t_l, *w2t_h, *w2t_l;

    cudaGetSymbolAddress((void**)&qkv,  g_qkv);
    cudaGetSymbolAddress((void**)&attn, g_attn);
    cudaGetSymbolAddress((void**)&qca,  g_qca);
    cudaGetSymbolAddress((void**)&kvca, g_kvca);
    cudaGetSymbolAddress((void**)&x2,   g_x2);
    cudaGetSymbolAddress((void**)&probs,g_probs);
    cudaGetSymbolAddress((void**)&gatev,g_gatev);
    cudaGetSymbolAddress((void**)&gidx, g_gidx);
    cudaGetSymbolAddress((void**)&sl,   g_sl);
    cudaGetSymbolAddress((void**)&rows, g_rows);
    cudaGetSymbolAddress((void**)&auxp, g_aux);
    cudaGetSymbolAddress((void**)&ybuf, g_y);
    cudaGetSymbolAddress((void**)&x3,   g_x3);
    cudaGetSymbolAddress((void**)&tgt_h, g_tgt_h); cudaGetSymbolAddress((void**)&tgt_l, g_tgt_l);
    cudaGetSymbolAddress((void**)&mem_h, g_mem_h); cudaGetSymbolAddress((void**)&mem_l, g_mem_l);
    cudaGetSymbolAddress((void**)&att_h, g_att_h); cudaGetSymbolAddress((void**)&att_l, g_att_l);
    cudaGetSymbolAddress((void**)&x1_h,  g_x1_h);  cudaGetSymbolAddress((void**)&x1_l,  g_x1_l);
    cudaGetSymbolAddress((void**)&buf_h, g_buf_h); cudaGetSymbolAddress((void**)&buf_l, g_buf_l);
    cudaGetSymbolAddress((void**)&hb_h,  g_hb_h);  cudaGetSymbolAddress((void**)&hb_l,  g_hb_l);
    cudaGetSymbolAddress((void**)&wqsa_h, g_wqsa_h); cudaGetSymbolAddress((void**)&wqsa_l, g_wqsa_l);
    cudaGetSymbolAddress((void**)&wosa_h, g_wosa_h); cudaGetSymbolAddress((void**)&wosa_l, g_wosa_l);
    cudaGetSymbolAddress((void**)&wqca_h, g_wqca_h); cudaGetSymbolAddress((void**)&wqca_l, g_wqca_l);
    cudaGetSymbolAddress((void**)&woca_h, g_woca_h); cudaGetSymbolAddress((void**)&woca_l, g_woca_l);
    cudaGetSymbolAddress((void**)&w1t_h, g_w1t_h); cudaGetSymbolAddress((void**)&w1t_l, g_w1t_l);
    cudaGetSymbolAddress((void**)&w2t_h, g_w2t_h); cudaGetSymbolAddress((void**)&w2t_l, g_w2t_l);

    cudaFuncSetAttribute(attn_kernel, cudaFuncAttributeMaxDynamicSharedMemorySize, ATTN_SMEM);
    cudaFuncSetAttribute(mmagemm_kernel<0,0>, cudaFuncAttributeMaxDynamicSharedMemorySize, GEMM_SMEM);
    cudaFuncSetAttribute(mmagemm_kernel<0,1>, cudaFuncAttributeMaxDynamicSharedMemorySize, GEMM_SMEM);
    cudaFuncSetAttribute(mmagemm_kernel<1,1>, cudaFuncAttributeMaxDynamicSharedMemorySize, GEMM_SMEM);

    // ---- weight & input conversions ----
    split_kernel<<<(3*DIM*DIM/4 + 255)/256, 256>>>((const float4*)w_qkv_sa, wqsa_h, wqsa_l, 3*DIM*DIM/4);
    split_kernel<<<(DIM*DIM/4 + 255)/256, 256>>>((const float4*)w_o_sa, wosa_h, wosa_l, DIM*DIM/4);
    split_kernel<<<(3*DIM*DIM/4 + 255)/256, 256>>>((const float4*)w_qkv_ca, wqca_h, wqca_l, 3*DIM*DIM/4);
    split_kernel<<<(DIM*DIM/4 + 255)/256, 256>>>((const float4*)w_o_ca, woca_h, woca_l, DIM*DIM/4);
    tsplit_kernel<<<dim3(DFF/32, DIM/32, NE), 256>>>(w1, w1t_h, w1t_l, DIM, DFF);
    tsplit_kernel<<<dim3(DIM/32, DFF/32, NE), 256>>>(w2, w2t_h, w2t_l, DFF, DIM);
    split_kernel<<<(NTOK*DIM/4 + 255)/256, 256>>>((const float4*)tgt, tgt_h, tgt_l, NTOK*DIM/4);
    split_kernel<<<(NTOK*DIM/4 + 255)/256, 256>>>((const float4*)mem, mem_h, mem_l, NTOK*DIM/4);

    // 1) SA qkv projection (NT)
    mmagemm_kernel<0,0><<<dim3(3072/128, NTOK/128, 1), 256, GEMM_SMEM>>>(
        tgt_h, tgt_l, wqsa_h, wqsa_l, b_qkv_sa, qkv, nullptr, nullptr,
        DIM, 3*DIM, 0, 0, 0, 0, nullptr);

    // 2) self-attention
    attn_kernel<<<dim3(SQ/64, NH, BB), 256, ATTN_SMEM>>>(
        qkv, 3*DIM, qkv + DIM, 3*DIM, qkv + 2*DIM, 3*DIM, attn, DIM, SQ);
    split_kernel<<<(NTOK*DIM/4 + 255)/256, 256>>>((const float4*)attn, att_h, att_l, NTOK*DIM/4);

    // 3) SA output projection -> x1 split
    mmagemm_kernel<0,1><<<dim3(DIM/128, NTOK/128, 1), 256, GEMM_SMEM>>>(
        att_h, att_l, wosa_h, wosa_l, b_o_sa, nullptr, x1_h, x1_l,
        DIM, DIM, 0, 0, 0, 0, nullptr);

    // 4) CA q projection -> fp32 qca
    mmagemm_kernel<0,0><<<dim3(DIM/128, NTOK/128, 1), 256, GEMM_SMEM>>>(
        x1_h, x1_l, wqca_h, wqca_l, b_qkv_ca, qca, nullptr, nullptr,
        DIM, DIM, 0, 0, 0, 0, nullptr);

    // 5) CA k,v projection from memory -> fp32 kvca
    mmagemm_kernel<0,0><<<dim3(2*DIM/128, NTOK/128, 1), 256, GEMM_SMEM>>>(
        mem_h, mem_l, wqca_h + (size_t)DIM*DIM, wqca_l + (size_t)DIM*DIM,
        b_qkv_ca + DIM, kvca, nullptr, nullptr,
        DIM, 2*DIM, 0, 0, 0, 0, nullptr);

    // 6) cross-attention
    attn_kernel<<<dim3(SQ/64, NH, BB), 256, ATTN_SMEM>>>(
        qca, DIM, kvca, 2*DIM, kvca + DIM, 2*DIM, attn, DIM, SQ);
    split_kernel<<<(NTOK*DIM/4 + 255)/256, 256>>>((const float4*)attn, att_h, att_l, NTOK*DIM/4);

    // 7) CA output projection -> fp32 x2
    mmagemm_kernel<0,0><<<dim3(DIM/128, NTOK/128, 1), 256, GEMM_SMEM>>>(
        att_h, att_l, woca_h, woca_l, b_o_ca, x2, nullptr, nullptr,
        DIM, DIM, 0, 0, 0, 0, nullptr);

    // 8-9) gating + routing
    gate_kernel<<<NTOK, 128>>>(x2, w_gate, probs, gatev, gidx);
    route_kernel<<<1, 256>>>(gidx, probs, sl, rows, auxp);

    // 10) scatter -> bf16 hi/lo expert buffer
    scatter_kernel<<<dim3(NTOK, 2), 256>>>(x2, gidx, sl, buf_h, buf_l);

    // 11) expert FFN layer 1 (+GELU, split-out), row-skip
    mmagemm_kernel<1,1><<<dim3(DFF/128, CAP/128, NE), 256, GEMM_SMEM>>>(
        buf_h, buf_l, w1t_h, w1t_l, b1e, nullptr, hb_h, hb_l,
        DIM, DFF, (long long)CAP*DIM, (long long)DFF*DIM, DFF, (long long)CAP*DFF, rows);

    // 12) expert FFN layer 2 -> fp32 ybuf, row-skip
    mmagemm_kernel<0,0><<<dim3(DIM/128, CAP/128, NE), 256, GEMM_SMEM>>>(
        hb_h, hb_l, w2t_h, w2t_l, b2e, ybuf, nullptr, nullptr,
        DFF, DIM, (long long)CAP*DFF, (long long)DIM*DFF, DIM, (long long)CAP*DIM, rows);

    // 13) gather
    gather_kernel<<<NTOK, 256>>>(ybuf, gidx, sl, gatev, x3);

    // 14) triple layernorm + aux
    ln3_kernel<<<NTOK, 256>>>(x3, ln1_g, ln1_b, ln2_g, ln2_b, ln3_g, ln3_b,
                              out, auxp, (long long)out_size);
}

// round 9
// speedup vs baseline: 2.3180x; 1.4338x over previous
#include <cuda_runtime.h>
#include <cuda_bf16.h>
#include <math.h>
#include <stdint.h>

// ---------------- problem constants ----------------
#define SQ   2048
#define BB   2
#define DIM  1024
#define NH   16
#define HD   64
#define NTOK 4096
#define NE   8
#define DFF  4096
#define CAP  2048
#define LN_EPS 1e-5f

// ---------------- scratch (device globals) ----------------
__device__ __nv_bfloat16 g_tgt_h[NTOK * DIM], g_tgt_l[NTOK * DIM];
__device__ __nv_bfloat16 g_mem_h[NTOK * DIM], g_mem_l[NTOK * DIM];
__device__ __nv_bfloat16 g_att_h[NTOK * DIM], g_att_l[NTOK * DIM];
__device__ __nv_bfloat16 g_x1_h [NTOK * DIM], g_x1_l [NTOK * DIM];
__device__ __nv_bfloat16 g_buf_h[NE * CAP * DIM], g_buf_l[NE * CAP * DIM];
__device__ __nv_bfloat16 g_hb_h[(size_t)NE * CAP * DFF], g_hb_l[(size_t)NE * CAP * DFF];
__device__ __nv_bfloat16 g_wqsa_h[3 * DIM * DIM], g_wqsa_l[3 * DIM * DIM];
__device__ __nv_bfloat16 g_wosa_h[DIM * DIM],     g_wosa_l[DIM * DIM];
__device__ __nv_bfloat16 g_wqca_h[3 * DIM * DIM], g_wqca_l[3 * DIM * DIM];
__device__ __nv_bfloat16 g_woca_h[DIM * DIM],     g_woca_l[DIM * DIM];
__device__ __nv_bfloat16 g_w1t_h[(size_t)NE * DIM * DFF], g_w1t_l[(size_t)NE * DIM * DFF];
__device__ __nv_bfloat16 g_w2t_h[(size_t)NE * DIM * DFF], g_w2t_l[(size_t)NE * DIM * DFF];
__device__ float g_qkv [NTOK * 3 * DIM];
__device__ float g_attn[NTOK * DIM];
__device__ float g_qca [NTOK * DIM];
__device__ float g_kvca[NTOK * 2 * DIM];
__device__ float g_x2  [NTOK * DIM];
__device__ float g_probs[NTOK * NE];
__device__ float g_gatev[NTOK * 2];
__device__ int   g_gidx[NTOK * 2];
__device__ int   g_sl  [NTOK * 2];
__device__ int   g_rows[NE];
__device__ float g_aux;
__device__ float g_y [NE * CAP * DIM];
__device__ float g_x3[NTOK * DIM];

__device__ __forceinline__ float gelu_exact(float x) {
    return 0.5f * x * (1.0f + erff(x * 0.70710678118654752440f));
}
__device__ __forceinline__ void split2(float v, __nv_bfloat16& h, __nv_bfloat16& l) {
    h = __float2bfloat16(v);
    l = __float2bfloat16(v - __bfloat162float(h));
}
__device__ __forceinline__ uint32_t smem_u32(const void* p) {
    uint32_t a;
    asm("{ .reg .u64 t; cvta.to.shared.u64 t, %1; cvt.u32.u64 %0, t; }" : "=r"(a) : "l"(p));
    return a;
}
__device__ __forceinline__ uint32_t packbf(float a, float b) {
    __nv_bfloat162 t = __floats2bfloat162_rn(a, b);
    return *(uint32_t*)&t;
}
// pack hi parts and lo parts of (a,b) into two b16x2 regs
__device__ __forceinline__ void packsplit(float a, float b, uint32_t& hi, uint32_t& lo) {
    __nv_bfloat16 ha, la, hb, lb;
    split2(a, ha, la); split2(b, hb, lb);
    __nv_bfloat162 th = __halves2bfloat162(ha, hb);
    __nv_bfloat162 tl = __halves2bfloat162(la, lb);
    hi = *(uint32_t*)&th; lo = *(uint32_t*)&tl;
}
#define CP_ASYNC16(s, g) \
    asm volatile("cp.async.cg.shared.global [%0], [%1], 16;" :: "r"(s), "l"(g))
#define CP_COMMIT() asm volatile("cp.async.commit_group;" ::: "memory")

__device__ __forceinline__ void mma16816(float* d, const uint32_t* a, const uint32_t* b) {
    asm volatile(
        "mma.sync.aligned.m16n8k16.row.col.f32.bf16.bf16.f32 "
        "{%0,%1,%2,%3}, {%4,%5,%6,%7}, {%8,%9}, {%0,%1,%2,%3};"
        : "+f"(d[0]), "+f"(d[1]), "+f"(d[2]), "+f"(d[3])
        : "r"(a[0]), "r"(a[1]), "r"(a[2]), "r"(a[3]), "r"(b[0]), "r"(b[1]));
}
#define LDSM_X4(r0, r1, r2, r3, addr) \
    asm volatile("ldmatrix.sync.aligned.m8n8.x4.shared.b16 {%0,%1,%2,%3}, [%4];" \
        : "=r"(r0), "=r"(r1), "=r"(r2), "=r"(r3) : "r"(addr))
#define LDSM_X4_T(r0, r1, r2, r3, addr) \
    asm volatile("ldmatrix.sync.aligned.m8n8.x4.trans.shared.b16 {%0,%1,%2,%3}, [%4];" \
        : "=r"(r0), "=r"(r1), "=r"(r2), "=r"(r3) : "r"(addr))

// ---------------- bf16 mma NT GEMM, 3-term hi/lo split, ldmatrix path ----------------
#define TPAD       40                    // smem row stride in bf16 (80 bytes)
#define TILE_B     (128 * TPAD * 2)      // 10240 bytes
#define STAGE_B    (4 * TILE_B)
#define GEMM_SMEM  (2 * STAGE_B)         // 81920 bytes

template<int DOGELU, int SPLITOUT>
__global__ void __launch_bounds__(256, 2) mmagemm_kernel(
    const __nv_bfloat16* __restrict__ Ah, const __nv_bfloat16* __restrict__ Al,
    const __nv_bfloat16* __restrict__ Bh, const __nv_bfloat16* __restrict__ Bl,
    const float* __restrict__ bias, float* __restrict__ C,
    __nv_bfloat16* __restrict__ Ch, __nv_bfloat16* __restrict__ Cl,
    int K, int ldc,
    long long sA, long long sB, long long sBias, long long sC,
    const int* __restrict__ rows_used)
{
    extern __shared__ char smem[];
    const int z = blockIdx.z;
    if (rows_used && (int)(blockIdx.y * 128) >= rows_used[z]) return;

    const int tid = threadIdx.x, wid = tid >> 5, lane = tid & 31;
    const int wm = wid & 1, wn = wid >> 1;
    const long long rowBase = (long long)blockIdx.y * 128;
    const int colBase = blockIdx.x * 128;
    Ah += z * sA; Al += z * sA; Bh += z * sB; Bl += z * sB; bias += z * sBias;

    const __nv_bfloat16* src[4];
    src[0] = Ah + rowBase * K;
    src[1] = Al + rowBase * K;
    src[2] = Bh + (long long)colBase * K;
    src[3] = Bl + (long long)colBase * K;

    const uint32_t sbase = smem_u32(smem);
    const int NC = K >> 5;

    auto prefetch = [&](int st, int kc) {
        const int koff = kc * 32;
        const uint32_t stb = sbase + st * STAGE_B;
        #pragma unroll
        for (int bi = 0; bi < 4; bi++) {
            const __nv_bfloat16* s = src[bi] + koff;
            const uint32_t tb = stb + bi * TILE_B;
            #pragma unroll
            for (int it = 0; it < 2; it++) {
                int idx = it * 256 + tid;
                int row = idx >> 2, c = idx & 3;
                CP_ASYNC16(tb + row * (TPAD * 2) + c * 16,
                           (const void*)(s + (long long)row * K + c * 8));
            }
        }
        CP_COMMIT();
    };

    float acc[4][4][4];
    #pragma unroll
    for (int i = 0; i < 4; i++)
        #pragma unroll
        for (int j = 0; j < 4; j++)
            #pragma unroll
            for (int r = 0; r < 4; r++) acc[i][j][r] = 0.f;

    const uint32_t lmoff =
        (uint32_t)(((lane & 7) + ((lane >> 3) & 1) * 8) * (TPAD * 2) + (lane >> 4) * 16);

    prefetch(0, 0);

    for (int ic = 0; ic < NC; ic++) {
        const int p = ic & 1;
        if (ic + 1 < NC) {
            prefetch(p ^ 1, ic + 1);
            asm volatile("cp.async.wait_group 1;" ::: "memory");
        } else {
            asm volatile("cp.async.wait_group 0;" ::: "memory");
        }
        __syncthreads();

        const uint32_t stp = sbase + p * STAGE_B;
        const uint32_t aHb = stp +              wm * 64 * (TPAD * 2) + lmoff;
        const uint32_t aLb = stp + TILE_B +     wm * 64 * (TPAD * 2) + lmoff;
        const uint32_t bHb = stp + 2 * TILE_B + wn * 32 * (TPAD * 2) + lmoff;
        const uint32_t bLb = stp + 3 * TILE_B + wn * 32 * (TPAD * 2) + lmoff;

        uint32_t afr[4][4];
        uint32_t bfr[4][2];

        #pragma unroll
        for (int ks = 0; ks < 2; ks++) {
            const uint32_t kb = ks * 32;

            #pragma unroll
            for (int i = 0; i < 4; i++)
                LDSM_X4(afr[i][0], afr[i][1], afr[i][2], afr[i][3],
                        aHb + i * 16 * (TPAD * 2) + kb);
            #pragma unroll
            for (int pr = 0; pr < 2; pr++)
                LDSM_X4(bfr[pr * 2][0], bfr[pr * 2 + 1][0],
                        bfr[pr * 2][1], bfr[pr * 2 + 1][1],
                        bHb + pr * 16 * (TPAD * 2) + kb);
            #pragma unroll
            for (int i = 0; i < 4; i++)
                #pragma unroll
                for (int j = 0; j < 4; j++)
                    mma16816(acc[i][j], afr[i], bfr[j]);

            #pragma unroll
            for (int i = 0; i < 4; i++)
                LDSM_X4(afr[i][0], afr[i][1], afr[i][2], afr[i][3],
                        aLb + i * 16 * (TPAD * 2) + kb);
            #pragma unroll
            for (int i = 0; i < 4; i++)
                #pragma unroll
                for (int j = 0; j < 4; j++)
                    mma16816(acc[i][j], afr[i], bfr[j]);

            #pragma unroll
            for (int i = 0; i < 4; i++)
                LDSM_X4(afr[i][0], afr[i][1], afr[i][2], afr[i][3],
                        aHb + i * 16 * (TPAD * 2) + kb);
            #pragma unroll
            for (int pr = 0; pr < 2; pr++)
                LDSM_X4(bfr[pr * 2][0], bfr[pr * 2 + 1][0],
                        bfr[pr * 2][1], bfr[pr * 2 + 1][1],
                        bLb + pr * 16 * (TPAD * 2) + kb);
            #pragma unroll
            for (int i = 0; i < 4; i++)
                #pragma unroll
                for (int j = 0; j < 4; j++)
                    mma16816(acc[i][j], afr[i], bfr[j]);
        }
        __syncthreads();
    }

    const int lr = lane >> 2, lc2 = (lane & 3) * 2;
    #pragma unroll
    for (int i = 0; i < 4; i++) {
        const int r0 = (int)rowBase + wm * 64 + i * 16 + lr;
        #pragma unroll
        for (int j = 0; j < 4; j++) {
            const int col = colBase + wn * 32 + j * 8 + lc2;
            float b0 = bias[col], b1 = bias[col + 1];
            float v0 = acc[i][j][0] + b0, v1 = acc[i][j][1] + b1;
            float v2 = acc[i][j][2] + b0, v3 = acc[i][j][3] + b1;
            if (DOGELU) {
                v0 = gelu_exact(v0); v1 = gelu_exact(v1);
                v2 = gelu_exact(v2); v3 = gelu_exact(v3);
            }
            if (SPLITOUT == 0) {
                float* c0 = C + ((long long)r0 * ldc + col) + z * sC;
                float* c1 = C + ((long long)(r0 + 8) * ldc + col) + z * sC;
                c0[0] = v0; c0[1] = v1;
                c1[0] = v2; c1[1] = v3;
            } else {
                long long o0 = (long long)r0 * ldc + col + z * sC;
                long long o1 = (long long)(r0 + 8) * ldc + col + z * sC;
                __nv_bfloat16 h0, l0, h1, l1, h2, l2, h3, l3;
                split2(v0, h0, l0); split2(v1, h1, l1);
                split2(v2, h2, l2); split2(v3, h3, l3);
                *(__nv_bfloat162*)(Ch + o0) = __halves2bfloat162(h0, h1);
                *(__nv_bfloat162*)(Cl + o0) = __halves2bfloat162(l0, l1);
                *(__nv_bfloat162*)(Ch + o1) = __halves2bfloat162(h2, h3);
                *(__nv_bfloat162*)(Cl + o1) = __halves2bfloat162(l2, l3);
            }
        }
    }
}

// ---------------- fp32 -> bf16 hi/lo split ----------------
__global__ void __launch_bounds__(256) split_kernel(
    const float4* __restrict__ x, __nv_bfloat16* __restrict__ h,
    __nv_bfloat16* __restrict__ l, int n4)
{
    int i = blockIdx.x * 256 + threadIdx.x;
    if (i >= n4) return;
    float4 v = x[i];
    __nv_bfloat16 h0, l0, h1, l1, h2, l2, h3, l3;
    split2(v.x, h0, l0); split2(v.y, h1, l1);
    split2(v.z, h2, l2); split2(v.w, h3, l3);
    ((__nv_bfloat162*)h)[2 * i]     = __halves2bfloat162(h0, h1);
    ((__nv_bfloat162*)h)[2 * i + 1] = __halves2bfloat162(h2, h3);
    ((__nv_bfloat162*)l)[2 * i]     = __halves2bfloat162(l0, l1);
    ((__nv_bfloat162*)l)[2 * i + 1] = __halves2bfloat162(l2, l3);
}

// ---------------- transpose + split ----------------
__global__ void __launch_bounds__(256) tsplit_kernel(
    const float* __restrict__ src, __nv_bfloat16* __restrict__ dh,
    __nv_bfloat16* __restrict__ dl, int R, int Cc)
{
    __shared__ float t[32][33];
    const long long zoff = (long long)blockIdx.z * R * Cc;
    src += zoff; dh += zoff; dl += zoff;
    const int r0 = blockIdx.y * 32, c0 = blockIdx.x * 32;
    const int tx = threadIdx.x & 31, ty = threadIdx.x >> 5;
    #pragma unroll
    for (int i = 0; i < 32; i += 8)
        t[ty + i][tx] = src[(long long)(r0 + ty + i) * Cc + c0 + tx];
    __syncthreads();
    #pragma unroll
    for (int i = 0; i < 32; i += 8) {
        float v = t[tx][ty + i];
        long long o = (long long)(c0 + ty + i) * R + r0 + tx;
        __nv_bfloat16 h, l;
        split2(v, h, l);
        dh[o] = h; dl[o] = l;
    }
}

// ---------------- mma flash attention (bf16 split, Br=128, Bc=64, hd=64) ----------------
#define FA_TP   72
#define FA_SMEM 73728

__device__ __forceinline__ void split4_store(
    float4 v, __nv_bfloat16* H, __nv_bfloat16* L, int off)
{
    __nv_bfloat16 h0, l0, h1, l1, h2, l2, h3, l3;
    split2(v.x, h0, l0); split2(v.y, h1, l1);
    split2(v.z, h2, l2); split2(v.w, h3, l3);
    *(__nv_bfloat162*)(H + off)     = __halves2bfloat162(h0, h1);
    *(__nv_bfloat162*)(H + off + 2) = __halves2bfloat162(h2, h3);
    *(__nv_bfloat162*)(L + off)     = __halves2bfloat162(l0, l1);
    *(__nv_bfloat162*)(L + off + 2) = __halves2bfloat162(l2, l3);
}

__global__ void __launch_bounds__(256, 2) fa_kernel(
    const float* __restrict__ Qb, int ldq,
    const float* __restrict__ Kb, int ldk,
    const float* __restrict__ Vb, int ldv,
    float* __restrict__ Ob, int ldo, int Skv)
{
    extern __shared__ __nv_bfloat16 sb[];
    __nv_bfloat16* Qh = sb;
    __nv_bfloat16* Ql = sb + 9216;
    __nv_bfloat16* Kh = sb + 18432;
    __nv_bfloat16* Kl = sb + 23040;
    __nv_bfloat16* Vh = sb + 27648;
    __nv_bfloat16* Vl = sb + 32256;

    const int b = blockIdx.z, h = blockIdx.y, qt = blockIdx.x;
    const int tid = threadIdx.x, wid = tid >> 5, lane = tid & 31;
    const float* Q  = Qb + h * HD;
    const float* Kp = Kb + h * HD;
    const float* Vp = Vb + h * HD;

    for (int u = tid; u < 128 * 16; u += 256) {
        int r = u >> 4, c4 = (u & 15) << 2;
        long long tok = (long long)(qt * 128 + r) * BB + b;
        float4 v = *(const float4*)(Q + tok * ldq + c4);
        v.x *= 0.125f; v.y *= 0.125f; v.z *= 0.125f; v.w *= 0.125f;
        split4_store(v, Qh, Ql, r * FA_TP + c4);
    }

    float o[8][4];
    #pragma unroll
    for (int j = 0; j < 8; j++)
        #pragma unroll
        for (int r = 0; r < 4; r++) o[j][r] = 0.f;
    float m0 = -1e30f, m1 = -1e30f, l0 = 0.f, l1 = 0.f;

    const uint32_t qbase = smem_u32(Qh);
    const uint32_t lbase = smem_u32(Ql);
    const uint32_t kbase = smem_u32(Kh);
    const uint32_t klbase = smem_u32(Kl);
    const uint32_t vbase = smem_u32(Vh);
    const uint32_t vlbase = smem_u32(Vl);
    const uint32_t lmA =
        (uint32_t)(((lane & 7) + ((lane >> 3) & 1) * 8) * (FA_TP * 2) + (lane >> 4) * 16);
    const uint32_t lmT =
        (uint32_t)(((lane & 7) + ((lane >> 4) & 1) * 8) * (FA_TP * 2) + ((lane >> 3) & 1) * 16);
    const uint32_t qwoff = (uint32_t)(wid * 16) * (FA_TP * 2);

    const int nkt = Skv >> 6;
    for (int kt = 0; kt < nkt; kt++) {
        __syncthreads();
        for (int u = tid; u < 64 * 16; u += 256) {
            int r = u >> 4, c4 = (u & 15) << 2;
            long long tok = (long long)(kt * 64 + r) * BB + b;
            float4 kv = *(const float4*)(Kp + tok * ldk + c4);
            split4_store(kv, Kh, Kl, r * FA_TP + c4);
            float4 vv = *(const float4*)(Vp + tok * ldv + c4);
            split4_store(vv, Vh, Vl, r * FA_TP + c4);
        }
        __syncthreads();

        // ---- QK^T: 3-term split ----
        float s[8][4];
        #pragma unroll
        for (int j = 0; j < 8; j++)
            #pragma unroll
            for (int r = 0; r < 4; r++) s[j][r] = 0.f;

        #pragma unroll
        for (int c = 0; c < 4; c++) {
            const uint32_t kb32 = c * 32;
            uint32_t aH[4], aL[4];
            LDSM_X4(aH[0], aH[1], aH[2], aH[3], qbase + qwoff + lmA + kb32);
            LDSM_X4(aL[0], aL[1], aL[2], aL[3], lbase + qwoff + lmA + kb32);
            #pragma unroll
            for (int jp = 0; jp < 4; jp++) {
                uint32_t r0, r1, r2, r3;
                LDSM_X4(r0, r1, r2, r3,
                        kbase + jp * 16 * (FA_TP * 2) + lmA + kb32);
                uint32_t bj[2]  = {r0, r2};
                uint32_t bj1[2] = {r1, r3};
                mma16816(s[2 * jp],     aH, bj);
                mma16816(s[2 * jp + 1], aH, bj1);
                mma16816(s[2 * jp],     aL, bj);
                mma16816(s[2 * jp + 1], aL, bj1);
                LDSM_X4(r0, r1, r2, r3,
                        klbase + jp * 16 * (FA_TP * 2) + lmA + kb32);
                uint32_t cj[2]  = {r0, r2};
                uint32_t cj1[2] = {r1, r3};
                mma16816(s[2 * jp],     aH, cj);
                mma16816(s[2 * jp + 1], aH, cj1);
            }
        }

        // ---- online softmax ----
        float mx0 = -1e30f, mx1 = -1e30f;
        #pragma unroll
        for (int j = 0; j < 8; j++) {
            mx0 = fmaxf(mx0, fmaxf(s[j][0], s[j][1]));
            mx1 = fmaxf(mx1, fmaxf(s[j][2], s[j][3]));
        }
        mx0 = fmaxf(mx0, __shfl_xor_sync(0xffffffffu, mx0, 1));
        mx0 = fmaxf(mx0, __shfl_xor_sync(0xffffffffu, mx0, 2));
        mx1 = fmaxf(mx1, __shfl_xor_sync(0xffffffffu, mx1, 1));
        mx1 = fmaxf(mx1, __shfl_xor_sync(0xffffffffu, mx1, 2));
        float mn0 = fmaxf(m0, mx0), mn1 = fmaxf(m1, mx1);
        float sc0 = __expf(m0 - mn0), sc1 = __expf(m1 - mn1);
        m0 = mn0; m1 = mn1;
        float rs0 = 0.f, rs1 = 0.f;
        #pragma unroll
        for (int j = 0; j < 8; j++) {
            s[j][0] = __expf(s[j][0] - m0);
            s[j][1] = __expf(s[j][1] - m0);
            s[j][2] = __expf(s[j][2] - m1);
            s[j][3] = __expf(s[j][3] - m1);
            rs0 += s[j][0] + s[j][1];
            rs1 += s[j][2] + s[j][3];
        }
        rs0 += __shfl_xor_sync(0xffffffffu, rs0, 1);
        rs0 += __shfl_xor_sync(0xffffffffu, rs0, 2);
        rs1 += __shfl_xor_sync(0xffffffffu, rs1, 1);
        rs1 += __shfl_xor_sync(0xffffffffu, rs1, 2);
        l0 = l0 * sc0 + rs0;
        l1 = l1 * sc1 + rs1;
        #pragma unroll
        for (int j = 0; j < 8; j++) {
            o[j][0] *= sc0; o[j][1] *= sc0;
            o[j][2] *= sc1; o[j][3] *= sc1;
        }

        // ---- P·V: 3-term split (Ph·Vh + Pl·Vh + Ph·Vl) ----
        #pragma unroll
        for (int c = 0; c < 4; c++) {
            uint32_t ph[4], pl[4];
            packsplit(s[2 * c][0],     s[2 * c][1],     ph[0], pl[0]);
            packsplit(s[2 * c][2],     s[2 * c][3],     ph[1], pl[1]);
            packsplit(s[2 * c + 1][0], s[2 * c + 1][1], ph[2], pl[2]);
            packsplit(s[2 * c + 1][2], s[2 * c + 1][3], ph[3], pl[3]);
            const uint32_t rowoff = (uint32_t)(c * 16) * (FA_TP * 2);
            #pragma unroll
            for (int jp = 0; jp < 4; jp++) {
                uint32_t r0, r1, r2, r3;
                LDSM_X4_T(r0, r1, r2, r3,
                          vbase + rowoff + lmT + jp * 32);
                uint32_t bj[2]  = {r0, r2};
                uint32_t bj1[2] = {r1, r3};
                mma16816(o[2 * jp],     ph, bj);
                mma16816(o[2 * jp + 1], ph, bj1);
                mma16816(o[2 * jp],     pl, bj);
                mma16816(o[2 * jp + 1], pl, bj1);
                LDSM_X4_T(r0, r1, r2, r3,
                          vlbase + rowoff + lmT + jp * 32);
                uint32_t cj[2]  = {r0, r2};
                uint32_t cj1[2] = {r1, r3};
                mma16816(o[2 * jp],     ph, cj);
                mma16816(o[2 * jp + 1], ph, cj1);
            }
        }
    }

    // ---- normalize + write ----
    const float il0 = 1.0f / l0, il1 = 1.0f / l1;
    const int r0 = qt * 128 + wid * 16 + (lane >> 2);
    const long long tok0 = (long long)r0 * BB + b;
    const long long tok1 = (long long)(r0 + 8) * BB + b;
    #pragma unroll
    for (int j = 0; j < 8; j++) {
        const int col = h * HD + j * 8 + (lane & 3) * 2;
        float2 w0 = make_float2(o[j][0] * il0, o[j][1] * il0);
        float2 w1 = make_float2(o[j][2] * il1, o[j][3] * il1);
        *(float2*)(Ob + tok0 * ldo + col) = w0;
        *(float2*)(Ob + tok1 * ldo + col) = w1;
    }
}

// ---------------- gating ----------------
__global__ void __launch_bounds__(128) gate_kernel(
    const float* __restrict__ x, const float* __restrict__ wg,
    float* __restrict__ probs, float* __restrict__ gatev, int* __restrict__ gidx)
{
    const int t = blockIdx.x, tid = threadIdx.x;
    __shared__ float red[128][8];
    float acc[8];
    #pragma unroll
    for (int e = 0; e < 8; e++) acc[e] = 0.f;
    for (int d = tid; d < DIM; d += 128) {
        float xv = x[(long long)t * DIM + d];
        const float4* w = (const float4*)(wg + d * 8);
        float4 w0 = w[0], w1 = w[1];
        acc[0] += xv * w0.x; acc[1] += xv * w0.y; acc[2] += xv * w0.z; acc[3] += xv * w0.w;
        acc[4] += xv * w1.x; acc[5] += xv * w1.y; acc[6] += xv * w1.z; acc[7] += xv * w1.w;
    }
    #pragma unroll
    for (int e = 0; e < 8; e++) red[tid][e] = acc[e];
    __syncthreads();
    for (int s = 64; s > 0; s >>= 1) {
        if (tid < s)
            #pragma unroll
            for (int e = 0; e < 8; e++) red[tid][e] += red[tid + s][e];
        __syncthreads();
    }
    if (tid == 0) {
        float l[8], mx = -1e30f;
        #pragma unroll
        for (int e = 0; e < 8; e++) { l[e] = red[0][e]; mx = fmaxf(mx, l[e]); }
        float sum = 0.f;
        #pragma unroll
        for (int e = 0; e < 8; e++) { l[e] = __expf(l[e] - mx); sum += l[e]; }
        float inv = 1.0f / sum;
        #pragma unroll
        for (int e = 0; e < 8; e++) { l[e] *= inv; probs[t * 8 + e] = l[e]; }
        int i1 = 0; float v1 = l[0];
        #pragma unroll
        for (int e = 1; e < 8; e++) if (l[e] > v1) { v1 = l[e]; i1 = e; }
        int i2 = -1; float v2 = -1.f;
        #pragma unroll
        for (int e = 0; e < 8; e++) if (e != i1 && l[e] > v2) { v2 = l[e]; i2 = e; }
        gatev[2 * t] = v1; gatev[2 * t + 1] = v2;
        gidx[2 * t] = i1;  gidx[2 * t + 1] = i2;
    }
}

// ---------------- routing ----------------
__global__ void __launch_bounds__(256) route_kernel(
    const int* __restrict__ gidx, const float* __restrict__ probs,
    int* __restrict__ sl, int* __restrict__ rows, float* __restrict__ auxp)
{
    __shared__ signed char s1[NTOK];
    __shared__ signed char s2[NTOK];
    __shared__ int cnt1[8];
    __shared__ float pr[256 * 8];
    const int tid = threadIdx.x;

    for (int i = tid; i < NTOK; i += 256) {
        int2 v = ((const int2*)gidx)[i];
        s1[i] = (signed char)v.x; s2[i] = (signed char)v.y;
    }
    float lp[8];
    #pragma unroll
    for (int e = 0; e < 8; e++) lp[e] = 0.f;
    for (int i = tid; i < NTOK; i += 256) {
        const float4* p = (const float4*)(probs + i * 8);
        float4 p0 = p[0], p1 = p[1];
        lp[0] += p0.x; lp[1] += p0.y; lp[2] += p0.z; lp[3] += p0.w;
        lp[4] += p1.x; lp[5] += p1.y; lp[6] += p1.z; lp[7] += p1.w;
    }
    #pragma unroll
    for (int e = 0; e < 8; e++) pr[tid * 8 + e] = lp[e];
    __syncthreads();
    for (int s = 128; s > 0; s >>= 1) {
        if (tid < s)
            #pragma unroll
            for (int e = 0; e < 8; e++) pr[tid * 8 + e] += pr[(tid + s) * 8 + e];
        __syncthreads();
    }

    if (tid < 8) {
        int e = tid, c = 0;
        #pragma unroll 1
        for (int i = 0; i < NTOK; i++)
            if (s1[i] == e) { sl[2 * i] = (c < CAP) ? c : -1; c++; }
        cnt1[e] = c;
    }
    __syncthreads();
    if (tid < 8) {
        int e = tid, base = cnt1[e], c = 0;
        #pragma unroll 1
        for (int i = 0; i < NTOK; i++)
            if (s2[i] == e) { int loc = base + c; sl[2 * i + 1] = (loc < CAP) ? loc : -1; c++; }
        int ru = cnt1[e] + c; if (ru > CAP) ru = CAP;
        rows[e] = ru;
    }
    __syncthreads();
    if (tid == 0) {
        float a = 0.f;
        for (int e = 0; e < 8; e++)
            a += ((float)cnt1[e] / (float)NTOK) * (pr[e] / (float)NTOK);
        *auxp = 0.01f * 8.0f * a;
    }
}

// ---------------- scatter ----------------
__global__ void __launch_bounds__(256) scatter_kernel(
    const float* __restrict__ x, const int* __restrict__ gidx,
    const int* __restrict__ sl, __nv_bfloat16* __restrict__ bh,
    __nv_bfloat16* __restrict__ bl)
{
    const int t = blockIdx.x, ch = blockIdx.y;
    const int s = sl[2 * t + ch];
    if (s < 0) return;
    const int e = gidx[2 * t + ch];
    float4 v = ((const float4*)(x + (long long)t * DIM))[threadIdx.x];
    size_t base = ((size_t)e * CAP + s) * DIM + threadIdx.x * 4;
    __nv_bfloat16 h0, l0, h1, l1, h2, l2, h3, l3;
    split2(v.x, h0, l0); split2(v.y, h1, l1);
    split2(v.z, h2, l2); split2(v.w, h3, l3);
    *(__nv_bfloat162*)(bh + base)     = __halves2bfloat162(h0, h1);
    *(__nv_bfloat162*)(bh + base + 2) = __halves2bfloat162(h2, h3);
    *(__nv_bfloat162*)(bl + base)     = __halves2bfloat162(l0, l1);
    *(__nv_bfloat162*)(bl + base + 2) = __halves2bfloat162(l2, l3);
}

// ---------------- gather ----------------
__global__ void __launch_bounds__(256) gather_kernel(
    const float* __restrict__ y, const int* __restrict__ gidx,
    const int* __restrict__ sl, const float* __restrict__ gatev,
    float* __restrict__ out)
{
    const int t = blockIdx.x;
    const float gv1 = gatev[2 * t], gv2 = gatev[2 * t + 1];
    const int s1 = sl[2 * t], s2 = sl[2 * t + 1];
    const int e1 = gidx[2 * t], e2 = gidx[2 * t + 1];
    float4 r = make_float4(0.f, 0.f, 0.f, 0.f);
    if (s1 >= 0) {
        float4 a = ((const float4*)(y + ((size_t)e1 * CAP + s1) * DIM))[threadIdx.x];
        r.x += gv1 * a.x; r.y += gv1 * a.y; r.z += gv1 * a.z; r.w += gv1 * a.w;
    }
    if (s2 >= 0) {
        float4 a = ((const float4*)(y + ((size_t)e2 * CAP + s2) * DIM))[threadIdx.x];
        r.x += gv2 * a.x; r.y += gv2 * a.y; r.z += gv2 * a.z; r.w += gv2 * a.w;
    }
    ((float4*)(out + (long long)t * DIM))[threadIdx.x] = r;
}

// ---------------- triple layernorm + aux ----------------
__device__ __forceinline__ float block_sum(float v, float* red) {
    int tid = threadIdx.x;
    red[tid] = v; __syncthreads();
    for (int s = 128; s > 0; s >>= 1) {
        if (tid < s) red[tid] += red[tid + s];
        __syncthreads();
    }
    float r = red[0]; __syncthreads();
    return r;
}

__global__ void __launch_bounds__(256) ln3_kernel(
    const float* __restrict__ x,
    const float* __restrict__ g1, const float* __restrict__ b1,
    const float* __restrict__ g2, const float* __restrict__ b2,
    const float* __restrict__ g3, const float* __restrict__ b3,
    float* __restrict__ out, const float* __restrict__ auxp, long long out_size)
{
    __shared__ float red[256];
    const int t = blockIdx.x, tid = threadIdx.x;
    float4 v = ((const float4*)(x + (long long)t * DIM))[tid];

    const float* gs[3] = {g1, g2, g3};
    const float* bs[3] = {b1, b2, b3};
    #pragma unroll
    for (int r3 = 0; r3 < 3; r3++) {
        float s = v.x + v.y + v.z + v.w;
        float mean = block_sum(s, red) * (1.0f / DIM);
        float dx = v.x - mean, dy = v.y - mean, dz = v.z - mean, dw = v.w - mean;
        float s2 = dx * dx + dy * dy + dz * dz + dw * dw;
        float var = block_sum(s2, red) * (1.0f / DIM);
        float rstd = rsqrtf(var + LN_EPS);
        float4 gg = ((const float4*)gs[r3])[tid];
        float4 bb = ((const float4*)bs[r3])[tid];
        v.x = dx * rstd * gg.x + bb.x;
        v.y = dy * rstd * gg.y + bb.y;
        v.z = dz * rstd * gg.z + bb.z;
        v.w = dw * rstd * gg.w + bb.w;
    }
    ((float4*)(out + (long long)t * DIM))[tid] = v;
    if (t == 0 && tid == 0 && out_size > (long long)NTOK * DIM)
        out[(long long)NTOK * DIM] = *auxp;
}

// ---------------- launch ----------------
extern "C" void kernel_launch(void* const* d_in, const int* in_sizes, int n_in,
                              void* d_out, int out_size) {
    const float* tgt      = (const float*)d_in[0];
    const float* mem      = (const float*)d_in[1];
    const float* w_qkv_sa = (const float*)d_in[2];
    const float* b_qkv_sa = (const float*)d_in[3];
    const float* w_o_sa   = (const float*)d_in[4];
    const float* b_o_sa   = (const float*)d_in[5];
    const float* w_qkv_ca = (const float*)d_in[6];
    const float* b_qkv_ca = (const float*)d_in[7];
    const float* w_o_ca   = (const float*)d_in[8];
    const float* b_o_ca   = (const float*)d_in[9];
    const float* ln1_g = (const float*)d_in[10];
    const float* ln1_b = (const float*)d_in[11];
    const float* ln2_g = (const float*)d_in[12];
    const float* ln2_b = (const float*)d_in[13];
    const float* ln3_g = (const float*)d_in[14];
    const float* ln3_b = (const float*)d_in[15];
    const float* w_gate = (const float*)d_in[16];
    const float* w1  = (const float*)d_in[17];
    const float* b1e = (const float*)d_in[18];
    const float* w2  = (const float*)d_in[19];
    const float* b2e = (const float*)d_in[20];
    float* out = (float*)d_out;

    float *qkv, *attn, *qca, *kvca, *x2, *probs, *gatev, *x3, *ybuf, *auxp;
    int *gidx, *sl, *rows;
    __nv_bfloat16 *tgt_h, *tgt_l, *mem_h, *mem_l, *att_h, *att_l, *x1_h, *x1_l;
    __nv_bfloat16 *buf_h, *buf_l, *hb_h, *hb_l;
    __nv_bfloat16 *wqsa_h, *wqsa_l, *wosa_h, *wosa_l, *wqca_h, *wqca_l, *woca_h, *woca_l;
    __nv_bfloat16 *w1t_h, *w1t_l, *w2t_h, *w2t_l;

    cudaGetSymbolAddress((void**)&qkv,  g_qkv);
    cudaGetSymbolAddress((void**)&attn, g_attn);
    cudaGetSymbolAddress((void**)&qca,  g_qca);
    cudaGetSymbolAddress((void**)&kvca, g_kvca);
    cudaGetSymbolAddress((void**)&x2,   g_x2);
    cudaGetSymbolAddress((void**)&probs,g_probs);
    cudaGetSymbolAddress((void**)&gatev,g_gatev);
    cudaGetSymbolAddress((void**)&gidx, g_gidx);
    cudaGetSymbolAddress((void**)&sl,   g_sl);
    cudaGetSymbolAddress((void**)&rows, g_rows);
    cudaGetSymbolAddress((void**)&auxp, g_aux);
    cudaGetSymbolAddress((void**)&ybuf, g_y);
    cudaGetSymbolAddress((void**)&x3,   g_x3);
    cudaGetSymbolAddress((void**)&tgt_h, g_tgt_h); cudaGetSymbolAddress((void**)&tgt_l, g_tgt_l);
    cudaGetSymbolAddress((void**)&mem_h, g_mem_h); cudaGetSymbolAddress((void**)&mem_l, g_mem_l);
    cudaGetSymbolAddress((void**)&att_h, g_att_h); cudaGetSymbolAddress((void**)&att_l, g_att_l);
    cudaGetSymbolAddress((void**)&x1_h,  g_x1_h);  cudaGetSymbolAddress((void**)&x1_l,  g_x1_l);
    cudaGetSymbolAddress((void**)&buf_h, g_buf_h); cudaGetSymbolAddress((void**)&buf_l, g_buf_l);
    cudaGetSymbolAddress((void**)&hb_h,  g_hb_h);  cudaGetSymbolAddress((void**)&hb_l,  g_hb_l);
    cudaGetSymbolAddress((void**)&wqsa_h, g_wqsa_h); cudaGetSymbolAddress((void**)&wqsa_l, g_wqsa_l);
    cudaGetSymbolAddress((void**)&wosa_h, g_wosa_h); cudaGetSymbolAddress((void**)&wosa_l, g_wosa_l);
    cudaGetSymbolAddress((void**)&wqca_h, g_wqca_h); cudaGetSymbolAddress((void**)&wqca_l, g_wqca_l);
    cudaGetSymbolAddress((void**)&woca_h, g_woca_h); cudaGetSymbolAddress((void**)&woca_l, g_woca_l);
    cudaGetSymbolAddress((void**)&w1t_h, g_w1t_h); cudaGetSymbolAddress((void**)&w1t_l, g_w1t_l);
    cudaGetSymbolAddress((void**)&w2t_h, g_w2t_h); cudaGetSymbolAddress((void**)&w2t_l, g_w2t_l);

    cudaFuncSetAttribute(fa_kernel, cudaFuncAttributeMaxDynamicSharedMemorySize, FA_SMEM);
    cudaFuncSetAttribute(mmagemm_kernel<0,0>, cudaFuncAttributeMaxDynamicSharedMemorySize, GEMM_SMEM);
    cudaFuncSetAttribute(mmagemm_kernel<0,1>, cudaFuncAttributeMaxDynamicSharedMemorySize, GEMM_SMEM);
    cudaFuncSetAttribute(mmagemm_kernel<1,1>, cudaFuncAttributeMaxDynamicSharedMemorySize, GEMM_SMEM);

    // ---- weight & input conversions ----
    split_kernel<<<(3*DIM*DIM/4 + 255)/256, 256>>>((const float4*)w_qkv_sa, wqsa_h, wqsa_l, 3*DIM*DIM/4);
    split_kernel<<<(DIM*DIM/4 + 255)/256, 256>>>((const float4*)w_o_sa, wosa_h, wosa_l, DIM*DIM/4);
    split_kernel<<<(3*DIM*DIM/4 + 255)/256, 256>>>((const float4*)w_qkv_ca, wqca_h, wqca_l, 3*DIM*DIM/4);
    split_kernel<<<(DIM*DIM/4 + 255)/256, 256>>>((const float4*)w_o_ca, woca_h, woca_l, DIM*DIM/4);
    tsplit_kernel<<<dim3(DFF/32, DIM/32, NE), 256>>>(w1, w1t_h, w1t_l, DIM, DFF);
    tsplit_kernel<<<dim3(DIM/32, DFF/32, NE), 256>>>(w2, w2t_h, w2t_l, DFF, DIM);
    split_kernel<<<(NTOK*DIM/4 + 255)/256, 256>>>((const float4*)tgt, tgt_h, tgt_l, NTOK*DIM/4);
    split_kernel<<<(NTOK*DIM/4 + 255)/256, 256>>>((const float4*)mem, mem_h, mem_l, NTOK*DIM/4);

    // 1) SA qkv projection (NT)
    mmagemm_kernel<0,0><<<dim3(3072/128, NTOK/128, 1), 256, GEMM_SMEM>>>(
        tgt_h, tgt_l, wqsa_h, wqsa_l, b_qkv_sa, qkv, nullptr, nullptr,
        DIM, 3*DIM, 0, 0, 0, 0, nullptr);

    // 2) self-attention (mma)
    fa_kernel<<<dim3(SQ/128, NH, BB), 256, FA_SMEM>>>(
        qkv, 3*DIM, qkv + DIM, 3*DIM, qkv + 2*DIM, 3*DIM, attn, DIM, SQ);
    split_kernel<<<(NTOK*DIM/4 + 255)/256, 256>>>((const float4*)attn, att_h, att_l, NTOK*DIM/4);

    // 3) SA output projection -> x1 split
    mmagemm_kernel<0,1><<<dim3(DIM/128, NTOK/128, 1), 256, GEMM_SMEM>>>(
        att_h, att_l, wosa_h, wosa_l, b_o_sa, nullptr, x1_h, x1_l,
        DIM, DIM, 0, 0, 0, 0, nullptr);

    // 4) CA q projection -> fp32 qca
    mmagemm_kernel<0,0><<<dim3(DIM/128, NTOK/128, 1), 256, GEMM_SMEM>>>(
        x1_h, x1_l, wqca_h, wqca_l, b_qkv_ca, qca, nullptr, nullptr,
        DIM, DIM, 0, 0, 0, 0, nullptr);

    // 5) CA k,v projection from memory -> fp32 kvca
    mmagemm_kernel<0,0><<<dim3(2*DIM/128, NTOK/128, 1), 256, GEMM_SMEM>>>(
        mem_h, mem_l, wqca_h + (size_t)DIM*DIM, wqca_l + (size_t)DIM*DIM,
        b_qkv_ca + DIM, kvca, nullptr, nullptr,
        DIM, 2*DIM, 0, 0, 0, 0, nullptr);

    // 6) cross-attention (mma)
    fa_kernel<<<dim3(SQ/128, NH, BB), 256, FA_SMEM>>>(
        qca, DIM, kvca, 2*DIM, kvca + DIM, 2*DIM, attn, DIM, SQ);
    split_kernel<<<(NTOK*DIM/4 + 255)/256, 256>>>((const float4*)attn, att_h, att_l, NTOK*DIM/4);

    // 7) CA output projection -> fp32 x2
    mmagemm_kernel<0,0><<<dim3(DIM/128, NTOK/128, 1), 256, GEMM_SMEM>>>(
        att_h, att_l, woca_h, woca_l, b_o_ca, x2, nullptr, nullptr,
        DIM, DIM, 0, 0, 0, 0, nullptr);

    // 8-9) gating + routing
    gate_kernel<<<NTOK, 128>>>(x2, w_gate, probs, gatev, gidx);
    route_kernel<<<1, 256>>>(gidx, probs, sl, rows, auxp);

    // 10) scatter -> bf16 hi/lo expert buffer
    scatter_kernel<<<dim3(NTOK, 2), 256>>>(x2, gidx, sl, buf_h, buf_l);

    // 11) expert FFN layer 1 (+GELU, split-out), row-skip
    mmagemm_kernel<1,1><<<dim3(DFF/128, CAP/128, NE), 256, GEMM_SMEM>>>(
        buf_h, buf_l, w1t_h, w1t_l, b1e, nullptr, hb_h, hb_l,
        DIM, DFF, (long long)CAP*DIM, (long long)DFF*DIM, DFF, (long long)CAP*DFF, rows);

    // 12) expert FFN layer 2 -> fp32 ybuf, row-skip
    mmagemm_kernel<0,0><<<dim3(DIM/128, CAP/128, NE), 256, GEMM_SMEM>>>(
        hb_h, hb_l, w2t_h, w2t_l, b2e, ybuf, nullptr, nullptr,
        DFF, DIM, (long long)CAP*DFF, (long long)DIM*DFF, DIM, (long long)CAP*DIM, rows);

    // 13) gather
    gather_kernel<<<NTOK, 256>>>(ybuf, gidx, sl, gatev, x3);

    // 14) triple layernorm + aux
    ln3_kernel<<<NTOK, 256>>>(x3, ln1_g, ln1_b, ln2_g, ln2_b, ln3_g, ln3_b,
                              out, auxp, (long long)out_size);
}

// round 10
// speedup vs baseline: 2.3707x; 1.0228x over previous
#include <cuda_runtime.h>
#include <cuda_bf16.h>
#include <math.h>
#include <stdint.h>

// ---------------- problem constants ----------------
#define SQ   2048
#define BB   2
#define DIM  1024
#define NH   16
#define HD   64
#define NTOK 4096
#define NE   8
#define DFF  4096
#define CAP  2048
#define LN_EPS 1e-5f

// ---------------- scratch (device globals) ----------------
__device__ __nv_bfloat16 g_tgt_h[NTOK * DIM], g_tgt_l[NTOK * DIM];
__device__ __nv_bfloat16 g_mem_h[NTOK * DIM], g_mem_l[NTOK * DIM];
__device__ __nv_bfloat16 g_att_h[NTOK * DIM], g_att_l[NTOK * DIM];
__device__ __nv_bfloat16 g_x1_h [NTOK * DIM], g_x1_l [NTOK * DIM];
__device__ __nv_bfloat16 g_buf_h[NE * CAP * DIM], g_buf_l[NE * CAP * DIM];
__device__ __nv_bfloat16 g_hb_h[(size_t)NE * CAP * DFF], g_hb_l[(size_t)NE * CAP * DFF];
__device__ __nv_bfloat16 g_wqsa_h[3 * DIM * DIM], g_wqsa_l[3 * DIM * DIM];
__device__ __nv_bfloat16 g_wosa_h[DIM * DIM],     g_wosa_l[DIM * DIM];
__device__ __nv_bfloat16 g_wqca_h[3 * DIM * DIM], g_wqca_l[3 * DIM * DIM];
__device__ __nv_bfloat16 g_woca_h[DIM * DIM],     g_woca_l[DIM * DIM];
__device__ __nv_bfloat16 g_w1s_h[(size_t)NE * DIM * DFF], g_w1s_l[(size_t)NE * DIM * DFF];
__device__ __nv_bfloat16 g_w2s_h[(size_t)NE * DIM * DFF], g_w2s_l[(size_t)NE * DIM * DFF];
__device__ float g_qkv [NTOK * 3 * DIM];
__device__ float g_qca [NTOK * DIM];
__device__ float g_kvca[NTOK * 2 * DIM];
__device__ float g_x2  [NTOK * DIM];
__device__ float g_probs[NTOK * NE];
__device__ float g_gatev[NTOK * 2];
__device__ int   g_gidx[NTOK * 2];
__device__ int   g_sl  [NTOK * 2];
__device__ int   g_rows[NE];
__device__ float g_aux;
__device__ float g_y [NE * CAP * DIM];
__device__ float g_x3[NTOK * DIM];

__device__ __forceinline__ float gelu_exact(float x) {
    return 0.5f * x * (1.0f + erff(x * 0.70710678118654752440f));
}
__device__ __forceinline__ void split2(float v, __nv_bfloat16& h, __nv_bfloat16& l) {
    h = __float2bfloat16(v);
    l = __float2bfloat16(v - __bfloat162float(h));
}
__device__ __forceinline__ uint32_t smem_u32(const void* p) {
    uint32_t a;
    asm("{ .reg .u64 t; cvta.to.shared.u64 t, %1; cvt.u32.u64 %0, t; }" : "=r"(a) : "l"(p));
    return a;
}
__device__ __forceinline__ uint32_t packh2(__nv_bfloat16 a, __nv_bfloat16 b) {
    __nv_bfloat162 t = __halves2bfloat162(a, b);
    return *(uint32_t*)&t;
}
// pack hi parts and lo parts of (a,b) into two b16x2 regs
__device__ __forceinline__ void packsplit(float a, float b, uint32_t& hi, uint32_t& lo) {
    __nv_bfloat16 ha, la, hb, lb;
    split2(a, ha, la); split2(b, hb, lb);
    hi = packh2(ha, hb); lo = packh2(la, lb);
}
#define CP_ASYNC16(s, g) \
    asm volatile("cp.async.cg.shared.global [%0], [%1], 16;" :: "r"(s), "l"(g))
#define CP_COMMIT() asm volatile("cp.async.commit_group;" ::: "memory")

__device__ __forceinline__ void mma16816(float* d, const uint32_t* a, const uint32_t* b) {
    asm volatile(
        "mma.sync.aligned.m16n8k16.row.col.f32.bf16.bf16.f32 "
        "{%0,%1,%2,%3}, {%4,%5,%6,%7}, {%8,%9}, {%0,%1,%2,%3};"
        : "+f"(d[0]), "+f"(d[1]), "+f"(d[2]), "+f"(d[3])
        : "r"(a[0]), "r"(a[1]), "r"(a[2]), "r"(a[3]), "r"(b[0]), "r"(b[1]));
}
#define LDSM_X4(r0, r1, r2, r3, addr) \
    asm volatile("ldmatrix.sync.aligned.m8n8.x4.shared.b16 {%0,%1,%2,%3}, [%4];" \
        : "=r"(r0), "=r"(r1), "=r"(r2), "=r"(r3) : "r"(addr))
#define LDSM_X4_T(r0, r1, r2, r3, addr) \
    asm volatile("ldmatrix.sync.aligned.m8n8.x4.trans.shared.b16 {%0,%1,%2,%3}, [%4];" \
        : "=r"(r0), "=r"(r1), "=r"(r2), "=r"(r3) : "r"(addr))

// ---------------- bf16 mma GEMM, 3-term hi/lo split ----------------
// BNN=0: C[r,c] = sum_k A[r,k]*B[c,k]   (B row-major [N][K], row stride ldb)
// BNN=1: C[r,c] = sum_k A[r,k]*B[k,c]   (B row-major [K][N], row stride ldb)
// A K-major (row stride = K). 128x128 block, 8 warps (2x4), K-chunk 32, double buffer.
#define TPAD   40                    // A/NT-B smem row stride in bf16 (80 bytes)
#define TPADB  136                   // NN-B smem row stride in bf16 (272 bytes)
#define TILE_B (128 * TPAD * 2)      // 10240 bytes per tile slot
#define STAGE_B (4 * TILE_B)
#define GEMM_SMEM (2 * STAGE_B)      // 81920 bytes

template<int BNN, int DOGELU, int SPLITOUT>
__global__ void __launch_bounds__(256, 2) mmagemm_kernel(
    const __nv_bfloat16* __restrict__ Ah, const __nv_bfloat16* __restrict__ Al,
    const __nv_bfloat16* __restrict__ Bh, const __nv_bfloat16* __restrict__ Bl,
    const float* __restrict__ bias, float* __restrict__ C,
    __nv_bfloat16* __restrict__ Ch, __nv_bfloat16* __restrict__ Cl,
    int K, int ldb, int ldc,
    long long sA, long long sB, long long sBias, long long sC,
    const int* __restrict__ rows_used)
{
    extern __shared__ char smem[];
    const int z = blockIdx.z;
    if (rows_used && (int)(blockIdx.y * 128) >= rows_used[z]) return;

    const int tid = threadIdx.x, wid = tid >> 5, lane = tid & 31;
    const int wm = wid & 1, wn = wid >> 1;
    const long long rowBase = (long long)blockIdx.y * 128;
    const int colBase = blockIdx.x * 128;
    Ah += z * sA; Al += z * sA; Bh += z * sB; Bl += z * sB; bias += z * sBias;

    const __nv_bfloat16* srcA0 = Ah + rowBase * K;
    const __nv_bfloat16* srcA1 = Al + rowBase * K;
    const __nv_bfloat16* srcB0;
    const __nv_bfloat16* srcB1;
    if (BNN) { srcB0 = Bh + colBase; srcB1 = Bl + colBase; }
    else     { srcB0 = Bh + (long long)colBase * ldb; srcB1 = Bl + (long long)colBase * ldb; }

    const uint32_t sbase = smem_u32(smem);
    const int NC = K >> 5;

    auto prefetch = [&](int st, int kc) {
        const int koff = kc * 32;
        const uint32_t stb = sbase + st * STAGE_B;
        // A tiles: 128 rows x 32 bf16 (64B/row = 4 x 16B)
        {
            const __nv_bfloat16* sa[2] = {srcA0 + koff, srcA1 + koff};
            #pragma unroll
            for (int bi = 0; bi < 2; bi++) {
                const uint32_t tb = stb + bi * TILE_B;
                #pragma unroll
                for (int it = 0; it < 2; it++) {
                    int idx = it * 256 + tid;
                    int row = idx >> 2, c = idx & 3;
                    CP_ASYNC16(tb + row * (TPAD * 2) + c * 16,
                               (const void*)(sa[bi] + (long long)row * K + c * 8));
                }
            }
        }
        if (BNN) {
            // B tiles: 32 k-rows x 128 n-cols (256B/row = 16 x 16B)
            const __nv_bfloat16* sb2[2] = {srcB0, srcB1};
            #pragma unroll
            for (int bi = 0; bi < 2; bi++) {
                const uint32_t tb = stb + (2 + bi) * TILE_B;
                #pragma unroll
                for (int it = 0; it < 2; it++) {
                    int idx = it * 256 + tid;
                    int row = idx >> 4, c = idx & 15;
                    CP_ASYNC16(tb + row * (TPADB * 2) + c * 16,
                               (const void*)(sb2[bi] + (long long)(koff + row) * ldb + c * 8));
                }
            }
        } else {
            const __nv_bfloat16* sb2[2] = {srcB0 + koff, srcB1 + koff};
            #pragma unroll
            for (int bi = 0; bi < 2; bi++) {
                const uint32_t tb = stb + (2 + bi) * TILE_B;
                #pragma unroll
                for (int it = 0; it < 2; it++) {
                    int idx = it * 256 + tid;
                    int row = idx >> 2, c = idx & 3;
                    CP_ASYNC16(tb + row * (TPAD * 2) + c * 16,
                               (const void*)(sb2[bi] + (long long)row * ldb + c * 8));
                }
            }
        }
        CP_COMMIT();
    };

    float acc[4][4][4];
    #pragma unroll
    for (int i = 0; i < 4; i++)
        #pragma unroll
        for (int j = 0; j < 4; j++)
            #pragma unroll
            for (int r = 0; r < 4; r++) acc[i][j][r] = 0.f;

    const uint32_t lmoff =
        (uint32_t)(((lane & 7) + ((lane >> 3) & 1) * 8) * (TPAD * 2) + (lane >> 4) * 16);
    const uint32_t lmT =
        (uint32_t)(((lane & 7) + ((lane >> 4) & 1) * 8) * (TPADB * 2) + ((lane >> 3) & 1) * 16);

    prefetch(0, 0);

    for (int ic = 0; ic < NC; ic++) {
        const int p = ic & 1;
        if (ic + 1 < NC) {
            prefetch(p ^ 1, ic + 1);
            asm volatile("cp.async.wait_group 1;" ::: "memory");
        } else {
            asm volatile("cp.async.wait_group 0;" ::: "memory");
        }
        __syncthreads();

        const uint32_t stp = sbase + p * STAGE_B;
        const uint32_t aHb = stp +          wm * 64 * (TPAD * 2) + lmoff;
        const uint32_t aLb = stp + TILE_B + wm * 64 * (TPAD * 2) + lmoff;
        uint32_t bHb, bLb;
        if (BNN) {
            bHb = stp + 2 * TILE_B + wn * 64 + lmT;
            bLb = stp + 3 * TILE_B + wn * 64 + lmT;
        } else {
            bHb = stp + 2 * TILE_B + wn * 32 * (TPAD * 2) + lmoff;
            bLb = stp + 3 * TILE_B + wn * 32 * (TPAD * 2) + lmoff;
        }

        uint32_t afr[4][4];
        uint32_t bfr[4][2];

        #pragma unroll
        for (int ks = 0; ks < 2; ks++) {
            const uint32_t kb = ks * 32;

            // ---- term 1: Ah x Bh ----
            #pragma unroll
            for (int i = 0; i < 4; i++)
                LDSM_X4(afr[i][0], afr[i][1], afr[i][2], afr[i][3],
                        aHb + i * 16 * (TPAD * 2) + kb);
            if (BNN) {
                const uint32_t kbn = ks * 16 * (TPADB * 2);
                #pragma unroll
                for (int jp = 0; jp < 2; jp++) {
                    uint32_t r0, r1, r2, r3;
                    LDSM_X4_T(r0, r1, r2, r3, bHb + kbn + jp * 32);
                    bfr[2 * jp][0] = r0; bfr[2 * jp][1] = r2;
                    bfr[2 * jp + 1][0] = r1; bfr[2 * jp + 1][1] = r3;
                }
            } else {
                #pragma unroll
                for (int pr = 0; pr < 2; pr++)
                    LDSM_X4(bfr[pr * 2][0], bfr[pr * 2 + 1][0],
                            bfr[pr * 2][1], bfr[pr * 2 + 1][1],
                            bHb + pr * 16 * (TPAD * 2) + kb);
            }
            #pragma unroll
            for (int i = 0; i < 4; i++)
                #pragma unroll
                for (int j = 0; j < 4; j++)
                    mma16816(acc[i][j], afr[i], bfr[j]);

            // ---- term 2: Al x Bh ----
            #pragma unroll
            for (int i = 0; i < 4; i++)
                LDSM_X4(afr[i][0], afr[i][1], afr[i][2], afr[i][3],
                        aLb + i * 16 * (TPAD * 2) + kb);
            #pragma unroll
            for (int i = 0; i < 4; i++)
                #pragma unroll
                for (int j = 0; j < 4; j++)
                    mma16816(acc[i][j], afr[i], bfr[j]);

            // ---- term 3: Ah x Bl ----
            #pragma unroll
            for (int i = 0; i < 4; i++)
                LDSM_X4(afr[i][0], afr[i][1], afr[i][2], afr[i][3],
                        aHb + i * 16 * (TPAD * 2) + kb);
            if (BNN) {
                const uint32_t kbn = ks * 16 * (TPADB * 2);
                #pragma unroll
                for (int jp = 0; jp < 2; jp++) {
                    uint32_t r0, r1, r2, r3;
                    LDSM_X4_T(r0, r1, r2, r3, bLb + kbn + jp * 32);
                    bfr[2 * jp][0] = r0; bfr[2 * jp][1] = r2;
                    bfr[2 * jp + 1][0] = r1; bfr[2 * jp + 1][1] = r3;
                }
            } else {
                #pragma unroll
                for (int pr = 0; pr < 2; pr++)
                    LDSM_X4(bfr[pr * 2][0], bfr[pr * 2 + 1][0],
                            bfr[pr * 2][1], bfr[pr * 2 + 1][1],
                            bLb + pr * 16 * (TPAD * 2) + kb);
            }
            #pragma unroll
            for (int i = 0; i < 4; i++)
                #pragma unroll
                for (int j = 0; j < 4; j++)
                    mma16816(acc[i][j], afr[i], bfr[j]);
        }
        __syncthreads();
    }

    const int lr = lane >> 2, lc2 = (lane & 3) * 2;
    #pragma unroll
    for (int i = 0; i < 4; i++) {
        const int r0 = (int)rowBase + wm * 64 + i * 16 + lr;
        #pragma unroll
        for (int j = 0; j < 4; j++) {
            const int col = colBase + wn * 32 + j * 8 + lc2;
            float b0 = bias[col], b1 = bias[col + 1];
            float v0 = acc[i][j][0] + b0, v1 = acc[i][j][1] + b1;
            float v2 = acc[i][j][2] + b0, v3 = acc[i][j][3] + b1;
            if (DOGELU) {
                v0 = gelu_exact(v0); v1 = gelu_exact(v1);
                v2 = gelu_exact(v2); v3 = gelu_exact(v3);
            }
            if (SPLITOUT == 0) {
                float* c0 = C + ((long long)r0 * ldc + col) + z * sC;
                float* c1 = C + ((long long)(r0 + 8) * ldc + col) + z * sC;
                c0[0] = v0; c0[1] = v1;
                c1[0] = v2; c1[1] = v3;
            } else {
                long long o0 = (long long)r0 * ldc + col + z * sC;
                long long o1 = (long long)(r0 + 8) * ldc + col + z * sC;
                uint32_t h0, l0, h1, l1;
                packsplit(v0, v1, h0, l0);
                packsplit(v2, v3, h1, l1);
                *(uint32_t*)(Ch + o0) = h0;
                *(uint32_t*)(Cl + o0) = l0;
                *(uint32_t*)(Ch + o1) = h1;
                *(uint32_t*)(Cl + o1) = l1;
            }
        }
    }
}

// ---------------- fp32 -> bf16 hi/lo split, 8 elems/thread ----------------
__global__ void __launch_bounds__(256) split8_kernel(
    const float4* __restrict__ x, uint4* __restrict__ h,
    uint4* __restrict__ l, int n8)
{
    int i = blockIdx.x * 256 + threadIdx.x;
    if (i >= n8) return;
    float4 a = x[2 * i], b = x[2 * i + 1];
    uint4 hv, lv;
    packsplit(a.x, a.y, hv.x, lv.x);
    packsplit(a.z, a.w, hv.y, lv.y);
    packsplit(b.x, b.y, hv.z, lv.z);
    packsplit(b.z, b.w, hv.w, lv.w);
    h[i] = hv; l[i] = lv;
}

// ---------------- mma flash attention (bf16 split, Br=128, Bc=64, hd=64) ----------------
#define FA_TP   72
#define FA_SMEM 73728

__device__ __forceinline__ void split4_store(
    float4 v, __nv_bfloat16* H, __nv_bfloat16* L, int off)
{
    uint32_t h0, l0, h1, l1;
    packsplit(v.x, v.y, h0, l0);
    packsplit(v.z, v.w, h1, l1);
    *(uint32_t*)(H + off)     = h0;
    *(uint32_t*)(H + off + 2) = h1;
    *(uint32_t*)(L + off)     = l0;
    *(uint32_t*)(L + off + 2) = l1;
}

__global__ void __launch_bounds__(256, 2) fa_kernel(
    const float* __restrict__ Qb, int ldq,
    const float* __restrict__ Kb, int ldk,
    const float* __restrict__ Vb, int ldv,
    __nv_bfloat16* __restrict__ Oh, __nv_bfloat16* __restrict__ Ol,
    int ldo, int Skv)
{
    extern __shared__ __nv_bfloat16 sb[];
    __nv_bfloat16* Qh = sb;
    __nv_bfloat16* Ql = sb + 9216;
    __nv_bfloat16* Kh = sb + 18432;
    __nv_bfloat16* Kl = sb + 23040;
    __nv_bfloat16* Vh = sb + 27648;
    __nv_bfloat16* Vl = sb + 32256;

    const int b = blockIdx.z, h = blockIdx.y, qt = blockIdx.x;
    const int tid = threadIdx.x, wid = tid >> 5, lane = tid & 31;
    const float* Q  = Qb + h * HD;
    const float* Kp = Kb + h * HD;
    const float* Vp = Vb + h * HD;

    for (int u = tid; u < 128 * 16; u += 256) {
        int r = u >> 4, c4 = (u & 15) << 2;
        long long tok = (long long)(qt * 128 + r) * BB + b;
        float4 v = *(const float4*)(Q + tok * ldq + c4);
        v.x *= 0.125f; v.y *= 0.125f; v.z *= 0.125f; v.w *= 0.125f;
        split4_store(v, Qh, Ql, r * FA_TP + c4);
    }

    float o[8][4];
    #pragma unroll
    for (int j = 0; j < 8; j++)
        #pragma unroll
        for (int r = 0; r < 4; r++) o[j][r] = 0.f;
    float m0 = -1e30f, m1 = -1e30f, l0 = 0.f, l1 = 0.f;

    const uint32_t qbase = smem_u32(Qh);
    const uint32_t lbase = smem_u32(Ql);
    const uint32_t kbase = smem_u32(Kh);
    const uint32_t klbase = smem_u32(Kl);
    const uint32_t vbase = smem_u32(Vh);
    const uint32_t vlbase = smem_u32(Vl);
    const uint32_t lmA =
        (uint32_t)(((lane & 7) + ((lane >> 3) & 1) * 8) * (FA_TP * 2) + (lane >> 4) * 16);
    const uint32_t lmT =
        (uint32_t)(((lane & 7) + ((lane >> 4) & 1) * 8) * (FA_TP * 2) + ((lane >> 3) & 1) * 16);
    const uint32_t qwoff = (uint32_t)(wid * 16) * (FA_TP * 2);

    const int nkt = Skv >> 6;
    for (int kt = 0; kt < nkt; kt++) {
        __syncthreads();
        for (int u = tid; u < 64 * 16; u += 256) {
            int r = u >> 4, c4 = (u & 15) << 2;
            long long tok = (long long)(kt * 64 + r) * BB + b;
            float4 kv = *(const float4*)(Kp + tok * ldk + c4);
            split4_store(kv, Kh, Kl, r * FA_TP + c4);
            float4 vv = *(const float4*)(Vp + tok * ldv + c4);
            split4_store(vv, Vh, Vl, r * FA_TP + c4);
        }
        __syncthreads();

        float s[8][4];
        #pragma unroll
        for (int j = 0; j < 8; j++)
            #pragma unroll
            for (int r = 0; r < 4; r++) s[j][r] = 0.f;

        #pragma unroll
        for (int c = 0; c < 4; c++) {
            const uint32_t kb32 = c * 32;
            uint32_t aH[4], aL[4];
            LDSM_X4(aH[0], aH[1], aH[2], aH[3], qbase + qwoff + lmA + kb32);
            LDSM_X4(aL[0], aL[1], aL[2], aL[3], lbase + qwoff + lmA + kb32);
            #pragma unroll
            for (int jp = 0; jp < 4; jp++) {
                uint32_t r0, r1, r2, r3;
                LDSM_X4(r0, r1, r2, r3,
                        kbase + jp * 16 * (FA_TP * 2) + lmA + kb32);
                uint32_t bj[2]  = {r0, r2};
                uint32_t bj1[2] = {r1, r3};
                mma16816(s[2 * jp],     aH, bj);
                mma16816(s[2 * jp + 1], aH, bj1);
                mma16816(s[2 * jp],     aL, bj);
                mma16816(s[2 * jp + 1], aL, bj1);
                LDSM_X4(r0, r1, r2, r3,
                        klbase + jp * 16 * (FA_TP * 2) + lmA + kb32);
                uint32_t cj[2]  = {r0, r2};
                uint32_t cj1[2] = {r1, r3};
                mma16816(s[2 * jp],     aH, cj);
                mma16816(s[2 * jp + 1], aH, cj1);
            }
        }

        float mx0 = -1e30f, mx1 = -1e30f;
        #pragma unroll
        for (int j = 0; j < 8; j++) {
            mx0 = fmaxf(mx0, fmaxf(s[j][0], s[j][1]));
            mx1 = fmaxf(mx1, fmaxf(s[j][2], s[j][3]));
        }
        mx0 = fmaxf(mx0, __shfl_xor_sync(0xffffffffu, mx0, 1));
        mx0 = fmaxf(mx0, __shfl_xor_sync(0xffffffffu, mx0, 2));
        mx1 = fmaxf(mx1, __shfl_xor_sync(0xffffffffu, mx1, 1));
        mx1 = fmaxf(mx1, __shfl_xor_sync(0xffffffffu, mx1, 2));
        float mn0 = fmaxf(m0, mx0), mn1 = fmaxf(m1, mx1);
        float sc0 = __expf(m0 - mn0), sc1 = __expf(m1 - mn1);
        m0 = mn0; m1 = mn1;
        float rs0 = 0.f, rs1 = 0.f;
        #pragma unroll
        for (int j = 0; j < 8; j++) {
            s[j][0] = __expf(s[j][0] - m0);
            s[j][1] = __expf(s[j][1] - m0);
            s[j][2] = __expf(s[j][2] - m1);
            s[j][3] = __expf(s[j][3] - m1);
            rs0 += s[j][0] + s[j][1];
            rs1 += s[j][2] + s[j][3];
        }
        rs0 += __shfl_xor_sync(0xffffffffu, rs0, 1);
        rs0 += __shfl_xor_sync(0xffffffffu, rs0, 2);
        rs1 += __shfl_xor_sync(0xffffffffu, rs1, 1);
        rs1 += __shfl_xor_sync(0xffffffffu, rs1, 2);
        l0 = l0 * sc0 + rs0;
        l1 = l1 * sc1 + rs1;
        #pragma unroll
        for (int j = 0; j < 8; j++) {
            o[j][0] *= sc0; o[j][1] *= sc0;
            o[j][2] *= sc1; o[j][3] *= sc1;
        }

        #pragma unroll
        for (int c = 0; c < 4; c++) {
            uint32_t ph[4], pl[4];
            packsplit(s[2 * c][0],     s[2 * c][1],     ph[0], pl[0]);
            packsplit(s[2 * c][2],     s[2 * c][3],     ph[1], pl[1]);
            packsplit(s[2 * c + 1][0], s[2 * c + 1][1], ph[2], pl[2]);
            packsplit(s[2 * c + 1][2], s[2 * c + 1][3], ph[3], pl[3]);
            const uint32_t rowoff = (uint32_t)(c * 16) * (FA_TP * 2);
            #pragma unroll
            for (int jp = 0; jp < 4; jp++) {
                uint32_t r0, r1, r2, r3;
                LDSM_X4_T(r0, r1, r2, r3,
                          vbase + rowoff + lmT + jp * 32);
                uint32_t bj[2]  = {r0, r2};
                uint32_t bj1[2] = {r1, r3};
                mma16816(o[2 * jp],     ph, bj);
                mma16816(o[2 * jp + 1], ph, bj1);
                mma16816(o[2 * jp],     pl, bj);
                mma16816(o[2 * jp + 1], pl, bj1);
                LDSM_X4_T(r0, r1, r2, r3,
                          vlbase + rowoff + lmT + jp * 32);
                uint32_t cj[2]  = {r0, r2};
                uint32_t cj1[2] = {r1, r3};
                mma16816(o[2 * jp],     ph, cj);
                mma16816(o[2 * jp + 1], ph, cj1);
            }
        }
    }

    // ---- normalize + split-write ----
    const float il0 = 1.0f / l0, il1 = 1.0f / l1;
    const int r0 = qt * 128 + wid * 16 + (lane >> 2);
    const long long tok0 = (long long)r0 * BB + b;
    const long long tok1 = (long long)(r0 + 8) * BB + b;
    #pragma unroll
    for (int j = 0; j < 8; j++) {
        const int col = h * HD + j * 8 + (lane & 3) * 2;
        uint32_t h0, l0v, h1, l1v;
        packsplit(o[j][0] * il0, o[j][1] * il0, h0, l0v);
        packsplit(o[j][2] * il1, o[j][3] * il1, h1, l1v);
        *(uint32_t*)(Oh + tok0 * ldo + col) = h0;
        *(uint32_t*)(Ol + tok0 * ldo + col) = l0v;
        *(uint32_t*)(Oh + tok1 * ldo + col) = h1;
        *(uint32_t*)(Ol + tok1 * ldo + col) = l1v;
    }
}

// ---------------- gating ----------------
__global__ void __launch_bounds__(128) gate_kernel(
    const float* __restrict__ x, const float* __restrict__ wg,
    float* __restrict__ probs, float* __restrict__ gatev, int* __restrict__ gidx)
{
    const int t = blockIdx.x, tid = threadIdx.x;
    __shared__ float red[128][8];
    float acc[8];
    #pragma unroll
    for (int e = 0; e < 8; e++) acc[e] = 0.f;
    for (int d = tid; d < DIM; d += 128) {
        float xv = x[(long long)t * DIM + d];
        const float4* w = (const float4*)(wg + d * 8);
        float4 w0 = w[0], w1 = w[1];
        acc[0] += xv * w0.x; acc[1] += xv * w0.y; acc[2] += xv * w0.z; acc[3] += xv * w0.w;
        acc[4] += xv * w1.x; acc[5] += xv * w1.y; acc[6] += xv * w1.z; acc[7] += xv * w1.w;
    }
    #pragma unroll
    for (int e = 0; e < 8; e++) red[tid][e] = acc[e];
    __syncthreads();
    for (int s = 64; s > 0; s >>= 1) {
        if (tid < s)
            #pragma unroll
            for (int e = 0; e < 8; e++) red[tid][e] += red[tid + s][e];
        __syncthreads();
    }
    if (tid == 0) {
        float l[8], mx = -1e30f;
        #pragma unroll
        for (int e = 0; e < 8; e++) { l[e] = red[0][e]; mx = fmaxf(mx, l[e]); }
        float sum = 0.f;
        #pragma unroll
        for (int e = 0; e < 8; e++) { l[e] = __expf(l[e] - mx); sum += l[e]; }
        float inv = 1.0f / sum;
        #pragma unroll
        for (int e = 0; e < 8; e++) { l[e] *= inv; probs[t * 8 + e] = l[e]; }
        int i1 = 0; float v1 = l[0];
        #pragma unroll
        for (int e = 1; e < 8; e++) if (l[e] > v1) { v1 = l[e]; i1 = e; }
        int i2 = -1; float v2 = -1.f;
        #pragma unroll
        for (int e = 0; e < 8; e++) if (e != i1 && l[e] > v2) { v2 = l[e]; i2 = e; }
        gatev[2 * t] = v1; gatev[2 * t + 1] = v2;
        gidx[2 * t] = i1;  gidx[2 * t + 1] = i2;
    }
}

// ---------------- routing ----------------
__global__ void __launch_bounds__(256) route_kernel(
    const int* __restrict__ gidx, const float* __restrict__ probs,
    int* __restrict__ sl, int* __restrict__ rows, float* __restrict__ auxp)
{
    __shared__ signed char s1[NTOK];
    __shared__ signed char s2[NTOK];
    __shared__ int cnt1[8];
    __shared__ float pr[256 * 8];
    const int tid = threadIdx.x;

    for (int i = tid; i < NTOK; i += 256) {
        int2 v = ((const int2*)gidx)[i];
        s1[i] = (signed char)v.x; s2[i] = (signed char)v.y;
    }
    float lp[8];
    #pragma unroll
    for (int e = 0; e < 8; e++) lp[e] = 0.f;
    for (int i = tid; i < NTOK; i += 256) {
        const float4* p = (const float4*)(probs + i * 8);
        float4 p0 = p[0], p1 = p[1];
        lp[0] += p0.x; lp[1] += p0.y; lp[2] += p0.z; lp[3] += p0.w;
        lp[4] += p1.x; lp[5] += p1.y; lp[6] += p1.z; lp[7] += p1.w;
    }
    #pragma unroll
    for (int e = 0; e < 8; e++) pr[tid * 8 + e] = lp[e];
    __syncthreads();
    for (int s = 128; s > 0; s >>= 1) {
        if (tid < s)
            #pragma unroll
            for (int e = 0; e < 8; e++) pr[tid * 8 + e] += pr[(tid + s) * 8 + e];
        __syncthreads();
    }

    if (tid < 8) {
        int e = tid, c = 0;
        #pragma unroll 1
        for (int i = 0; i < NTOK; i++)
            if (s1[i] == e) { sl[2 * i] = (c < CAP) ? c : -1; c++; }
        cnt1[e] = c;
    }
    __syncthreads();
    if (tid < 8) {
        int e = tid, base = cnt1[e], c = 0;
        #pragma unroll 1
        for (int i = 0; i < NTOK; i++)
            if (s2[i] == e) { int loc = base + c; sl[2 * i + 1] = (loc < CAP) ? loc : -1; c++; }
        int ru = cnt1[e] + c; if (ru > CAP) ru = CAP;
        rows[e] = ru;
    }
    __syncthreads();
    if (tid == 0) {
        float a = 0.f;
        for (int e = 0; e < 8; e++)
            a += ((float)cnt1[e] / (float)NTOK) * (pr[e] / (float)NTOK);
        *auxp = 0.01f * 8.0f * a;
    }
}

// ---------------- scatter ----------------
__global__ void __launch_bounds__(256) scatter_kernel(
    const float* __restrict__ x, const int* __restrict__ gidx,
    const int* __restrict__ sl, __nv_bfloat16* __restrict__ bh,
    __nv_bfloat16* __restrict__ bl)
{
    const int t = blockIdx.x, ch = blockIdx.y;
    const int s = sl[2 * t + ch];
    if (s < 0) return;
    const int e = gidx[2 * t + ch];
    float4 v = ((const float4*)(x + (long long)t * DIM))[threadIdx.x];
    size_t base = ((size_t)e * CAP + s) * DIM + threadIdx.x * 4;
    uint32_t h0, l0, h1, l1;
    packsplit(v.x, v.y, h0, l0);
    packsplit(v.z, v.w, h1, l1);
    *(uint32_t*)(bh + base)     = h0;
    *(uint32_t*)(bh + base + 2) = h1;
    *(uint32_t*)(bl + base)     = l0;
    *(uint32_t*)(bl + base + 2) = l1;
}

// ---------------- gather ----------------
__global__ void __launch_bounds__(256) gather_kernel(
    const float* __restrict__ y, const int* __restrict__ gidx,
    const int* __restrict__ sl, const float* __restrict__ gatev,
    float* __restrict__ out)
{
    const int t = blockIdx.x;
    const float gv1 = gatev[2 * t], gv2 = gatev[2 * t + 1];
    const int s1 = sl[2 * t], s2 = sl[2 * t + 1];
    const int e1 = gidx[2 * t], e2 = gidx[2 * t + 1];
    float4 r = make_float4(0.f, 0.f, 0.f, 0.f);
    if (s1 >= 0) {
        float4 a = ((const float4*)(y + ((size_t)e1 * CAP + s1) * DIM))[threadIdx.x];
        r.x += gv1 * a.x; r.y += gv1 * a.y; r.z += gv1 * a.z; r.w += gv1 * a.w;
    }
    if (s2 >= 0) {
        float4 a = ((const float4*)(y + ((size_t)e2 * CAP + s2) * DIM))[threadIdx.x];
        r.x += gv2 * a.x; r.y += gv2 * a.y; r.z += gv2 * a.z; r.w += gv2 * a.w;
    }
    ((float4*)(out + (long long)t * DIM))[threadIdx.x] = r;
}

// ---------------- triple layernorm + aux ----------------
__device__ __forceinline__ float block_sum(float v, float* red) {
    int tid = threadIdx.x;
    red[tid] = v; __syncthreads();
    for (int s = 128; s > 0; s >>= 1) {
        if (tid < s) red[tid] += red[tid + s];
        __syncthreads();
    }
    float r = red[0]; __syncthreads();
    return r;
}

__global__ void __launch_bounds__(256) ln3_kernel(
    const float* __restrict__ x,
    const float* __restrict__ g1, const float* __restrict__ b1,
    const float* __restrict__ g2, const float* __restrict__ b2,
    const float* __restrict__ g3, const float* __restrict__ b3,
    float* __restrict__ out, const float* __restrict__ auxp, long long out_size)
{
    __shared__ float red[256];
    const int t = blockIdx.x, tid = threadIdx.x;
    float4 v = ((const float4*)(x + (long long)t * DIM))[tid];

    const float* gs[3] = {g1, g2, g3};
    const float* bs[3] = {b1, b2, b3};
    #pragma unroll
    for (int r3 = 0; r3 < 3; r3++) {
        float s = v.x + v.y + v.z + v.w;
        float mean = block_sum(s, red) * (1.0f / DIM);
        float dx = v.x - mean, dy = v.y - mean, dz = v.z - mean, dw = v.w - mean;
        float s2 = dx * dx + dy * dy + dz * dz + dw * dw;
        float var = block_sum(s2, red) * (1.0f / DIM);
        float rstd = rsqrtf(var + LN_EPS);
        float4 gg = ((const float4*)gs[r3])[tid];
        float4 bb = ((const float4*)bs[r3])[tid];
        v.x = dx * rstd * gg.x + bb.x;
        v.y = dy * rstd * gg.y + bb.y;
        v.z = dz * rstd * gg.z + bb.z;
        v.w = dw * rstd * gg.w + bb.w;
    }
    ((float4*)(out + (long long)t * DIM))[tid] = v;
    if (t == 0 && tid == 0 && out_size > (long long)NTOK * DIM)
        out[(long long)NTOK * DIM] = *auxp;
}

// ---------------- launch ----------------
extern "C" void kernel_launch(void* const* d_in, const int* in_sizes, int n_in,
                              void* d_out, int out_size) {
    const float* tgt      = (const float*)d_in[0];
    const float* mem      = (const float*)d_in[1];
    const float* w_qkv_sa = (const float*)d_in[2];
    const float* b_qkv_sa = (const float*)d_in[3];
    const float* w_o_sa   = (const float*)d_in[4];
    const float* b_o_sa   = (const float*)d_in[5];
    const float* w_qkv_ca = (const float*)d_in[6];
    const float* b_qkv_ca = (const float*)d_in[7];
    const float* w_o_ca   = (const float*)d_in[8];
    const float* b_o_ca   = (const float*)d_in[9];
    const float* ln1_g = (const float*)d_in[10];
    const float* ln1_b = (const float*)d_in[11];
    const float* ln2_g = (const float*)d_in[12];
    const float* ln2_b = (const float*)d_in[13];
    const float* ln3_g = (const float*)d_in[14];
    const float* ln3_b = (const float*)d_in[15];
    const float* w_gate = (const float*)d_in[16];
    const float* w1  = (const float*)d_in[17];
    const float* b1e = (const float*)d_in[18];
    const float* w2  = (const float*)d_in[19];
    const float* b2e = (const float*)d_in[20];
    float* out = (float*)d_out;

    float *qkv, *qca, *kvca, *x2, *probs, *gatev, *x3, *ybuf, *auxp;
    int *gidx, *sl, *rows;
    __nv_bfloat16 *tgt_h, *tgt_l, *mem_h, *mem_l, *att_h, *att_l, *x1_h, *x1_l;
    __nv_bfloat16 *buf_h, *buf_l, *hb_h, *hb_l;
    __nv_bfloat16 *wqsa_h, *wqsa_l, *wosa_h, *wosa_l, *wqca_h, *wqca_l, *woca_h, *woca_l;
    __nv_bfloat16 *w1s_h, *w1s_l, *w2s_h, *w2s_l;

    cudaGetSymbolAddress((void**)&qkv,  g_qkv);
    cudaGetSymbolAddress((void**)&qca,  g_qca);
    cudaGetSymbolAddress((void**)&kvca, g_kvca);
    cudaGetSymbolAddress((void**)&x2,   g_x2);
    cudaGetSymbolAddress((void**)&probs,g_probs);
    cudaGetSymbolAddress((void**)&gatev,g_gatev);
    cudaGetSymbolAddress((void**)&gidx, g_gidx);
    cudaGetSymbolAddress((void**)&sl,   g_sl);
    cudaGetSymbolAddress((void**)&rows, g_rows);
    cudaGetSymbolAddress((void**)&auxp, g_aux);
    cudaGetSymbolAddress((void**)&ybuf, g_y);
    cudaGetSymbolAddress((void**)&x3,   g_x3);
    cudaGetSymbolAddress((void**)&tgt_h, g_tgt_h); cudaGetSymbolAddress((void**)&tgt_l, g_tgt_l);
    cudaGetSymbolAddress((void**)&mem_h, g_mem_h); cudaGetSymbolAddress((void**)&mem_l, g_mem_l);
    cudaGetSymbolAddress((void**)&att_h, g_att_h); cudaGetSymbolAddress((void**)&att_l, g_att_l);
    cudaGetSymbolAddress((void**)&x1_h,  g_x1_h);  cudaGetSymbolAddress((void**)&x1_l,  g_x1_l);
    cudaGetSymbolAddress((void**)&buf_h, g_buf_h); cudaGetSymbolAddress((void**)&buf_l, g_buf_l);
    cudaGetSymbolAddress((void**)&hb_h,  g_hb_h);  cudaGetSymbolAddress((void**)&hb_l,  g_hb_l);
    cudaGetSymbolAddress((void**)&wqsa_h, g_wqsa_h); cudaGetSymbolAddress((void**)&wqsa_l, g_wqsa_l);
    cudaGetSymbolAddress((void**)&wosa_h, g_wosa_h); cudaGetSymbolAddress((void**)&wosa_l, g_wosa_l);
    cudaGetSymbolAddress((void**)&wqca_h, g_wqca_h); cudaGetSymbolAddress((void**)&wqca_l, g_wqca_l);
    cudaGetSymbolAddress((void**)&woca_h, g_woca_h); cudaGetSymbolAddress((void**)&woca_l, g_woca_l);
    cudaGetSymbolAddress((void**)&w1s_h, g_w1s_h); cudaGetSymbolAddress((void**)&w1s_l, g_w1s_l);
    cudaGetSymbolAddress((void**)&w2s_h, g_w2s_h); cudaGetSymbolAddress((void**)&w2s_l, g_w2s_l);

    cudaFuncSetAttribute(fa_kernel, cudaFuncAttributeMaxDynamicSharedMemorySize, FA_SMEM);
    cudaFuncSetAttribute(mmagemm_kernel<0,0,0>, cudaFuncAttributeMaxDynamicSharedMemorySize, GEMM_SMEM);
    cudaFuncSetAttribute(mmagemm_kernel<0,0,1>, cudaFuncAttributeMaxDynamicSharedMemorySize, GEMM_SMEM);
    cudaFuncSetAttribute(mmagemm_kernel<1,1,1>, cudaFuncAttributeMaxDynamicSharedMemorySize, GEMM_SMEM);
    cudaFuncSetAttribute(mmagemm_kernel<1,0,0>, cudaFuncAttributeMaxDynamicSharedMemorySize, GEMM_SMEM);

    // ---- conversions (all elementwise now) ----
    split8_kernel<<<(3*DIM*DIM/8 + 255)/256, 256>>>((const float4*)w_qkv_sa, (uint4*)wqsa_h, (uint4*)wqsa_l, 3*DIM*DIM/8);
    split8_kernel<<<(DIM*DIM/8 + 255)/256, 256>>>((const float4*)w_o_sa, (uint4*)wosa_h, (uint4*)wosa_l, DIM*DIM/8);
    split8_kernel<<<(3*DIM*DIM/8 + 255)/256, 256>>>((const float4*)w_qkv_ca, (uint4*)wqca_h, (uint4*)wqca_l, 3*DIM*DIM/8);
    split8_kernel<<<(DIM*DIM/8 + 255)/256, 256>>>((const float4*)w_o_ca, (uint4*)woca_h, (uint4*)woca_l, DIM*DIM/8);
    split8_kernel<<<(int)((size_t)NE*DIM*DFF/8 + 255)/256, 256>>>((const float4*)w1, (uint4*)w1s_h, (uint4*)w1s_l, (int)((size_t)NE*DIM*DFF/8));
    split8_kernel<<<(int)((size_t)NE*DIM*DFF/8 + 255)/256, 256>>>((const float4*)w2, (uint4*)w2s_h, (uint4*)w2s_l, (int)((size_t)NE*DIM*DFF/8));
    split8_kernel<<<(NTOK*DIM/8 + 255)/256, 256>>>((const float4*)tgt, (uint4*)tgt_h, (uint4*)tgt_l, NTOK*DIM/8);
    split8_kernel<<<(NTOK*DIM/8 + 255)/256, 256>>>((const float4*)mem, (uint4*)mem_h, (uint4*)mem_l, NTOK*DIM/8);

    // 1) SA qkv projection (NT)
    mmagemm_kernel<0,0,0><<<dim3(3072/128, NTOK/128, 1), 256, GEMM_SMEM>>>(
        tgt_h, tgt_l, wqsa_h, wqsa_l, b_qkv_sa, qkv, nullptr, nullptr,
        DIM, DIM, 3*DIM, 0, 0, 0, 0, nullptr);

    // 2) self-attention (mma, split-out)
    fa_kernel<<<dim3(SQ/128, NH, BB), 256, FA_SMEM>>>(
        qkv, 3*DIM, qkv + DIM, 3*DIM, qkv + 2*DIM, 3*DIM, att_h, att_l, DIM, SQ);

    // 3) SA output projection -> x1 split
    mmagemm_kernel<0,0,1><<<dim3(DIM/128, NTOK/128, 1), 256, GEMM_SMEM>>>(
        att_h, att_l, wosa_h, wosa_l, b_o_sa, nullptr, x1_h, x1_l,
        DIM, DIM, DIM, 0, 0, 0, 0, nullptr);

    // 4) CA q projection -> fp32 qca
    mmagemm_kernel<0,0,0><<<dim3(DIM/128, NTOK/128, 1), 256, GEMM_SMEM>>>(
        x1_h, x1_l, wqca_h, wqca_l, b_qkv_ca, qca, nullptr, nullptr,
        DIM, DIM, DIM, 0, 0, 0, 0, nullptr);

    // 5) CA k,v projection from memory -> fp32 kvca
    mmagemm_kernel<0,0,0><<<dim3(2*DIM/128, NTOK/128, 1), 256, GEMM_SMEM>>>(
        mem_h, mem_l, wqca_h + (size_t)DIM*DIM, wqca_l + (size_t)DIM*DIM,
        b_qkv_ca + DIM, kvca, nullptr, nullptr,
        DIM, DIM, 2*DIM, 0, 0, 0, 0, nullptr);

    // 6) cross-attention (mma, split-out)
    fa_kernel<<<dim3(SQ/128, NH, BB), 256, FA_SMEM>>>(
        qca, DIM, kvca, 2*DIM, kvca + DIM, 2*DIM, att_h, att_l, DIM, SQ);

    // 7) CA output projection -> fp32 x2
    mmagemm_kernel<0,0,0><<<dim3(DIM/128, NTOK/128, 1), 256, GEMM_SMEM>>>(
        att_h, att_l, woca_h, woca_l, b_o_ca, x2, nullptr, nullptr,
        DIM, DIM, DIM, 0, 0, 0, 0, nullptr);

    // 8-9) gating + routing
    gate_kernel<<<NTOK, 128>>>(x2, w_gate, probs, gatev, gidx);
    route_kernel<<<1, 256>>>(gidx, probs, sl, rows, auxp);

    // 10) scatter -> bf16 hi/lo expert buffer
    scatter_kernel<<<dim3(NTOK, 2), 256>>>(x2, gidx, sl, buf_h, buf_l);

    // 11) expert FFN layer 1 (B NN, +GELU, split-out), row-skip
    mmagemm_kernel<1,1,1><<<dim3(DFF/128, CAP/128, NE), 256, GEMM_SMEM>>>(
        buf_h, buf_l, w1s_h, w1s_l, b1e, nullptr, hb_h, hb_l,
        DIM, DFF, DFF, (long long)CAP*DIM, (long long)DIM*DFF, DFF, (long long)CAP*DFF, rows);

    // 12) expert FFN layer 2 (B NN) -> fp32 ybuf, row-skip
    mmagemm_kernel<1,0,0><<<dim3(DIM/128, CAP/128, NE), 256, GEMM_SMEM>>>(
        hb_h, hb_l, w2s_h, w2s_l, b2e, ybuf, nullptr, nullptr,
        DFF, DIM, DIM, (long long)CAP*DFF, (long long)DFF*DIM, DIM, (long long)CAP*DIM, rows);

    // 13) gather
    gather_kernel<<<NTOK, 256>>>(ybuf, gidx, sl, gatev, x3);

    // 14) triple layernorm + aux
    ln3_kernel<<<NTOK, 256>>>(x3, ln1_g, ln1_b, ln2_g, ln2_b, ln3_g, ln3_b,
                              out, auxp, (long long)out_size);
}

// round 14
// speedup vs baseline: 2.5537x; 1.0772x over previous
#include <cuda_runtime.h>
#include <cuda_bf16.h>
#include <math.h>
#include <stdint.h>

// ---------------- problem constants ----------------
#define SQ   2048
#define BB   2
#define DIM  1024
#define NH   16
#define HD   64
#define NTOK 4096
#define NE   8
#define DFF  4096
#define CAP  2048
#define LN_EPS 1e-5f

// ---------------- scratch (device globals) ----------------
__device__ __nv_bfloat16 g_tgt_h[NTOK * DIM], g_tgt_l[NTOK * DIM];
__device__ __nv_bfloat16 g_mem_h[NTOK * DIM], g_mem_l[NTOK * DIM];
__device__ __nv_bfloat16 g_att_h[NTOK * DIM], g_att_l[NTOK * DIM];
__device__ __nv_bfloat16 g_x1_h [NTOK * DIM], g_x1_l [NTOK * DIM];
__device__ __nv_bfloat16 g_buf_h[NE * CAP * DIM], g_buf_l[NE * CAP * DIM];
__device__ __nv_bfloat16 g_hb_h[(size_t)NE * CAP * DFF], g_hb_l[(size_t)NE * CAP * DFF];
__device__ __nv_bfloat16 g_wqsa_h[3 * DIM * DIM], g_wqsa_l[3 * DIM * DIM];
__device__ __nv_bfloat16 g_wosa_h[DIM * DIM],     g_wosa_l[DIM * DIM];
__device__ __nv_bfloat16 g_wqca_h[3 * DIM * DIM], g_wqca_l[3 * DIM * DIM];
__device__ __nv_bfloat16 g_woca_h[DIM * DIM],     g_woca_l[DIM * DIM];
__device__ __nv_bfloat16 g_w1s_h[(size_t)NE * DIM * DFF], g_w1s_l[(size_t)NE * DIM * DFF];
__device__ __nv_bfloat16 g_w2s_h[(size_t)NE * DIM * DFF], g_w2s_l[(size_t)NE * DIM * DFF];
__device__ float g_qkv [NTOK * 3 * DIM];
__device__ float g_qca [NTOK * DIM];
__device__ float g_kvca[NTOK * 2 * DIM];
__device__ float g_x2  [NTOK * DIM];
__device__ float g_probs[NTOK * NE];
__device__ float g_gatev[NTOK * 2];
__device__ int   g_gidx[NTOK * 2];
__device__ int   g_sl  [NTOK * 2];
__device__ int   g_rows[NE];
__device__ float g_aux;
__device__ float g_y [NE * CAP * DIM];

__device__ __forceinline__ float gelu_exact(float x) {
    return 0.5f * x * (1.0f + erff(x * 0.70710678118654752440f));
}
__device__ __forceinline__ void split2(float v, __nv_bfloat16& h, __nv_bfloat16& l) {
    h = __float2bfloat16(v);
    l = __float2bfloat16(v - __bfloat162float(h));
}
__device__ __forceinline__ uint32_t smem_u32(const void* p) {
    uint32_t a;
    asm("{ .reg .u64 t; cvta.to.shared.u64 t, %1; cvt.u32.u64 %0, t; }" : "=r"(a) : "l"(p));
    return a;
}
__device__ __forceinline__ uint32_t packh2(__nv_bfloat16 a, __nv_bfloat16 b) {
    __nv_bfloat162 t = __halves2bfloat162(a, b);
    return *(uint32_t*)&t;
}
__device__ __forceinline__ void packsplit(float a, float b, uint32_t& hi, uint32_t& lo) {
    __nv_bfloat16 ha, la, hb, lb;
    split2(a, ha, la); split2(b, hb, lb);
    hi = packh2(ha, hb); lo = packh2(la, lb);
}
#define CP_ASYNC16(s, g) \
    asm volatile("cp.async.cg.shared.global [%0], [%1], 16;" :: "r"(s), "l"(g))
#define CP_COMMIT() asm volatile("cp.async.commit_group;" ::: "memory")

__device__ __forceinline__ void mma16816(float* d, const uint32_t* a, const uint32_t* b) {
    asm volatile(
        "mma.sync.aligned.m16n8k16.row.col.f32.bf16.bf16.f32 "
        "{%0,%1,%2,%3}, {%4,%5,%6,%7}, {%8,%9}, {%0,%1,%2,%3};"
        : "+f"(d[0]), "+f"(d[1]), "+f"(d[2]), "+f"(d[3])
        : "r"(a[0]), "r"(a[1]), "r"(a[2]), "r"(a[3]), "r"(b[0]), "r"(b[1]));
}
#define LDSM_X4(r0, r1, r2, r3, addr) \
    asm volatile("ldmatrix.sync.aligned.m8n8.x4.shared.b16 {%0,%1,%2,%3}, [%4];" \
        : "=r"(r0), "=r"(r1), "=r"(r2), "=r"(r3) : "r"(addr))
#define LDSM_X4_T(r0, r1, r2, r3, addr) \
    asm volatile("ldmatrix.sync.aligned.m8n8.x4.trans.shared.b16 {%0,%1,%2,%3}, [%4];" \
        : "=r"(r0), "=r"(r1), "=r"(r2), "=r"(r3) : "r"(addr))

// ---------------- bf16 mma GEMM, 3-term hi/lo split ----------------
// BNN=0: C[r,c] = sum_k A[r,k]*B[c,k]   (B [N][K], row stride ldb)
// BNN=1: C[r,c] = sum_k A[r,k]*B[k,c]   (B [K][N], row stride ldb)
#define TPAD   40
#define TPADB  136
#define TILE_B (128 * TPAD * 2)
#define STAGE_B (4 * TILE_B)
#define GEMM_SMEM (2 * STAGE_B)

template<int BNN, int DOGELU, int SPLITOUT>
__global__ void __launch_bounds__(256, 2) mmagemm_kernel(
    const __nv_bfloat16* __restrict__ Ah, const __nv_bfloat16* __restrict__ Al,
    const __nv_bfloat16* __restrict__ Bh, const __nv_bfloat16* __restrict__ Bl,
    const float* __restrict__ bias, float* __restrict__ C,
    __nv_bfloat16* __restrict__ Ch, __nv_bfloat16* __restrict__ Cl,
    int K, int ldb, int ldc,
    long long sA, long long sB, long long sBias, long long sC,
    const int* __restrict__ rows_used)
{
    extern __shared__ char smem[];
    const int z = blockIdx.z;
    if (rows_used && (int)(blockIdx.y * 128) >= rows_used[z]) return;

    const int tid = threadIdx.x, wid = tid >> 5, lane = tid & 31;
    const int wm = wid & 1, wn = wid >> 1;
    const long long rowBase = (long long)blockIdx.y * 128;
    const int colBase = blockIdx.x * 128;
    Ah += z * sA; Al += z * sA; Bh += z * sB; Bl += z * sB; bias += z * sBias;

    const __nv_bfloat16* srcA0 = Ah + rowBase * K;
    const __nv_bfloat16* srcA1 = Al + rowBase * K;
    const __nv_bfloat16* srcB0;
    const __nv_bfloat16* srcB1;
    if (BNN) { srcB0 = Bh + colBase; srcB1 = Bl + colBase; }
    else     { srcB0 = Bh + (long long)colBase * ldb; srcB1 = Bl + (long long)colBase * ldb; }

    const uint32_t sbase = smem_u32(smem);
    const int NC = K >> 5;

    auto prefetch = [&](int st, int kc) {
        const int koff = kc * 32;
        const uint32_t stb = sbase + st * STAGE_B;
        {
            const __nv_bfloat16* sa[2] = {srcA0 + koff, srcA1 + koff};
            #pragma unroll
            for (int bi = 0; bi < 2; bi++) {
                const uint32_t tb = stb + bi * TILE_B;
                #pragma unroll
                for (int it = 0; it < 2; it++) {
                    int idx = it * 256 + tid;
                    int row = idx >> 2, c = idx & 3;
                    CP_ASYNC16(tb + row * (TPAD * 2) + c * 16,
                               (const void*)(sa[bi] + (long long)row * K + c * 8));
                }
            }
        }
        if (BNN) {
            const __nv_bfloat16* sb2[2] = {srcB0, srcB1};
            #pragma unroll
            for (int bi = 0; bi < 2; bi++) {
                const uint32_t tb = stb + (2 + bi) * TILE_B;
                #pragma unroll
                for (int it = 0; it < 2; it++) {
                    int idx = it * 256 + tid;
                    int row = idx >> 4, c = idx & 15;
                    CP_ASYNC16(tb + row * (TPADB * 2) + c * 16,
                               (const void*)(sb2[bi] + (long long)(koff + row) * ldb + c * 8));
                }
            }
        } else {
            const __nv_bfloat16* sb2[2] = {srcB0 + koff, srcB1 + koff};
            #pragma unroll
            for (int bi = 0; bi < 2; bi++) {
                const uint32_t tb = stb + (2 + bi) * TILE_B;
                #pragma unroll
                for (int it = 0; it < 2; it++) {
                    int idx = it * 256 + tid;
                    int row = idx >> 2, c = idx & 3;
                    CP_ASYNC16(tb + row * (TPAD * 2) + c * 16,
                               (const void*)(sb2[bi] + (long long)row * ldb + c * 8));
                }
            }
        }
        CP_COMMIT();
    };

    float acc[4][4][4];
    #pragma unroll
    for (int i = 0; i < 4; i++)
        #pragma unroll
        for (int j = 0; j < 4; j++)
            #pragma unroll
            for (int r = 0; r < 4; r++) acc[i][j][r] = 0.f;

    const uint32_t lmoff =
        (uint32_t)(((lane & 7) + ((lane >> 3) & 1) * 8) * (TPAD * 2) + (lane >> 4) * 16);
    const uint32_t lmT =
        (uint32_t)(((lane & 7) + ((lane >> 4) & 1) * 8) * (TPADB * 2) + ((lane >> 3) & 1) * 16);

    prefetch(0, 0);

    for (int ic = 0; ic < NC; ic++) {
        const int p = ic & 1;
        if (ic + 1 < NC) {
            prefetch(p ^ 1, ic + 1);
            asm volatile("cp.async.wait_group 1;" ::: "memory");
        } else {
            asm volatile("cp.async.wait_group 0;" ::: "memory");
        }
        __syncthreads();

        const uint32_t stp = sbase + p * STAGE_B;
        const uint32_t aHb = stp +          wm * 64 * (TPAD * 2) + lmoff;
        const uint32_t aLb = stp + TILE_B + wm * 64 * (TPAD * 2) + lmoff;
        uint32_t bHb, bLb;
        if (BNN) {
            bHb = stp + 2 * TILE_B + wn * 64 + lmT;
            bLb = stp + 3 * TILE_B + wn * 64 + lmT;
        } else {
            bHb = stp + 2 * TILE_B + wn * 32 * (TPAD * 2) + lmoff;
            bLb = stp + 3 * TILE_B + wn * 32 * (TPAD * 2) + lmoff;
        }

        uint32_t afr[4][4];
        uint32_t bfh[4][2], bfl[4][2];

        #pragma unroll
        for (int ks = 0; ks < 2; ks++) {
            const uint32_t kb = ks * 32;

            // load Bh and Bl fragment sets once per sub-step
            if (BNN) {
                const uint32_t kbn = ks * 16 * (TPADB * 2);
                #pragma unroll
                for (int jp = 0; jp < 2; jp++) {
                    uint32_t r0, r1, r2, r3;
                    LDSM_X4_T(r0, r1, r2, r3, bHb + kbn + jp * 32);
                    bfh[2 * jp][0] = r0; bfh[2 * jp][1] = r2;
                    bfh[2 * jp + 1][0] = r1; bfh[2 * jp + 1][1] = r3;
                    LDSM_X4_T(r0, r1, r2, r3, bLb + kbn + jp * 32);
                    bfl[2 * jp][0] = r0; bfl[2 * jp][1] = r2;
                    bfl[2 * jp + 1][0] = r1; bfl[2 * jp + 1][1] = r3;
                }
            } else {
                #pragma unroll
                for (int pr = 0; pr < 2; pr++) {
                    LDSM_X4(bfh[pr * 2][0], bfh[pr * 2 + 1][0],
                            bfh[pr * 2][1], bfh[pr * 2 + 1][1],
                            bHb + pr * 16 * (TPAD * 2) + kb);
                    LDSM_X4(bfl[pr * 2][0], bfl[pr * 2 + 1][0],
                            bfl[pr * 2][1], bfl[pr * 2 + 1][1],
                            bLb + pr * 16 * (TPAD * 2) + kb);
                }
            }

            // Ah x (Bh, Bl)
            #pragma unroll
            for (int i = 0; i < 4; i++)
                LDSM_X4(afr[i][0], afr[i][1], afr[i][2], afr[i][3],
                        aHb + i * 16 * (TPAD * 2) + kb);
            #pragma unroll
            for (int i = 0; i < 4; i++)
                #pragma unroll
                for (int j = 0; j < 4; j++) {
                    mma16816(acc[i][j], afr[i], bfh[j]);
                    mma16816(acc[i][j], afr[i], bfl[j]);
                }

            // Al x Bh
            #pragma unroll
            for (int i = 0; i < 4; i++)
                LDSM_X4(afr[i][0], afr[i][1], afr[i][2], afr[i][3],
                        aLb + i * 16 * (TPAD * 2) + kb);
            #pragma unroll
            for (int i = 0; i < 4; i++)
                #pragma unroll
                for (int j = 0; j < 4; j++)
                    mma16816(acc[i][j], afr[i], bfh[j]);
        }
        __syncthreads();
    }

    const int lr = lane >> 2, lc2 = (lane & 3) * 2;
    #pragma unroll
    for (int i = 0; i < 4; i++) {
        const int r0 = (int)rowBase + wm * 64 + i * 16 + lr;
        #pragma unroll
        for (int j = 0; j < 4; j++) {
            const int col = colBase + wn * 32 + j * 8 + lc2;
            float b0 = bias[col], b1 = bias[col + 1];
            float v0 = acc[i][j][0] + b0, v1 = acc[i][j][1] + b1;
            float v2 = acc[i][j][2] + b0, v3 = acc[i][j][3] + b1;
            if (DOGELU) {
                v0 = gelu_exact(v0); v1 = gelu_exact(v1);
                v2 = gelu_exact(v2); v3 = gelu_exact(v3);
            }
            if (SPLITOUT == 0) {
                float* c0 = C + ((long long)r0 * ldc + col) + z * sC;
                float* c1 = C + ((long long)(r0 + 8) * ldc + col) + z * sC;
                c0[0] = v0; c0[1] = v1;
                c1[0] = v2; c1[1] = v3;
            } else {
                long long o0 = (long long)r0 * ldc + col + z * sC;
                long long o1 = (long long)(r0 + 8) * ldc + col + z * sC;
                uint32_t h0, l0, h1, l1;
                packsplit(v0, v1, h0, l0);
                packsplit(v2, v3, h1, l1);
                *(uint32_t*)(Ch + o0) = h0;
                *(uint32_t*)(Cl + o0) = l0;
                *(uint32_t*)(Ch + o1) = h1;
                *(uint32_t*)(Cl + o1) = l1;
            }
        }
    }
}

// ---------------- fp32 -> bf16 hi/lo split, 8 elems/thread ----------------
__global__ void __launch_bounds__(256) split8_kernel(
    const float4* __restrict__ x, uint4* __restrict__ h,
    uint4* __restrict__ l, int n8)
{
    int i = blockIdx.x * 256 + threadIdx.x;
    if (i >= n8) return;
    float4 a = x[2 * i], b = x[2 * i + 1];
    uint4 hv, lv;
    packsplit(a.x, a.y, hv.x, lv.x);
    packsplit(a.z, a.w, hv.y, lv.y);
    packsplit(b.x, b.y, hv.z, lv.z);
    packsplit(b.z, b.w, hv.w, lv.w);
    h[i] = hv; l[i] = lv;
}

// ---------------- mma flash attention (bf16 split, Br=128, Bc=64, hd=64) ----------------
#define FA_TP   72
#define FA_SMEM 73728

__device__ __forceinline__ void split4_store(
    float4 v, __nv_bfloat16* H, __nv_bfloat16* L, int off)
{
    uint32_t h0, l0, h1, l1;
    packsplit(v.x, v.y, h0, l0);
    packsplit(v.z, v.w, h1, l1);
    *(uint32_t*)(H + off)     = h0;
    *(uint32_t*)(H + off + 2) = h1;
    *(uint32_t*)(L + off)     = l0;
    *(uint32_t*)(L + off + 2) = l1;
}

__global__ void __launch_bounds__(256, 2) fa_kernel(
    const float* __restrict__ Qb, int ldq,
    const float* __restrict__ Kb, int ldk,
    const float* __restrict__ Vb, int ldv,
    __nv_bfloat16* __restrict__ Oh, __nv_bfloat16* __restrict__ Ol,
    int ldo, int Skv)
{
    extern __shared__ __nv_bfloat16 sb[];
    __nv_bfloat16* Qh = sb;
    __nv_bfloat16* Ql = sb + 9216;
    __nv_bfloat16* Kh = sb + 18432;
    __nv_bfloat16* Kl = sb + 23040;
    __nv_bfloat16* Vh = sb + 27648;
    __nv_bfloat16* Vl = sb + 32256;

    const int b = blockIdx.z, h = blockIdx.y, qt = blockIdx.x;
    const int tid = threadIdx.x, wid = tid >> 5, lane = tid & 31;
    const float* Q  = Qb + h * HD;
    const float* Kp = Kb + h * HD;
    const float* Vp = Vb + h * HD;

    for (int u = tid; u < 128 * 16; u += 256) {
        int r = u >> 4, c4 = (u & 15) << 2;
        long long tok = (long long)(qt * 128 + r) * BB + b;
        float4 v = *(const float4*)(Q + tok * ldq + c4);
        v.x *= 0.125f; v.y *= 0.125f; v.z *= 0.125f; v.w *= 0.125f;
        split4_store(v, Qh, Ql, r * FA_TP + c4);
    }

    float o[8][4];
    #pragma unroll
    for (int j = 0; j < 8; j++)
        #pragma unroll
        for (int r = 0; r < 4; r++) o[j][r] = 0.f;
    float m0 = -1e30f, m1 = -1e30f, l0 = 0.f, l1 = 0.f;

    const uint32_t qbase = smem_u32(Qh);
    const uint32_t lbase = smem_u32(Ql);
    const uint32_t kbase = smem_u32(Kh);
    const uint32_t klbase = smem_u32(Kl);
    const uint32_t vbase = smem_u32(Vh);
    const uint32_t vlbase = smem_u32(Vl);
    const uint32_t lmA =
        (uint32_t)(((lane & 7) + ((lane >> 3) & 1) * 8) * (FA_TP * 2) + (lane >> 4) * 16);
    const uint32_t lmT =
        (uint32_t)(((lane & 7) + ((lane >> 4) & 1) * 8) * (FA_TP * 2) + ((lane >> 3) & 1) * 16);
    const uint32_t qwoff = (uint32_t)(wid * 16) * (FA_TP * 2);

    const int nkt = Skv >> 6;
    for (int kt = 0; kt < nkt; kt++) {
        __syncthreads();
        for (int u = tid; u < 64 * 16; u += 256) {
            int r = u >> 4, c4 = (u & 15) << 2;
            long long tok = (long long)(kt * 64 + r) * BB + b;
            float4 kv = *(const float4*)(Kp + tok * ldk + c4);
            split4_store(kv, Kh, Kl, r * FA_TP + c4);
            float4 vv = *(const float4*)(Vp + tok * ldv + c4);
            split4_store(vv, Vh, Vl, r * FA_TP + c4);
        }
        __syncthreads();

        float s[8][4];
        #pragma unroll
        for (int j = 0; j < 8; j++)
            #pragma unroll
            for (int r = 0; r < 4; r++) s[j][r] = 0.f;

        #pragma unroll
        for (int c = 0; c < 4; c++) {
            const uint32_t kb32 = c * 32;
            uint32_t aH[4], aL[4];
            LDSM_X4(aH[0], aH[1], aH[2], aH[3], qbase + qwoff + lmA + kb32);
            LDSM_X4(aL[0], aL[1], aL[2], aL[3], lbase + qwoff + lmA + kb32);
            #pragma unroll
            for (int jp = 0; jp < 4; jp++) {
                uint32_t r0, r1, r2, r3;
                LDSM_X4(r0, r1, r2, r3,
                        kbase + jp * 16 * (FA_TP * 2) + lmA + kb32);
                uint32_t bj[2]  = {r0, r2};
                uint32_t bj1[2] = {r1, r3};
                mma16816(s[2 * jp],     aH, bj);
                mma16816(s[2 * jp + 1], aH, bj1);
                mma16816(s[2 * jp],     aL, bj);
                mma16816(s[2 * jp + 1], aL, bj1);
                LDSM_X4(r0, r1, r2, r3,
                        klbase + jp * 16 * (FA_TP * 2) + lmA + kb32);
                uint32_t cj[2]  = {r0, r2};
                uint32_t cj1[2] = {r1, r3};
                mma16816(s[2 * jp],     aH, cj);
                mma16816(s[2 * jp + 1], aH, cj1);
            }
        }

        float mx0 = -1e30f, mx1 = -1e30f;
        #pragma unroll
        for (int j = 0; j < 8; j++) {
            mx0 = fmaxf(mx0, fmaxf(s[j][0], s[j][1]));
            mx1 = fmaxf(mx1, fmaxf(s[j][2], s[j][3]));
        }
        mx0 = fmaxf(mx0, __shfl_xor_sync(0xffffffffu, mx0, 1));
        mx0 = fmaxf(mx0, __shfl_xor_sync(0xffffffffu, mx0, 2));
        mx1 = fmaxf(mx1, __shfl_xor_sync(0xffffffffu, mx1, 1));
        mx1 = fmaxf(mx1, __shfl_xor_sync(0xffffffffu, mx1, 2));
        float mn0 = fmaxf(m0, mx0), mn1 = fmaxf(m1, mx1);
        float sc0 = __expf(m0 - mn0), sc1 = __expf(m1 - mn1);
        m0 = mn0; m1 = mn1;
        float rs0 = 0.f, rs1 = 0.f;
        #pragma unroll
        for (int j = 0; j < 8; j++) {
            s[j][0] = __expf(s[j][0] - m0);
            s[j][1] = __expf(s[j][1] - m0);
            s[j][2] = __expf(s[j][2] - m1);
            s[j][3] = __expf(s[j][3] - m1);
            rs0 += s[j][0] + s[j][1];
            rs1 += s[j][2] + s[j][3];
        }
        rs0 += __shfl_xor_sync(0xffffffffu, rs0, 1);
        rs0 += __shfl_xor_sync(0xffffffffu, rs0, 2);
        rs1 += __shfl_xor_sync(0xffffffffu, rs1, 1);
        rs1 += __shfl_xor_sync(0xffffffffu, rs1, 2);
        l0 = l0 * sc0 + rs0;
        l1 = l1 * sc1 + rs1;
        #pragma unroll
        for (int j = 0; j < 8; j++) {
            o[j][0] *= sc0; o[j][1] *= sc0;
            o[j][2] *= sc1; o[j][3] *= sc1;
        }

        #pragma unroll
        for (int c = 0; c < 4; c++) {
            uint32_t ph[4], pl[4];
            packsplit(s[2 * c][0],     s[2 * c][1],     ph[0], pl[0]);
            packsplit(s[2 * c][2],     s[2 * c][3],     ph[1], pl[1]);
            packsplit(s[2 * c + 1][0], s[2 * c + 1][1], ph[2], pl[2]);
            packsplit(s[2 * c + 1][2], s[2 * c + 1][3], ph[3], pl[3]);
            const uint32_t rowoff = (uint32_t)(c * 16) * (FA_TP * 2);
            #pragma unroll
            for (int jp = 0; jp < 4; jp++) {
                uint32_t r0, r1, r2, r3;
                LDSM_X4_T(r0, r1, r2, r3,
                          vbase + rowoff + lmT + jp * 32);
                uint32_t bj[2]  = {r0, r2};
                uint32_t bj1[2] = {r1, r3};
                mma16816(o[2 * jp],     ph, bj);
                mma16816(o[2 * jp + 1], ph, bj1);
                mma16816(o[2 * jp],     pl, bj);
                mma16816(o[2 * jp + 1], pl, bj1);
                LDSM_X4_T(r0, r1, r2, r3,
                          vlbase + rowoff + lmT + jp * 32);
                uint32_t cj[2]  = {r0, r2};
                uint32_t cj1[2] = {r1, r3};
                mma16816(o[2 * jp],     ph, cj);
                mma16816(o[2 * jp + 1], ph, cj1);
            }
        }
    }

    const float il0 = 1.0f / l0, il1 = 1.0f / l1;
    const int r0 = qt * 128 + wid * 16 + (lane >> 2);
    const long long tok0 = (long long)r0 * BB + b;
    const long long tok1 = (long long)(r0 + 8) * BB + b;
    #pragma unroll
    for (int j = 0; j < 8; j++) {
        const int col = h * HD + j * 8 + (lane & 3) * 2;
        uint32_t h0, l0v, h1, l1v;
        packsplit(o[j][0] * il0, o[j][1] * il0, h0, l0v);
        packsplit(o[j][2] * il1, o[j][3] * il1, h1, l1v);
        *(uint32_t*)(Oh + tok0 * ldo + col) = h0;
        *(uint32_t*)(Ol + tok0 * ldo + col) = l0v;
        *(uint32_t*)(Oh + tok1 * ldo + col) = h1;
        *(uint32_t*)(Ol + tok1 * ldo + col) = l1v;
    }
}

// ---------------- gating ----------------
__global__ void __launch_bounds__(128) gate_kernel(
    const float* __restrict__ x, const float* __restrict__ wg,
    float* __restrict__ probs, float* __restrict__ gatev, int* __restrict__ gidx)
{
    const int t = blockIdx.x, tid = threadIdx.x;
    __shared__ float red[128][8];
    float acc[8];
    #pragma unroll
    for (int e = 0; e < 8; e++) acc[e] = 0.f;
    for (int d = tid; d < DIM; d += 128) {
        float xv = x[(long long)t * DIM + d];
        const float4* w = (const float4*)(wg + d * 8);
        float4 w0 = w[0], w1 = w[1];
        acc[0] += xv * w0.x; acc[1] += xv * w0.y; acc[2] += xv * w0.z; acc[3] += xv * w0.w;
        acc[4] += xv * w1.x; acc[5] += xv * w1.y; acc[6] += xv * w1.z; acc[7] += xv * w1.w;
    }
    #pragma unroll
    for (int e = 0; e < 8; e++) red[tid][e] = acc[e];
    __syncthreads();
    for (int s = 64; s > 0; s >>= 1) {
        if (tid < s)
            #pragma unroll
            for (int e = 0; e < 8; e++) red[tid][e] += red[tid + s][e];
        __syncthreads();
    }
    if (tid == 0) {
        float l[8], mx = -1e30f;
        #pragma unroll
        for (int e = 0; e < 8; e++) { l[e] = red[0][e]; mx = fmaxf(mx, l[e]); }
        float sum = 0.f;
        #pragma unroll
        for (int e = 0; e < 8; e++) { l[e] = __expf(l[e] - mx); sum += l[e]; }
        float inv = 1.0f / sum;
        #pragma unroll
        for (int e = 0; e < 8; e++) { l[e] *= inv; probs[t * 8 + e] = l[e]; }
        int i1 = 0; float v1 = l[0];
        #pragma unroll
        for (int e = 1; e < 8; e++) if (l[e] > v1) { v1 = l[e]; i1 = e; }
        int i2 = -1; float v2 = -1.f;
        #pragma unroll
        for (int e = 0; e < 8; e++) if (e != i1 && l[e] > v2) { v2 = l[e]; i2 = e; }
        gatev[2 * t] = v1; gatev[2 * t + 1] = v2;
        gidx[2 * t] = i1;  gidx[2 * t + 1] = i2;
    }
}

// ---------------- routing (warp-ballot prefix scan; 8 warps, 1 per expert) ----------------
__global__ void __launch_bounds__(256) route_kernel(
    const int* __restrict__ gidx, const float* __restrict__ probs,
    int* __restrict__ sl, int* __restrict__ rows, float* __restrict__ auxp)
{
    __shared__ int cnt1[8];
    __shared__ float pr[256 * 8];
    const int tid = threadIdx.x, wid = tid >> 5, lane = tid & 31;
    const uint32_t ltmask = (1u << lane) - 1u;

    // probs.mean partial sums (all 256 threads)
    float lp[8];
    #pragma unroll
    for (int e = 0; e < 8; e++) lp[e] = 0.f;
    for (int i = tid; i < NTOK; i += 256) {
        const float4* p = (const float4*)(probs + i * 8);
        float4 p0 = p[0], p1 = p[1];
        lp[0] += p0.x; lp[1] += p0.y; lp[2] += p0.z; lp[3] += p0.w;
        lp[4] += p1.x; lp[5] += p1.y; lp[6] += p1.z; lp[7] += p1.w;
    }
    #pragma unroll
    for (int e = 0; e < 8; e++) pr[tid * 8 + e] = lp[e];
    __syncthreads();
    for (int s = 128; s > 0; s >>= 1) {
        if (tid < s)
            #pragma unroll
            for (int e = 0; e < 8; e++) pr[tid * 8 + e] += pr[(tid + s) * 8 + e];
        __syncthreads();
    }

    // first-choice slots: warp e scans tokens 32 at a time
    {
        const int e = wid;
        int c = 0;
        for (int base = 0; base < NTOK; base += 32) {
            int tok = base + lane;
            int m = (gidx[2 * tok] == e);
            uint32_t mask = __ballot_sync(0xffffffffu, m);
            if (m) {
                int pos = c + __popc(mask & ltmask);
                sl[2 * tok] = (pos < CAP) ? pos : -1;
            }
            c += __popc(mask);
        }
        if (lane == 0) cnt1[e] = c;
    }
    __syncthreads();

    // second-choice slots, offset by cnt1[e]
    {
        const int e = wid;
        int c = cnt1[e];
        for (int base = 0; base < NTOK; base += 32) {
            int tok = base + lane;
            int m = (gidx[2 * tok + 1] == e);
            uint32_t mask = __ballot_sync(0xffffffffu, m);
            if (m) {
                int pos = c + __popc(mask & ltmask);
                sl[2 * tok + 1] = (pos < CAP) ? pos : -1;
            }
            c += __popc(mask);
        }
        if (lane == 0) {
            int ru = c; if (ru > CAP) ru = CAP;
            rows[e] = ru;
        }
    }
    __syncthreads();
    if (tid == 0) {
        float a = 0.f;
        for (int e = 0; e < 8; e++)
            a += ((float)cnt1[e] / (float)NTOK) * (pr[e] / (float)NTOK);
        *auxp = 0.01f * 8.0f * a;
    }
}

// ---------------- scatter ----------------
__global__ void __launch_bounds__(256) scatter_kernel(
    const float* __restrict__ x, const int* __restrict__ gidx,
    const int* __restrict__ sl, __nv_bfloat16* __restrict__ bh,
    __nv_bfloat16* __restrict__ bl)
{
    const int t = blockIdx.x, ch = blockIdx.y;
    const int s = sl[2 * t + ch];
    if (s < 0) return;
    const int e = gidx[2 * t + ch];
    float4 v = ((const float4*)(x + (long long)t * DIM))[threadIdx.x];
    size_t base = ((size_t)e * CAP + s) * DIM + threadIdx.x * 4;
    uint32_t h0, l0, h1, l1;
    packsplit(v.x, v.y, h0, l0);
    packsplit(v.z, v.w, h1, l1);
    *(uint32_t*)(bh + base)     = h0;
    *(uint32_t*)(bh + base + 2) = h1;
    *(uint32_t*)(bl + base)     = l0;
    *(uint32_t*)(bl + base + 2) = l1;
}

// ---------------- fused gather + triple layernorm + aux ----------------
__device__ __forceinline__ float block_sum(float v, float* red) {
    int tid = threadIdx.x;
    red[tid] = v; __syncthreads();
    for (int s = 128; s > 0; s >>= 1) {
        if (tid < s) red[tid] += red[tid + s];
        __syncthreads();
    }
    float r = red[0]; __syncthreads();
    return r;
}

__global__ void __launch_bounds__(256) gather_ln3_kernel(
    const float* __restrict__ y, const int* __restrict__ gidx,
    const int* __restrict__ sl, const float* __restrict__ gatev,
    const float* __restrict__ g1, const float* __restrict__ b1,
    const float* __restrict__ g2, const float* __restrict__ b2,
    const float* __restrict__ g3, const float* __restrict__ b3,
    float* __restrict__ out, const float* __restrict__ auxp, long long out_size)
{
    __shared__ float red[256];
    const int t = blockIdx.x, tid = threadIdx.x;

    const float gv1 = gatev[2 * t], gv2 = gatev[2 * t + 1];
    const int s1 = sl[2 * t], s2 = sl[2 * t + 1];
    const int e1 = gidx[2 * t], e2 = gidx[2 * t + 1];
    float4 v = make_float4(0.f, 0.f, 0.f, 0.f);
    if (s1 >= 0) {
        float4 a = ((const float4*)(y + ((size_t)e1 * CAP + s1) * DIM))[tid];
        v.x += gv1 * a.x; v.y += gv1 * a.y; v.z += gv1 * a.z; v.w += gv1 * a.w;
    }
    if (s2 >= 0) {
        float4 a = ((const float4*)(y + ((size_t)e2 * CAP + s2) * DIM))[tid];
        v.x += gv2 * a.x; v.y += gv2 * a.y; v.z += gv2 * a.z; v.w += gv2 * a.w;
    }

    const float* gs[3] = {g1, g2, g3};
    const float* bs[3] = {b1, b2, b3};
    #pragma unroll
    for (int r3 = 0; r3 < 3; r3++) {
        float s = v.x + v.y + v.z + v.w;
        float mean = block_sum(s, red) * (1.0f / DIM);
        float dx = v.x - mean, dy = v.y - mean, dz = v.z - mean, dw = v.w - mean;
        float s2 = dx * dx + dy * dy + dz * dz + dw * dw;
        float var = block_sum(s2, red) * (1.0f / DIM);
        float rstd = rsqrtf(var + LN_EPS);
        float4 gg = ((const float4*)gs[r3])[tid];
        float4 bb = ((const float4*)bs[r3])[tid];
        v.x = dx * rstd * gg.x + bb.x;
        v.y = dy * rstd * gg.y + bb.y;
        v.z = dz * rstd * gg.z + bb.z;
        v.w = dw * rstd * gg.w + bb.w;
    }
    ((float4*)(out + (long long)t * DIM))[tid] = v;
    if (t == 0 && tid == 0 && out_size > (long long)NTOK * DIM)
        out[(long long)NTOK * DIM] = *auxp;
}

// ---------------- launch ----------------
extern "C" void kernel_launch(void* const* d_in, const int* in_sizes, int n_in,
                              void* d_out, int out_size) {
    const float* tgt      = (const float*)d_in[0];
    const float* mem      = (const float*)d_in[1];
    const float* w_qkv_sa = (const float*)d_in[2];
    const float* b_qkv_sa = (const float*)d_in[3];
    const float* w_o_sa   = (const float*)d_in[4];
    const float* b_o_sa   = (const float*)d_in[5];
    const float* w_qkv_ca = (const float*)d_in[6];
    const float* b_qkv_ca = (const float*)d_in[7];
    const float* w_o_ca   = (const float*)d_in[8];
    const float* b_o_ca   = (const float*)d_in[9];
    const float* ln1_g = (const float*)d_in[10];
    const float* ln1_b = (const float*)d_in[11];
    const float* ln2_g = (const float*)d_in[12];
    const float* ln2_b = (const float*)d_in[13];
    const float* ln3_g = (const float*)d_in[14];
    const float* ln3_b = (const float*)d_in[15];
    const float* w_gate = (const float*)d_in[16];
    const float* w1  = (const float*)d_in[17];
    const float* b1e = (const float*)d_in[18];
    const float* w2  = (const float*)d_in[19];
    const float* b2e = (const float*)d_in[20];
    float* out = (float*)d_out;

    float *qkv, *qca, *kvca, *x2, *probs, *gatev, *ybuf, *auxp;
    int *gidx, *sl, *rows;
    __nv_bfloat16 *tgt_h, *tgt_l, *mem_h, *mem_l, *att_h, *att_l, *x1_h, *x1_l;
    __nv_bfloat16 *buf_h, *buf_l, *hb_h, *hb_l;
    __nv_bfloat16 *wqsa_h, *wqsa_l, *wosa_h, *wosa_l, *wqca_h, *wqca_l, *woca_h, *woca_l;
    __nv_bfloat16 *w1s_h, *w1s_l, *w2s_h, *w2s_l;

    cudaGetSymbolAddress((void**)&qkv,  g_qkv);
    cudaGetSymbolAddress((void**)&qca,  g_qca);
    cudaGetSymbolAddress((void**)&kvca, g_kvca);
    cudaGetSymbolAddress((void**)&x2,   g_x2);
    cudaGetSymbolAddress((void**)&probs,g_probs);
    cudaGetSymbolAddress((void**)&gatev,g_gatev);
    cudaGetSymbolAddress((void**)&gidx, g_gidx);
    cudaGetSymbolAddress((void**)&sl,   g_sl);
    cudaGetSymbolAddress((void**)&rows, g_rows);
    cudaGetSymbolAddress((void**)&auxp, g_aux);
    cudaGetSymbolAddress((void**)&ybuf, g_y);
    cudaGetSymbolAddress((void**)&tgt_h, g_tgt_h); cudaGetSymbolAddress((void**)&tgt_l, g_tgt_l);
    cudaGetSymbolAddress((void**)&mem_h, g_mem_h); cudaGetSymbolAddress((void**)&mem_l, g_mem_l);
    cudaGetSymbolAddress((void**)&att_h, g_att_h); cudaGetSymbolAddress((void**)&att_l, g_att_l);
    cudaGetSymbolAddress((void**)&x1_h,  g_x1_h);  cudaGetSymbolAddress((void**)&x1_l,  g_x1_l);
    cudaGetSymbolAddress((void**)&buf_h, g_buf_h); cudaGetSymbolAddress((void**)&buf_l, g_buf_l);
    cudaGetSymbolAddress((void**)&hb_h,  g_hb_h);  cudaGetSymbolAddress((void**)&hb_l,  g_hb_l);
    cudaGetSymbolAddress((void**)&wqsa_h, g_wqsa_h); cudaGetSymbolAddress((void**)&wqsa_l, g_wqsa_l);
    cudaGetSymbolAddress((void**)&wosa_h, g_wosa_h); cudaGetSymbolAddress((void**)&wosa_l, g_wosa_l);
    cudaGetSymbolAddress((void**)&wqca_h, g_wqca_h); cudaGetSymbolAddress((void**)&wqca_l, g_wqca_l);
    cudaGetSymbolAddress((void**)&woca_h, g_woca_h); cudaGetSymbolAddress((void**)&woca_l, g_woca_l);
    cudaGetSymbolAddress((void**)&w1s_h, g_w1s_h); cudaGetSymbolAddress((void**)&w1s_l, g_w1s_l);
    cudaGetSymbolAddress((void**)&w2s_h, g_w2s_h); cudaGetSymbolAddress((void**)&w2s_l, g_w2s_l);

    cudaFuncSetAttribute(fa_kernel, cudaFuncAttributeMaxDynamicSharedMemorySize, FA_SMEM);
    cudaFuncSetAttribute(mmagemm_kernel<0,0,0>, cudaFuncAttributeMaxDynamicSharedMemorySize, GEMM_SMEM);
    cudaFuncSetAttribute(mmagemm_kernel<0,0,1>, cudaFuncAttributeMaxDynamicSharedMemorySize, GEMM_SMEM);
    cudaFuncSetAttribute(mmagemm_kernel<1,1,1>, cudaFuncAttributeMaxDynamicSharedMemorySize, GEMM_SMEM);
    cudaFuncSetAttribute(mmagemm_kernel<1,0,0>, cudaFuncAttributeMaxDynamicSharedMemorySize, GEMM_SMEM);

    // ---- conversions ----
    split8_kernel<<<(3*DIM*DIM/8 + 255)/256, 256>>>((const float4*)w_qkv_sa, (uint4*)wqsa_h, (uint4*)wqsa_l, 3*DIM*DIM/8);
    split8_kernel<<<(DIM*DIM/8 + 255)/256, 256>>>((const float4*)w_o_sa, (uint4*)wosa_h, (uint4*)wosa_l, DIM*DIM/8);
    split8_kernel<<<(3*DIM*DIM/8 + 255)/256, 256>>>((const float4*)w_qkv_ca, (uint4*)wqca_h, (uint4*)wqca_l, 3*DIM*DIM/8);
    split8_kernel<<<(DIM*DIM/8 + 255)/256, 256>>>((const float4*)w_o_ca, (uint4*)woca_h, (uint4*)woca_l, DIM*DIM/8);
    split8_kernel<<<(int)((size_t)NE*DIM*DFF/8 + 255)/256, 256>>>((const float4*)w1, (uint4*)w1s_h, (uint4*)w1s_l, (int)((size_t)NE*DIM*DFF/8));
    split8_kernel<<<(int)((size_t)NE*DIM*DFF/8 + 255)/256, 256>>>((const float4*)w2, (uint4*)w2s_h, (uint4*)w2s_l, (int)((size_t)NE*DIM*DFF/8));
    split8_kernel<<<(NTOK*DIM/8 + 255)/256, 256>>>((const float4*)tgt, (uint4*)tgt_h, (uint4*)tgt_l, NTOK*DIM/8);
    split8_kernel<<<(NTOK*DIM/8 + 255)/256, 256>>>((const float4*)mem, (uint4*)mem_h, (uint4*)mem_l, NTOK*DIM/8);

    // 1) SA qkv projection (NT)
    mmagemm_kernel<0,0,0><<<dim3(3072/128, NTOK/128, 1), 256, GEMM_SMEM>>>(
        tgt_h, tgt_l, wqsa_h, wqsa_l, b_qkv_sa, qkv, nullptr, nullptr,
        DIM, DIM, 3*DIM, 0, 0, 0, 0, nullptr);

    // 2) self-attention
    fa_kernel<<<dim3(SQ/128, NH, BB), 256, FA_SMEM>>>(
        qkv, 3*DIM, qkv + DIM, 3*DIM, qkv + 2*DIM, 3*DIM, att_h, att_l, DIM, SQ);

    // 3) SA output projection -> x1 split
    mmagemm_kernel<0,0,1><<<dim3(DIM/128, NTOK/128, 1), 256, GEMM_SMEM>>>(
        att_h, att_l, wosa_h, wosa_l, b_o_sa, nullptr, x1_h, x1_l,
        DIM, DIM, DIM, 0, 0, 0, 0, nullptr);

    // 4) CA q projection
    mmagemm_kernel<0,0,0><<<dim3(DIM/128, NTOK/128, 1), 256, GEMM_SMEM>>>(
        x1_h, x1_l, wqca_h, wqca_l, b_qkv_ca, qca, nullptr, nullptr,
        DIM, DIM, DIM, 0, 0, 0, 0, nullptr);

    // 5) CA k,v projection from memory
    mmagemm_kernel<0,0,0><<<dim3(2*DIM/128, NTOK/128, 1), 256, GEMM_SMEM>>>(
        mem_h, mem_l, wqca_h + (size_t)DIM*DIM, wqca_l + (size_t)DIM*DIM,
        b_qkv_ca + DIM, kvca, nullptr, nullptr,
        DIM, DIM, 2*DIM, 0, 0, 0, 0, nullptr);

    // 6) cross-attention
    fa_kernel<<<dim3(SQ/128, NH, BB), 256, FA_SMEM>>>(
        qca, DIM, kvca, 2*DIM, kvca + DIM, 2*DIM, att_h, att_l, DIM, SQ);

    // 7) CA output projection -> fp32 x2
    mmagemm_kernel<0,0,0><<<dim3(DIM/128, NTOK/128, 1), 256, GEMM_SMEM>>>(
        att_h, att_l, woca_h, woca_l, b_o_ca, x2, nullptr, nullptr,
        DIM, DIM, DIM, 0, 0, 0, 0, nullptr);

    // 8-9) gating + routing
    gate_kernel<<<NTOK, 128>>>(x2, w_gate, probs, gatev, gidx);
    route_kernel<<<1, 256>>>(gidx, probs, sl, rows, auxp);

    // 10) scatter
    scatter_kernel<<<dim3(NTOK, 2), 256>>>(x2, gidx, sl, buf_h, buf_l);

    // 11) expert FFN layer 1 (B NN, +GELU, split-out), row-skip
    mmagemm_kernel<1,1,1><<<dim3(DFF/128, CAP/128, NE), 256, GEMM_SMEM>>>(
        buf_h, buf_l, w1s_h, w1s_l, b1e, nullptr, hb_h, hb_l,
        DIM, DFF, DFF, (long long)CAP*DIM, (long long)DIM*DFF, DFF, (long long)CAP*DFF, rows);

    // 12) expert FFN layer 2 (B NN) -> fp32 ybuf, row-skip
    mmagemm_kernel<1,0,0><<<dim3(DIM/128, CAP/128, NE), 256, GEMM_SMEM>>>(
        hb_h, hb_l, w2s_h, w2s_l, b2e, ybuf, nullptr, nullptr,
        DFF, DIM, DIM, (long long)CAP*DFF, (long long)DFF*DIM, DIM, (long long)CAP*DIM, rows);

    // 13-14) fused gather + triple layernorm + aux
    gather_ln3_kernel<<<NTOK, 256>>>(ybuf, gidx, sl, gatev,
                                     ln1_g, ln1_b, ln2_g, ln2_b, ln3_g, ln3_b,
                                     out, auxp, (long long)out_size);
}

// round 17
// speedup vs baseline: 2.6438x; 1.0353x over previous
#include <cuda_runtime.h>
#include <cuda_bf16.h>
#include <math.h>
#include <stdint.h>

// ---------------- problem constants ----------------
#define SQ   2048
#define BB   2
#define DIM  1024
#define NH   16
#define HD   64
#define NTOK 4096
#define NE   8
#define DFF  4096
#define CAP  2048
#define LN_EPS 1e-5f

// ---------------- scratch (device globals) ----------------
__device__ __nv_bfloat16 g_tgt_h[NTOK * DIM], g_tgt_l[NTOK * DIM];
__device__ __nv_bfloat16 g_mem_h[NTOK * DIM], g_mem_l[NTOK * DIM];
__device__ __nv_bfloat16 g_att_h[NTOK * DIM], g_att_l[NTOK * DIM];
__device__ __nv_bfloat16 g_x1_h [NTOK * DIM], g_x1_l [NTOK * DIM];
__device__ __nv_bfloat16 g_qkv_h[NTOK * 3 * DIM], g_qkv_l[NTOK * 3 * DIM];
__device__ __nv_bfloat16 g_qca_h[NTOK * DIM],     g_qca_l[NTOK * DIM];
__device__ __nv_bfloat16 g_kvca_h[NTOK * 2 * DIM], g_kvca_l[NTOK * 2 * DIM];
__device__ __nv_bfloat16 g_buf_h[NE * CAP * DIM], g_buf_l[NE * CAP * DIM];
__device__ __nv_bfloat16 g_hb_h[(size_t)NE * CAP * DFF], g_hb_l[(size_t)NE * CAP * DFF];
__device__ __nv_bfloat16 g_wqsa_h[3 * DIM * DIM], g_wqsa_l[3 * DIM * DIM];
__device__ __nv_bfloat16 g_wosa_h[DIM * DIM],     g_wosa_l[DIM * DIM];
__device__ __nv_bfloat16 g_wqca_h[3 * DIM * DIM], g_wqca_l[3 * DIM * DIM];
__device__ __nv_bfloat16 g_woca_h[DIM * DIM],     g_woca_l[DIM * DIM];
__device__ __nv_bfloat16 g_w1s_h[(size_t)NE * DIM * DFF], g_w1s_l[(size_t)NE * DIM * DFF];
__device__ __nv_bfloat16 g_w2s_h[(size_t)NE * DIM * DFF], g_w2s_l[(size_t)NE * DIM * DFF];
__device__ float g_x2  [NTOK * DIM];
__device__ float g_probs[NTOK * NE];
__device__ float g_gatev[NTOK * 2];
__device__ int   g_gidx[NTOK * 2];
__device__ int   g_sl  [NTOK * 2];
__device__ int   g_rows[NE];
__device__ float g_aux;
__device__ float g_y [NE * CAP * DIM];

__device__ __forceinline__ float gelu_exact(float x) {
    return 0.5f * x * (1.0f + erff(x * 0.70710678118654752440f));
}
__device__ __forceinline__ void split2(float v, __nv_bfloat16& h, __nv_bfloat16& l) {
    h = __float2bfloat16(v);
    l = __float2bfloat16(v - __bfloat162float(h));
}
__device__ __forceinline__ uint32_t smem_u32(const void* p) {
    uint32_t a;
    asm("{ .reg .u64 t; cvta.to.shared.u64 t, %1; cvt.u32.u64 %0, t; }" : "=r"(a) : "l"(p));
    return a;
}
__device__ __forceinline__ uint32_t packh2(__nv_bfloat16 a, __nv_bfloat16 b) {
    __nv_bfloat162 t = __halves2bfloat162(a, b);
    return *(uint32_t*)&t;
}
__device__ __forceinline__ void packsplit(float a, float b, uint32_t& hi, uint32_t& lo) {
    __nv_bfloat16 ha, la, hb, lb;
    split2(a, ha, la); split2(b, hb, lb);
    hi = packh2(ha, hb); lo = packh2(la, lb);
}
#define CP_ASYNC16(s, g) \
    asm volatile("cp.async.cg.shared.global [%0], [%1], 16;" :: "r"(s), "l"(g))
#define CP_COMMIT() asm volatile("cp.async.commit_group;" ::: "memory")

__device__ __forceinline__ void mma16816(float* d, const uint32_t* a, const uint32_t* b) {
    asm volatile(
        "mma.sync.aligned.m16n8k16.row.col.f32.bf16.bf16.f32 "
        "{%0,%1,%2,%3}, {%4,%5,%6,%7}, {%8,%9}, {%0,%1,%2,%3};"
        : "+f"(d[0]), "+f"(d[1]), "+f"(d[2]), "+f"(d[3])
        : "r"(a[0]), "r"(a[1]), "r"(a[2]), "r"(a[3]), "r"(b[0]), "r"(b[1]));
}
#define LDSM_X4(r0, r1, r2, r3, addr) \
    asm volatile("ldmatrix.sync.aligned.m8n8.x4.shared.b16 {%0,%1,%2,%3}, [%4];" \
        : "=r"(r0), "=r"(r1), "=r"(r2), "=r"(r3) : "r"(addr))
#define LDSM_X4_T(r0, r1, r2, r3, addr) \
    asm volatile("ldmatrix.sync.aligned.m8n8.x4.trans.shared.b16 {%0,%1,%2,%3}, [%4];" \
        : "=r"(r0), "=r"(r1), "=r"(r2), "=r"(r3) : "r"(addr))

// ---------------- bf16 mma GEMM, 3-term hi/lo split ----------------
// BNN=0: C[r,c] = sum_k A[r,k]*B[c,k]   (B [N][K], row stride ldb)
// BNN=1: C[r,c] = sum_k A[r,k]*B[k,c]   (B [K][N], row stride ldb)
#define TPAD   40
#define TPADB  136
#define TILE_B (128 * TPAD * 2)
#define STAGE_B (4 * TILE_B)
#define GEMM_SMEM (2 * STAGE_B)

template<int BNN, int DOGELU, int SPLITOUT>
__global__ void __launch_bounds__(256, 2) mmagemm_kernel(
    const __nv_bfloat16* __restrict__ Ah, const __nv_bfloat16* __restrict__ Al,
    const __nv_bfloat16* __restrict__ Bh, const __nv_bfloat16* __restrict__ Bl,
    const float* __restrict__ bias, float* __restrict__ C,
    __nv_bfloat16* __restrict__ Ch, __nv_bfloat16* __restrict__ Cl,
    int K, int ldb, int ldc,
    long long sA, long long sB, long long sBias, long long sC,
    const int* __restrict__ rows_used)
{
    extern __shared__ char smem[];
    const int z = blockIdx.z;
    if (rows_used && (int)(blockIdx.y * 128) >= rows_used[z]) return;

    const int tid = threadIdx.x, wid = tid >> 5, lane = tid & 31;
    const int wm = wid & 1, wn = wid >> 1;
    const long long rowBase = (long long)blockIdx.y * 128;
    const int colBase = blockIdx.x * 128;
    Ah += z * sA; Al += z * sA; Bh += z * sB; Bl += z * sB; bias += z * sBias;

    const __nv_bfloat16* srcA0 = Ah + rowBase * K;
    const __nv_bfloat16* srcA1 = Al + rowBase * K;
    const __nv_bfloat16* srcB0;
    const __nv_bfloat16* srcB1;
    if (BNN) { srcB0 = Bh + colBase; srcB1 = Bl + colBase; }
    else     { srcB0 = Bh + (long long)colBase * ldb; srcB1 = Bl + (long long)colBase * ldb; }

    const uint32_t sbase = smem_u32(smem);
    const int NC = K >> 5;

    auto prefetch = [&](int st, int kc) {
        const int koff = kc * 32;
        const uint32_t stb = sbase + st * STAGE_B;
        {
            const __nv_bfloat16* sa[2] = {srcA0 + koff, srcA1 + koff};
            #pragma unroll
            for (int bi = 0; bi < 2; bi++) {
                const uint32_t tb = stb + bi * TILE_B;
                #pragma unroll
                for (int it = 0; it < 2; it++) {
                    int idx = it * 256 + tid;
                    int row = idx >> 2, c = idx & 3;
                    CP_ASYNC16(tb + row * (TPAD * 2) + c * 16,
                               (const void*)(sa[bi] + (long long)row * K + c * 8));
                }
            }
        }
        if (BNN) {
            const __nv_bfloat16* sb2[2] = {srcB0, srcB1};
            #pragma unroll
            for (int bi = 0; bi < 2; bi++) {
                const uint32_t tb = stb + (2 + bi) * TILE_B;
                #pragma unroll
                for (int it = 0; it < 2; it++) {
                    int idx = it * 256 + tid;
                    int row = idx >> 4, c = idx & 15;
                    CP_ASYNC16(tb + row * (TPADB * 2) + c * 16,
                               (const void*)(sb2[bi] + (long long)(koff + row) * ldb + c * 8));
                }
            }
        } else {
            const __nv_bfloat16* sb2[2] = {srcB0 + koff, srcB1 + koff};
            #pragma unroll
            for (int bi = 0; bi < 2; bi++) {
                const uint32_t tb = stb + (2 + bi) * TILE_B;
                #pragma unroll
                for (int it = 0; it < 2; it++) {
                    int idx = it * 256 + tid;
                    int row = idx >> 2, c = idx & 3;
                    CP_ASYNC16(tb + row * (TPAD * 2) + c * 16,
                               (const void*)(sb2[bi] + (long long)row * ldb + c * 8));
                }
            }
        }
        CP_COMMIT();
    };

    float acc[4][4][4];
    #pragma unroll
    for (int i = 0; i < 4; i++)
        #pragma unroll
        for (int j = 0; j < 4; j++)
            #pragma unroll
            for (int r = 0; r < 4; r++) acc[i][j][r] = 0.f;

    const uint32_t lmoff =
        (uint32_t)(((lane & 7) + ((lane >> 3) & 1) * 8) * (TPAD * 2) + (lane >> 4) * 16);
    const uint32_t lmT =
        (uint32_t)(((lane & 7) + ((lane >> 4) & 1) * 8) * (TPADB * 2) + ((lane >> 3) & 1) * 16);

    prefetch(0, 0);

    for (int ic = 0; ic < NC; ic++) {
        const int p = ic & 1;
        if (ic + 1 < NC) {
            prefetch(p ^ 1, ic + 1);
            asm volatile("cp.async.wait_group 1;" ::: "memory");
        } else {
            asm volatile("cp.async.wait_group 0;" ::: "memory");
        }
        __syncthreads();

        const uint32_t stp = sbase + p * STAGE_B;
        const uint32_t aHb = stp +          wm * 64 * (TPAD * 2) + lmoff;
        const uint32_t aLb = stp + TILE_B + wm * 64 * (TPAD * 2) + lmoff;
        uint32_t bHb, bLb;
        if (BNN) {
            bHb = stp + 2 * TILE_B + wn * 64 + lmT;
            bLb = stp + 3 * TILE_B + wn * 64 + lmT;
        } else {
            bHb = stp + 2 * TILE_B + wn * 32 * (TPAD * 2) + lmoff;
            bLb = stp + 3 * TILE_B + wn * 32 * (TPAD * 2) + lmoff;
        }

        uint32_t afr[4][4];
        uint32_t bfh[4][2], bfl[4][2];

        #pragma unroll
        for (int ks = 0; ks < 2; ks++) {
            const uint32_t kb = ks * 32;

            if (BNN) {
                const uint32_t kbn = ks * 16 * (TPADB * 2);
                #pragma unroll
                for (int jp = 0; jp < 2; jp++) {
                    uint32_t r0, r1, r2, r3;
                    LDSM_X4_T(r0, r1, r2, r3, bHb + kbn + jp * 32);
                    bfh[2 * jp][0] = r0; bfh[2 * jp][1] = r2;
                    bfh[2 * jp + 1][0] = r1; bfh[2 * jp + 1][1] = r3;
                    LDSM_X4_T(r0, r1, r2, r3, bLb + kbn + jp * 32);
                    bfl[2 * jp][0] = r0; bfl[2 * jp][1] = r2;
                    bfl[2 * jp + 1][0] = r1; bfl[2 * jp + 1][1] = r3;
                }
            } else {
                #pragma unroll
                for (int pr = 0; pr < 2; pr++) {
                    LDSM_X4(bfh[pr * 2][0], bfh[pr * 2 + 1][0],
                            bfh[pr * 2][1], bfh[pr * 2 + 1][1],
                            bHb + pr * 16 * (TPAD * 2) + kb);
                    LDSM_X4(bfl[pr * 2][0], bfl[pr * 2 + 1][0],
                            bfl[pr * 2][1], bfl[pr * 2 + 1][1],
                            bLb + pr * 16 * (TPAD * 2) + kb);
                }
            }

            #pragma unroll
            for (int i = 0; i < 4; i++)
                LDSM_X4(afr[i][0], afr[i][1], afr[i][2], afr[i][3],
                        aHb + i * 16 * (TPAD * 2) + kb);
            #pragma unroll
            for (int i = 0; i < 4; i++)
                #pragma unroll
                for (int j = 0; j < 4; j++) {
                    mma16816(acc[i][j], afr[i], bfh[j]);
                    mma16816(acc[i][j], afr[i], bfl[j]);
                }

            #pragma unroll
            for (int i = 0; i < 4; i++)
                LDSM_X4(afr[i][0], afr[i][1], afr[i][2], afr[i][3],
                        aLb + i * 16 * (TPAD * 2) + kb);
            #pragma unroll
            for (int i = 0; i < 4; i++)
                #pragma unroll
                for (int j = 0; j < 4; j++)
                    mma16816(acc[i][j], afr[i], bfh[j]);
        }
        __syncthreads();
    }

    const int lr = lane >> 2, lc2 = (lane & 3) * 2;
    #pragma unroll
    for (int i = 0; i < 4; i++) {
        const int r0 = (int)rowBase + wm * 64 + i * 16 + lr;
        #pragma unroll
        for (int j = 0; j < 4; j++) {
            const int col = colBase + wn * 32 + j * 8 + lc2;
            float b0 = bias[col], b1 = bias[col + 1];
            float v0 = acc[i][j][0] + b0, v1 = acc[i][j][1] + b1;
            float v2 = acc[i][j][2] + b0, v3 = acc[i][j][3] + b1;
            if (DOGELU) {
                v0 = gelu_exact(v0); v1 = gelu_exact(v1);
                v2 = gelu_exact(v2); v3 = gelu_exact(v3);
            }
            if (SPLITOUT == 0) {
                float* c0 = C + ((long long)r0 * ldc + col) + z * sC;
                float* c1 = C + ((long long)(r0 + 8) * ldc + col) + z * sC;
                c0[0] = v0; c0[1] = v1;
                c1[0] = v2; c1[1] = v3;
            } else {
                long long o0 = (long long)r0 * ldc + col + z * sC;
                long long o1 = (long long)(r0 + 8) * ldc + col + z * sC;
                uint32_t h0, l0, h1, l1;
                packsplit(v0, v1, h0, l0);
                packsplit(v2, v3, h1, l1);
                *(uint32_t*)(Ch + o0) = h0;
                *(uint32_t*)(Cl + o0) = l0;
                *(uint32_t*)(Ch + o1) = h1;
                *(uint32_t*)(Cl + o1) = l1;
            }
        }
    }
}

// ---------------- fp32 -> bf16 hi/lo split, 8 elems/thread ----------------
__global__ void __launch_bounds__(256) split8_kernel(
    const float4* __restrict__ x, uint4* __restrict__ h,
    uint4* __restrict__ l, int n8)
{
    int i = blockIdx.x * 256 + threadIdx.x;
    if (i >= n8) return;
    float4 a = x[2 * i], b = x[2 * i + 1];
    uint4 hv, lv;
    packsplit(a.x, a.y, hv.x, lv.x);
    packsplit(a.z, a.w, hv.y, lv.y);
    packsplit(b.x, b.y, hv.z, lv.z);
    packsplit(b.z, b.w, hv.w, lv.w);
    h[i] = hv; l[i] = lv;
}

// ---------------- mma flash attention (pre-split bf16 in, Br=128, Bc=64, hd=64) ----
#define FA_TP   72
#define FA_SMEM 73728

__global__ void __launch_bounds__(256, 2) fa_kernel(
    const __nv_bfloat16* __restrict__ Qhg, const __nv_bfloat16* __restrict__ Qlg, int ldq,
    const __nv_bfloat16* __restrict__ Khg, const __nv_bfloat16* __restrict__ Klg, int ldk,
    const __nv_bfloat16* __restrict__ Vhg, const __nv_bfloat16* __restrict__ Vlg, int ldv,
    __nv_bfloat16* __restrict__ Oh, __nv_bfloat16* __restrict__ Ol,
    int ldo, int Skv)
{
    extern __shared__ __nv_bfloat16 sb[];
    __nv_bfloat16* Qh = sb;
    __nv_bfloat16* Ql = sb + 9216;
    __nv_bfloat16* Kh = sb + 18432;
    __nv_bfloat16* Kl = sb + 23040;
    __nv_bfloat16* Vh = sb + 27648;
    __nv_bfloat16* Vl = sb + 32256;

    const int b = blockIdx.z, h = blockIdx.y, qt = blockIdx.x;
    const int tid = threadIdx.x, wid = tid >> 5, lane = tid & 31;
    const __nv_bfloat16* Qhp = Qhg + h * HD;
    const __nv_bfloat16* Qlp = Qlg + h * HD;
    const __nv_bfloat16* Khp = Khg + h * HD;
    const __nv_bfloat16* Klp = Klg + h * HD;
    const __nv_bfloat16* Vhp = Vhg + h * HD;
    const __nv_bfloat16* Vlp = Vlg + h * HD;

    const uint32_t qbase = smem_u32(Qh);
    const uint32_t lbase = smem_u32(Ql);
    const uint32_t kbase = smem_u32(Kh);
    const uint32_t klbase = smem_u32(Kl);
    const uint32_t vbase = smem_u32(Vh);
    const uint32_t vlbase = smem_u32(Vl);

    // load Q once (cp.async): 2 tiles x 128 rows x 8 chunks
    {
        const __nv_bfloat16* src[2] = {Qhp, Qlp};
        const uint32_t dst[2] = {qbase, lbase};
        #pragma unroll
        for (int bi = 0; bi < 2; bi++) {
            #pragma unroll
            for (int it = 0; it < 4; it++) {
                int idx = it * 256 + tid;
                int r = idx >> 3, c = idx & 7;
                long long tok = (long long)(qt * 128 + r) * BB + b;
                CP_ASYNC16(dst[bi] + r * (FA_TP * 2) + c * 16,
                           (const void*)(src[bi] + tok * ldq + c * 8));
            }
        }
        CP_COMMIT();
    }

    float o[8][4];
    #pragma unroll
    for (int j = 0; j < 8; j++)
        #pragma unroll
        for (int r = 0; r < 4; r++) o[j][r] = 0.f;
    float m0 = -1e30f, m1 = -1e30f, l0 = 0.f, l1 = 0.f;

    const uint32_t lmA =
        (uint32_t)(((lane & 7) + ((lane >> 3) & 1) * 8) * (FA_TP * 2) + (lane >> 4) * 16);
    const uint32_t lmT =
        (uint32_t)(((lane & 7) + ((lane >> 4) & 1) * 8) * (FA_TP * 2) + ((lane >> 3) & 1) * 16);
    const uint32_t qwoff = (uint32_t)(wid * 16) * (FA_TP * 2);

    const int nkt = Skv >> 6;
    for (int kt = 0; kt < nkt; kt++) {
        __syncthreads();
        // load K/V h+l tiles (cp.async): 4 tiles x 64 rows x 8 chunks = 2048 chunks
        {
            const __nv_bfloat16* src[4] = {Khp, Klp, Vhp, Vlp};
            const int lds[4] = {ldk, ldk, ldv, ldv};
            const uint32_t dst[4] = {kbase, klbase, vbase, vlbase};
            #pragma unroll
            for (int bi = 0; bi < 4; bi++) {
                #pragma unroll
                for (int it = 0; it < 2; it++) {
                    int idx = it * 256 + tid;
                    int r = idx >> 3, c = idx & 7;
                    long long tok = (long long)(kt * 64 + r) * BB + b;
                    CP_ASYNC16(dst[bi] + r * (FA_TP * 2) + c * 16,
                               (const void*)(src[bi] + tok * (long long)lds[bi] + c * 8));
                }
            }
            CP_COMMIT();
        }
        asm volatile("cp.async.wait_group 0;" ::: "memory");
        __syncthreads();

        float s[8][4];
        #pragma unroll
        for (int j = 0; j < 8; j++)
            #pragma unroll
            for (int r = 0; r < 4; r++) s[j][r] = 0.f;

        #pragma unroll
        for (int c = 0; c < 4; c++) {
            const uint32_t kb32 = c * 32;
            uint32_t aH[4], aL[4];
            LDSM_X4(aH[0], aH[1], aH[2], aH[3], qbase + qwoff + lmA + kb32);
            LDSM_X4(aL[0], aL[1], aL[2], aL[3], lbase + qwoff + lmA + kb32);
            #pragma unroll
            for (int jp = 0; jp < 4; jp++) {
                uint32_t r0, r1, r2, r3;
                LDSM_X4(r0, r1, r2, r3,
                        kbase + jp * 16 * (FA_TP * 2) + lmA + kb32);
                uint32_t bj[2]  = {r0, r2};
                uint32_t bj1[2] = {r1, r3};
                mma16816(s[2 * jp],     aH, bj);
                mma16816(s[2 * jp + 1], aH, bj1);
                mma16816(s[2 * jp],     aL, bj);
                mma16816(s[2 * jp + 1], aL, bj1);
                LDSM_X4(r0, r1, r2, r3,
                        klbase + jp * 16 * (FA_TP * 2) + lmA + kb32);
                uint32_t cj[2]  = {r0, r2};
                uint32_t cj1[2] = {r1, r3};
                mma16816(s[2 * jp],     aH, cj);
                mma16816(s[2 * jp + 1], aH, cj1);
            }
        }
        // apply 1/sqrt(hd) scale to raw scores
        #pragma unroll
        for (int j = 0; j < 8; j++) {
            s[j][0] *= 0.125f; s[j][1] *= 0.125f;
            s[j][2] *= 0.125f; s[j][3] *= 0.125f;
        }

        float mx0 = -1e30f, mx1 = -1e30f;
        #pragma unroll
        for (int j = 0; j < 8; j++) {
            mx0 = fmaxf(mx0, fmaxf(s[j][0], s[j][1]));
            mx1 = fmaxf(mx1, fmaxf(s[j][2], s[j][3]));
        }
        mx0 = fmaxf(mx0, __shfl_xor_sync(0xffffffffu, mx0, 1));
        mx0 = fmaxf(mx0, __shfl_xor_sync(0xffffffffu, mx0, 2));
        mx1 = fmaxf(mx1, __shfl_xor_sync(0xffffffffu, mx1, 1));
        mx1 = fmaxf(mx1, __shfl_xor_sync(0xffffffffu, mx1, 2));
        float mn0 = fmaxf(m0, mx0), mn1 = fmaxf(m1, mx1);
        float sc0 = __expf(m0 - mn0), sc1 = __expf(m1 - mn1);
        m0 = mn0; m1 = mn1;
        float rs0 = 0.f, rs1 = 0.f;
        #pragma unroll
        for (int j = 0; j < 8; j++) {
            s[j][0] = __expf(s[j][0] - m0);
            s[j][1] = __expf(s[j][1] - m0);
            s[j][2] = __expf(s[j][2] - m1);
            s[j][3] = __expf(s[j][3] - m1);
            rs0 += s[j][0] + s[j][1];
            rs1 += s[j][2] + s[j][3];
        }
        rs0 += __shfl_xor_sync(0xffffffffu, rs0, 1);
        rs0 += __shfl_xor_sync(0xffffffffu, rs0, 2);
        rs1 += __shfl_xor_sync(0xffffffffu, rs1, 1);
        rs1 += __shfl_xor_sync(0xffffffffu, rs1, 2);
        l0 = l0 * sc0 + rs0;
        l1 = l1 * sc1 + rs1;
        #pragma unroll
        for (int j = 0; j < 8; j++) {
            o[j][0] *= sc0; o[j][1] *= sc0;
            o[j][2] *= sc1; o[j][3] *= sc1;
        }

        #pragma unroll
        for (int c = 0; c < 4; c++) {
            uint32_t ph[4], pl[4];
            packsplit(s[2 * c][0],     s[2 * c][1],     ph[0], pl[0]);
            packsplit(s[2 * c][2],     s[2 * c][3],     ph[1], pl[1]);
            packsplit(s[2 * c + 1][0], s[2 * c + 1][1], ph[2], pl[2]);
            packsplit(s[2 * c + 1][2], s[2 * c + 1][3], ph[3], pl[3]);
            const uint32_t rowoff = (uint32_t)(c * 16) * (FA_TP * 2);
            #pragma unroll
            for (int jp = 0; jp < 4; jp++) {
                uint32_t r0, r1, r2, r3;
                LDSM_X4_T(r0, r1, r2, r3,
                          vbase + rowoff + lmT + jp * 32);
                uint32_t bj[2]  = {r0, r2};
                uint32_t bj1[2] = {r1, r3};
                mma16816(o[2 * jp],     ph, bj);
                mma16816(o[2 * jp + 1], ph, bj1);
                mma16816(o[2 * jp],     pl, bj);
                mma16816(o[2 * jp + 1], pl, bj1);
                LDSM_X4_T(r0, r1, r2, r3,
                          vlbase + rowoff + lmT + jp * 32);
                uint32_t cj[2]  = {r0, r2};
                uint32_t cj1[2] = {r1, r3};
                mma16816(o[2 * jp],     ph, cj);
                mma16816(o[2 * jp + 1], ph, cj1);
            }
        }
    }

    const float il0 = 1.0f / l0, il1 = 1.0f / l1;
    const int r0 = qt * 128 + wid * 16 + (lane >> 2);
    const long long tok0 = (long long)r0 * BB + b;
    const long long tok1 = (long long)(r0 + 8) * BB + b;
    #pragma unroll
    for (int j = 0; j < 8; j++) {
        const int col = h * HD + j * 8 + (lane & 3) * 2;
        uint32_t h0, l0v, h1, l1v;
        packsplit(o[j][0] * il0, o[j][1] * il0, h0, l0v);
        packsplit(o[j][2] * il1, o[j][3] * il1, h1, l1v);
        *(uint32_t*)(Oh + tok0 * ldo + col) = h0;
        *(uint32_t*)(Ol + tok0 * ldo + col) = l0v;
        *(uint32_t*)(Oh + tok1 * ldo + col) = h1;
        *(uint32_t*)(Ol + tok1 * ldo + col) = l1v;
    }
}

// ---------------- gating ----------------
__global__ void __launch_bounds__(128) gate_kernel(
    const float* __restrict__ x, const float* __restrict__ wg,
    float* __restrict__ probs, float* __restrict__ gatev, int* __restrict__ gidx)
{
    const int t = blockIdx.x, tid = threadIdx.x;
    __shared__ float red[128][8];
    float acc[8];
    #pragma unroll
    for (int e = 0; e < 8; e++) acc[e] = 0.f;
    for (int d = tid; d < DIM; d += 128) {
        float xv = x[(long long)t * DIM + d];
        const float4* w = (const float4*)(wg + d * 8);
        float4 w0 = w[0], w1 = w[1];
        acc[0] += xv * w0.x; acc[1] += xv * w0.y; acc[2] += xv * w0.z; acc[3] += xv * w0.w;
        acc[4] += xv * w1.x; acc[5] += xv * w1.y; acc[6] += xv * w1.z; acc[7] += xv * w1.w;
    }
    #pragma unroll
    for (int e = 0; e < 8; e++) red[tid][e] = acc[e];
    __syncthreads();
    for (int s = 64; s > 0; s >>= 1) {
        if (tid < s)
            #pragma unroll
            for (int e = 0; e < 8; e++) red[tid][e] += red[tid + s][e];
        __syncthreads();
    }
    if (tid == 0) {
        float l[8], mx = -1e30f;
        #pragma unroll
        for (int e = 0; e < 8; e++) { l[e] = red[0][e]; mx = fmaxf(mx, l[e]); }
        float sum = 0.f;
        #pragma unroll
        for (int e = 0; e < 8; e++) { l[e] = __expf(l[e] - mx); sum += l[e]; }
        float inv = 1.0f / sum;
        #pragma unroll
        for (int e = 0; e < 8; e++) { l[e] *= inv; probs[t * 8 + e] = l[e]; }
        int i1 = 0; float v1 = l[0];
        #pragma unroll
        for (int e = 1; e < 8; e++) if (l[e] > v1) { v1 = l[e]; i1 = e; }
        int i2 = -1; float v2 = -1.f;
        #pragma unroll
        for (int e = 0; e < 8; e++) if (e != i1 && l[e] > v2) { v2 = l[e]; i2 = e; }
        gatev[2 * t] = v1; gatev[2 * t + 1] = v2;
        gidx[2 * t] = i1;  gidx[2 * t + 1] = i2;
    }
}

// ---------------- routing (warp-ballot prefix scan) ----------------
__global__ void __launch_bounds__(256) route_kernel(
    const int* __restrict__ gidx, const float* __restrict__ probs,
    int* __restrict__ sl, int* __restrict__ rows, float* __restrict__ auxp)
{
    __shared__ int cnt1[8];
    __shared__ float pr[256 * 8];
    const int tid = threadIdx.x, wid = tid >> 5, lane = tid & 31;
    const uint32_t ltmask = (1u << lane) - 1u;

    float lp[8];
    #pragma unroll
    for (int e = 0; e < 8; e++) lp[e] = 0.f;
    for (int i = tid; i < NTOK; i += 256) {
        const float4* p = (const float4*)(probs + i * 8);
        float4 p0 = p[0], p1 = p[1];
        lp[0] += p0.x; lp[1] += p0.y; lp[2] += p0.z; lp[3] += p0.w;
        lp[4] += p1.x; lp[5] += p1.y; lp[6] += p1.z; lp[7] += p1.w;
    }
    #pragma unroll
    for (int e = 0; e < 8; e++) pr[tid * 8 + e] = lp[e];
    __syncthreads();
    for (int s = 128; s > 0; s >>= 1) {
        if (tid < s)
            #pragma unroll
            for (int e = 0; e < 8; e++) pr[tid * 8 + e] += pr[(tid + s) * 8 + e];
        __syncthreads();
    }

    {
        const int e = wid;
        int c = 0;
        for (int base = 0; base < NTOK; base += 32) {
            int tok = base + lane;
            int m = (gidx[2 * tok] == e);
            uint32_t mask = __ballot_sync(0xffffffffu, m);
            if (m) {
                int pos = c + __popc(mask & ltmask);
                sl[2 * tok] = (pos < CAP) ? pos : -1;
            }
            c += __popc(mask);
        }
        if (lane == 0) cnt1[e] = c;
    }
    __syncthreads();
    {
        const int e = wid;
        int c = cnt1[e];
        for (int base = 0; base < NTOK; base += 32) {
            int tok = base + lane;
            int m = (gidx[2 * tok + 1] == e);
            uint32_t mask = __ballot_sync(0xffffffffu, m);
            if (m) {
                int pos = c + __popc(mask & ltmask);
                sl[2 * tok + 1] = (pos < CAP) ? pos : -1;
            }
            c += __popc(mask);
        }
        if (lane == 0) {
            int ru = c; if (ru > CAP) ru = CAP;
            rows[e] = ru;
        }
    }
    __syncthreads();
    if (tid == 0) {
        float a = 0.f;
        for (int e = 0; e < 8; e++)
            a += ((float)cnt1[e] / (float)NTOK) * (pr[e] / (float)NTOK);
        *auxp = 0.01f * 8.0f * a;
    }
}

// ---------------- scatter ----------------
__global__ void __launch_bounds__(256) scatter_kernel(
    const float* __restrict__ x, const int* __restrict__ gidx,
    const int* __restrict__ sl, __nv_bfloat16* __restrict__ bh,
    __nv_bfloat16* __restrict__ bl)
{
    const int t = blockIdx.x, ch = blockIdx.y;
    const int s = sl[2 * t + ch];
    if (s < 0) return;
    const int e = gidx[2 * t + ch];
    float4 v = ((const float4*)(x + (long long)t * DIM))[threadIdx.x];
    size_t base = ((size_t)e * CAP + s) * DIM + threadIdx.x * 4;
    uint32_t h0, l0, h1, l1;
    packsplit(v.x, v.y, h0, l0);
    packsplit(v.z, v.w, h1, l1);
    *(uint32_t*)(bh + base)     = h0;
    *(uint32_t*)(bh + base + 2) = h1;
    *(uint32_t*)(bl + base)     = l0;
    *(uint32_t*)(bl + base + 2) = l1;
}

// ---------------- fused gather + triple layernorm + aux ----------------
__device__ __forceinline__ float block_sum(float v, float* red) {
    int tid = threadIdx.x;
    red[tid] = v; __syncthreads();
    for (int s = 128; s > 0; s >>= 1) {
        if (tid < s) red[tid] += red[tid + s];
        __syncthreads();
    }
    float r = red[0]; __syncthreads();
    return r;
}

__global__ void __launch_bounds__(256) gather_ln3_kernel(
    const float* __restrict__ y, const int* __restrict__ gidx,
    const int* __restrict__ sl, const float* __restrict__ gatev,
    const float* __restrict__ g1, const float* __restrict__ b1,
    const float* __restrict__ g2, const float* __restrict__ b2,
    const float* __restrict__ g3, const float* __restrict__ b3,
    float* __restrict__ out, const float* __restrict__ auxp, long long out_size)
{
    __shared__ float red[256];
    const int t = blockIdx.x, tid = threadIdx.x;

    const float gv1 = gatev[2 * t], gv2 = gatev[2 * t + 1];
    const int s1 = sl[2 * t], s2 = sl[2 * t + 1];
    const int e1 = gidx[2 * t], e2 = gidx[2 * t + 1];
    float4 v = make_float4(0.f, 0.f, 0.f, 0.f);
    if (s1 >= 0) {
        float4 a = ((const float4*)(y + ((size_t)e1 * CAP + s1) * DIM))[tid];
        v.x += gv1 * a.x; v.y += gv1 * a.y; v.z += gv1 * a.z; v.w += gv1 * a.w;
    }
    if (s2 >= 0) {
        float4 a = ((const float4*)(y + ((size_t)e2 * CAP + s2) * DIM))[tid];
        v.x += gv2 * a.x; v.y += gv2 * a.y; v.z += gv2 * a.z; v.w += gv2 * a.w;
    }

    const float* gs[3] = {g1, g2, g3};
    const float* bs[3] = {b1, b2, b3};
    #pragma unroll
    for (int r3 = 0; r3 < 3; r3++) {
        float s = v.x + v.y + v.z + v.w;
        float mean = block_sum(s, red) * (1.0f / DIM);
        float dx = v.x - mean, dy = v.y - mean, dz = v.z - mean, dw = v.w - mean;
        float s2 = dx * dx + dy * dy + dz * dz + dw * dw;
        float var = block_sum(s2, red) * (1.0f / DIM);
        float rstd = rsqrtf(var + LN_EPS);
        float4 gg = ((const float4*)gs[r3])[tid];
        float4 bb = ((const float4*)bs[r3])[tid];
        v.x = dx * rstd * gg.x + bb.x;
        v.y = dy * rstd * gg.y + bb.y;
        v.z = dz * rstd * gg.z + bb.z;
        v.w = dw * rstd * gg.w + bb.w;
    }
    ((float4*)(out + (long long)t * DIM))[tid] = v;
    if (t == 0 && tid == 0 && out_size > (long long)NTOK * DIM)
        out[(long long)NTOK * DIM] = *auxp;
}

// ---------------- launch ----------------
extern "C" void kernel_launch(void* const* d_in, const int* in_sizes, int n_in,
                              void* d_out, int out_size) {
    const float* tgt      = (const float*)d_in[0];
    const float* mem      = (const float*)d_in[1];
    const float* w_qkv_sa = (const float*)d_in[2];
    const float* b_qkv_sa = (const float*)d_in[3];
    const float* w_o_sa   = (const float*)d_in[4];
    const float* b_o_sa   = (const float*)d_in[5];
    const float* w_qkv_ca = (const float*)d_in[6];
    const float* b_qkv_ca = (const float*)d_in[7];
    const float* w_o_ca   = (const float*)d_in[8];
    const float* b_o_ca   = (const float*)d_in[9];
    const float* ln1_g = (const float*)d_in[10];
    const float* ln1_b = (const float*)d_in[11];
    const float* ln2_g = (const float*)d_in[12];
    const float* ln2_b = (const float*)d_in[13];
    const float* ln3_g = (const float*)d_in[14];
    const float* ln3_b = (const float*)d_in[15];
    const float* w_gate = (const float*)d_in[16];
    const float* w1  = (const float*)d_in[17];
    const float* b1e = (const float*)d_in[18];
    const float* w2  = (const float*)d_in[19];
    const float* b2e = (const float*)d_in[20];
    float* out = (float*)d_out;

    float *x2, *probs, *gatev, *ybuf, *auxp;
    int *gidx, *sl, *rows;
    __nv_bfloat16 *tgt_h, *tgt_l, *mem_h, *mem_l, *att_h, *att_l, *x1_h, *x1_l;
    __nv_bfloat16 *qkv_h, *qkv_l, *qca_h, *qca_l, *kvca_h, *kvca_l;
    __nv_bfloat16 *buf_h, *buf_l, *hb_h, *hb_l;
    __nv_bfloat16 *wqsa_h, *wqsa_l, *wosa_h, *wosa_l, *wqca_h, *wqca_l, *woca_h, *woca_l;
    __nv_bfloat16 *w1s_h, *w1s_l, *w2s_h, *w2s_l;

    cudaGetSymbolAddress((void**)&x2,   g_x2);
    cudaGetSymbolAddress((void**)&probs,g_probs);
    cudaGetSymbolAddress((void**)&gatev,g_gatev);
    cudaGetSymbolAddress((void**)&gidx, g_gidx);
    cudaGetSymbolAddress((void**)&sl,   g_sl);
    cudaGetSymbolAddress((void**)&rows, g_rows);
    cudaGetSymbolAddress((void**)&auxp, g_aux);
    cudaGetSymbolAddress((void**)&ybuf, g_y);
    cudaGetSymbolAddress((void**)&tgt_h, g_tgt_h); cudaGetSymbolAddress((void**)&tgt_l, g_tgt_l);
    cudaGetSymbolAddress((void**)&mem_h, g_mem_h); cudaGetSymbolAddress((void**)&mem_l, g_mem_l);
    cudaGetSymbolAddress((void**)&att_h, g_att_h); cudaGetSymbolAddress((void**)&att_l, g_att_l);
    cudaGetSymbolAddress((void**)&x1_h,  g_x1_h);  cudaGetSymbolAddress((void**)&x1_l,  g_x1_l);
    cudaGetSymbolAddress((void**)&qkv_h, g_qkv_h); cudaGetSymbolAddress((void**)&qkv_l, g_qkv_l);
    cudaGetSymbolAddress((void**)&qca_h, g_qca_h); cudaGetSymbolAddress((void**)&qca_l, g_qca_l);
    cudaGetSymbolAddress((void**)&kvca_h, g_kvca_h); cudaGetSymbolAddress((void**)&kvca_l, g_kvca_l);
    cudaGetSymbolAddress((void**)&buf_h, g_buf_h); cudaGetSymbolAddress((void**)&buf_l, g_buf_l);
    cudaGetSymbolAddress((void**)&hb_h,  g_hb_h);  cudaGetSymbolAddress((void**)&hb_l,  g_hb_l);
    cudaGetSymbolAddress((void**)&wqsa_h, g_wqsa_h); cudaGetSymbolAddress((void**)&wqsa_l, g_wqsa_l);
    cudaGetSymbolAddress((void**)&wosa_h, g_wosa_h); cudaGetSymbolAddress((void**)&wosa_l, g_wosa_l);
    cudaGetSymbolAddress((void**)&wqca_h, g_wqca_h); cudaGetSymbolAddress((void**)&wqca_l, g_wqca_l);
    cudaGetSymbolAddress((void**)&woca_h, g_woca_h); cudaGetSymbolAddress((void**)&woca_l, g_woca_l);
    cudaGetSymbolAddress((void**)&w1s_h, g_w1s_h); cudaGetSymbolAddress((void**)&w1s_l, g_w1s_l);
    cudaGetSymbolAddress((void**)&w2s_h, g_w2s_h); cudaGetSymbolAddress((void**)&w2s_l, g_w2s_l);

    cudaFuncSetAttribute(fa_kernel, cudaFuncAttributeMaxDynamicSharedMemorySize, FA_SMEM);
    cudaFuncSetAttribute(mmagemm_kernel<0,0,0>, cudaFuncAttributeMaxDynamicSharedMemorySize, GEMM_SMEM);
    cudaFuncSetAttribute(mmagemm_kernel<0,0,1>, cudaFuncAttributeMaxDynamicSharedMemorySize, GEMM_SMEM);
    cudaFuncSetAttribute(mmagemm_kernel<1,1,1>, cudaFuncAttributeMaxDynamicSharedMemorySize, GEMM_SMEM);
    cudaFuncSetAttribute(mmagemm_kernel<1,0,0>, cudaFuncAttributeMaxDynamicSharedMemorySize, GEMM_SMEM);

    // ---- conversions ----
    split8_kernel<<<(3*DIM*DIM/8 + 255)/256, 256>>>((const float4*)w_qkv_sa, (uint4*)wqsa_h, (uint4*)wqsa_l, 3*DIM*DIM/8);
    split8_kernel<<<(DIM*DIM/8 + 255)/256, 256>>>((const float4*)w_o_sa, (uint4*)wosa_h, (uint4*)wosa_l, DIM*DIM/8);
    split8_kernel<<<(3*DIM*DIM/8 + 255)/256, 256>>>((const float4*)w_qkv_ca, (uint4*)wqca_h, (uint4*)wqca_l, 3*DIM*DIM/8);
    split8_kernel<<<(DIM*DIM/8 + 255)/256, 256>>>((const float4*)w_o_ca, (uint4*)woca_h, (uint4*)woca_l, DIM*DIM/8);
    split8_kernel<<<(int)((size_t)NE*DIM*DFF/8 + 255)/256, 256>>>((const float4*)w1, (uint4*)w1s_h, (uint4*)w1s_l, (int)((size_t)NE*DIM*DFF/8));
    split8_kernel<<<(int)((size_t)NE*DIM*DFF/8 + 255)/256, 256>>>((const float4*)w2, (uint4*)w2s_h, (uint4*)w2s_l, (int)((size_t)NE*DIM*DFF/8));
    split8_kernel<<<(NTOK*DIM/8 + 255)/256, 256>>>((const float4*)tgt, (uint4*)tgt_h, (uint4*)tgt_l, NTOK*DIM/8);
    split8_kernel<<<(NTOK*DIM/8 + 255)/256, 256>>>((const float4*)mem, (uint4*)mem_h, (uint4*)mem_l, NTOK*DIM/8);

    // 1) SA qkv projection (NT) -> split bf16 qkv
    mmagemm_kernel<0,0,1><<<dim3(3072/128, NTOK/128, 1), 256, GEMM_SMEM>>>(
        tgt_h, tgt_l, wqsa_h, wqsa_l, b_qkv_sa, nullptr, qkv_h, qkv_l,
        DIM, DIM, 3*DIM, 0, 0, 0, 0, nullptr);

    // 2) self-attention (pre-split in, split out)
    fa_kernel<<<dim3(SQ/128, NH, BB), 256, FA_SMEM>>>(
        qkv_h, qkv_l, 3*DIM, qkv_h + DIM, qkv_l + DIM, 3*DIM,
        qkv_h + 2*DIM, qkv_l + 2*DIM, 3*DIM, att_h, att_l, DIM, SQ);

    // 3) SA output projection -> x1 split
    mmagemm_kernel<0,0,1><<<dim3(DIM/128, NTOK/128, 1), 256, GEMM_SMEM>>>(
        att_h, att_l, wosa_h, wosa_l, b_o_sa, nullptr, x1_h, x1_l,
        DIM, DIM, DIM, 0, 0, 0, 0, nullptr);

    // 4) CA q projection -> split bf16
    mmagemm_kernel<0,0,1><<<dim3(DIM/128, NTOK/128, 1), 256, GEMM_SMEM>>>(
        x1_h, x1_l, wqca_h, wqca_l, b_qkv_ca, nullptr, qca_h, qca_l,
        DIM, DIM, DIM, 0, 0, 0, 0, nullptr);

    // 5) CA k,v projection from memory -> split bf16
    mmagemm_kernel<0,0,1><<<dim3(2*DIM/128, NTOK/128, 1), 256, GEMM_SMEM>>>(
        mem_h, mem_l, wqca_h + (size_t)DIM*DIM, wqca_l + (size_t)DIM*DIM,
        b_qkv_ca + DIM, nullptr, kvca_h, kvca_l,
        DIM, DIM, 2*DIM, 0, 0, 0, 0, nullptr);

    // 6) cross-attention
    fa_kernel<<<dim3(SQ/128, NH, BB), 256, FA_SMEM>>>(
        qca_h, qca_l, DIM, kvca_h, kvca_l, 2*DIM,
        kvca_h + DIM, kvca_l + DIM, 2*DIM, att_h, att_l, DIM, SQ);

    // 7) CA output projection -> fp32 x2
    mmagemm_kernel<0,0,0><<<dim3(DIM/128, NTOK/128, 1), 256, GEMM_SMEM>>>(
        att_h, att_l, woca_h, woca_l, b_o_ca, x2, nullptr, nullptr,
        DIM, DIM, DIM, 0, 0, 0, 0, nullptr);

    // 8-9) gating + routing
    gate_kernel<<<NTOK, 128>>>(x2, w_gate, probs, gatev, gidx);
    route_kernel<<<1, 256>>>(gidx, probs, sl, rows, auxp);

    // 10) scatter
    scatter_kernel<<<dim3(NTOK, 2), 256>>>(x2, gidx, sl, buf_h, buf_l);

    // 11) expert FFN layer 1 (B NN, +GELU, split-out), row-skip
    mmagemm_kernel<1,1,1><<<dim3(DFF/128, CAP/128, NE), 256, GEMM_SMEM>>>(
        buf_h, buf_l, w1s_h, w1s_l, b1e, nullptr, hb_h, hb_l,
        DIM, DFF, DFF, (long long)CAP*DIM, (long long)DIM*DFF, DFF, (long long)CAP*DFF, rows);

    // 12) expert FFN layer 2 (B NN) -> fp32 ybuf, row-skip
    mmagemm_kernel<1,0,0><<<dim3(DIM/128, CAP/128, NE), 256, GEMM_SMEM>>>(
        hb_h, hb_l, w2s_h, w2s_l, b2e, ybuf, nullptr, nullptr,
        DFF, DIM, DIM, (long long)CAP*DFF, (long long)DFF*DIM, DIM, (long long)CAP*DIM, rows);

    // 13-14) fused gather + triple layernorm + aux
    gather_ln3_kernel<<<NTOK, 256>>>(ybuf, gidx, sl, gatev,
                                     ln1_g, ln1_b, ln2_g, ln2_b, ln3_g, ln3_b,
                                     out, auxp, (long long)out_size);
}